// round 1
// baseline (speedup 1.0000x reference)
#include <cuda_runtime.h>
#include <cstdint>

#define NPTS 200000
#define MPIL 30000
#define BATCH 2
#define GS 256
#define GS2 128
#define C1 64
#define C2 128

// ---------------- scratch (static __device__, no allocation) ----------------
__device__ __align__(16) float g_h0  [NPTS * 16];
__device__ __align__(16) float g_hmax[MPIL * 16];
__device__ __align__(16) float g_fv  [MPIL * 64];
__device__ __align__(16) float g_img [BATCH * GS * GS * C1];
__device__ __align__(16) float g_x1  [BATCH * GS * GS * C1];
__device__ __align__(16) float g_y1  [BATCH * GS * GS * C1];
__device__ __align__(16) float g_xb1 [BATCH * GS * GS * C1];
__device__ __align__(16) float g_x2  [BATCH * GS2 * GS2 * C2];
__device__ __align__(16) float g_y2  [BATCH * GS2 * GS2 * C2];
__device__ __align__(16) float g_xb2 [BATCH * GS2 * GS2 * C2];
__device__ __align__(16) float g_occ [BATCH * GS * GS];
__device__ __align__(16) float g_occ1[BATCH * GS * GS];
__device__ __align__(16) float g_occ2[BATCH * GS2 * GS2];

// ---------------- small helpers ----------------
__device__ __forceinline__ unsigned long long pack2(float v) {
    unsigned long long r;
    asm("mov.b64 %0, {%1, %1};" : "=l"(r) : "f"(v));
    return r;
}
__device__ __forceinline__ void ffma2(unsigned long long& acc, unsigned long long a,
                                      unsigned long long b) {
    asm("fma.rn.f32x2 %0, %1, %2, %0;" : "+l"(acc) : "l"(a), "l"(b));
}
__device__ __forceinline__ void unpack2(unsigned long long v, float& lo, float& hi) {
    asm("mov.b64 {%0, %1}, %2;" : "=f"(lo), "=f"(hi) : "l"(v));
}

// ---------------- zero ----------------
__global__ void zero4_kernel(float4* __restrict__ p, int n4) {
    int i = blockIdx.x * blockDim.x + threadIdx.x;
    if (i < n4) p[i] = make_float4(0.f, 0.f, 0.f, 0.f);
}

// ---------------- PFN layer 0: h = relu(bn(f @ W0)); hmax = segmax(h) ----------------
__global__ __launch_bounds__(256) void pfn0_kernel(
    const float* __restrict__ feat, const int* __restrict__ inv,
    const float* __restrict__ w0, const float* __restrict__ g0, const float* __restrict__ b0,
    float* __restrict__ h0, float* __restrict__ hmax)
{
    __shared__ float sw[256];
    __shared__ float sg[16], sb[16];
    if (threadIdx.x < 256) sw[threadIdx.x] = w0[threadIdx.x];
    if (threadIdx.x < 16) { sg[threadIdx.x] = g0[threadIdx.x]; sb[threadIdx.x] = b0[threadIdx.x]; }
    __syncthreads();
    int i = blockIdx.x * 256 + threadIdx.x;
    if (i >= NPTS) return;
    float f[16];
    const float4* fp = reinterpret_cast<const float4*>(feat + (size_t)i * 16);
#pragma unroll
    for (int t = 0; t < 4; t++) {
        float4 v = fp[t];
        f[4 * t] = v.x; f[4 * t + 1] = v.y; f[4 * t + 2] = v.z; f[4 * t + 3] = v.w;
    }
    float acc[16];
#pragma unroll
    for (int j = 0; j < 16; j++) acc[j] = 0.f;
#pragma unroll
    for (int c = 0; c < 16; c++) {
        float xv = f[c];
#pragma unroll
        for (int j = 0; j < 16; j++) acc[j] += xv * sw[c * 16 + j];
    }
    int seg = inv[i];
    float h[16];
#pragma unroll
    for (int j = 0; j < 16; j++) h[j] = fmaxf(acc[j] * sg[j] + sb[j], 0.f);
    float4* hp = reinterpret_cast<float4*>(h0 + (size_t)i * 16);
#pragma unroll
    for (int t = 0; t < 4; t++) hp[t] = make_float4(h[4 * t], h[4 * t + 1], h[4 * t + 2], h[4 * t + 3]);
    int* hm = reinterpret_cast<int*>(hmax + (size_t)seg * 16);
#pragma unroll
    for (int j = 0; j < 16; j++) atomicMax(hm + j, __float_as_int(h[j]));
}

// ---------------- PFN layer 1: h3 = relu(bn([h,hmax]@W1)); fv = segmax(h3) ----------------
__global__ __launch_bounds__(128) void pfn1_kernel(
    const int* __restrict__ inv,
    const float* __restrict__ w1, const float* __restrict__ g1, const float* __restrict__ b1,
    const float* __restrict__ h0, const float* __restrict__ hmax, float* __restrict__ fv)
{
    __shared__ float sw[32 * 64];
    __shared__ float sg[64], sb[64];
    for (int t = threadIdx.x; t < 2048; t += blockDim.x) sw[t] = w1[t];
    if (threadIdx.x < 64) { sg[threadIdx.x] = g1[threadIdx.x]; sb[threadIdx.x] = b1[threadIdx.x]; }
    __syncthreads();
    int i = blockIdx.x * blockDim.x + threadIdx.x;
    if (i >= NPTS) return;
    int seg = inv[i];
    float x[32];
    const float4* hp = reinterpret_cast<const float4*>(h0 + (size_t)i * 16);
    const float4* mp = reinterpret_cast<const float4*>(hmax + (size_t)seg * 16);
#pragma unroll
    for (int t = 0; t < 4; t++) {
        float4 v = hp[t];
        x[4 * t] = v.x; x[4 * t + 1] = v.y; x[4 * t + 2] = v.z; x[4 * t + 3] = v.w;
        float4 u = mp[t];
        x[16 + 4 * t] = u.x; x[16 + 4 * t + 1] = u.y; x[16 + 4 * t + 2] = u.z; x[16 + 4 * t + 3] = u.w;
    }
    float acc[64];
#pragma unroll
    for (int j = 0; j < 64; j++) acc[j] = 0.f;
#pragma unroll
    for (int c = 0; c < 32; c++) {
        float xv = x[c];
        const float4* wr = reinterpret_cast<const float4*>(&sw[c * 64]);
#pragma unroll
        for (int k = 0; k < 16; k++) {
            float4 w = wr[k];
            acc[4 * k] += xv * w.x; acc[4 * k + 1] += xv * w.y;
            acc[4 * k + 2] += xv * w.z; acc[4 * k + 3] += xv * w.w;
        }
    }
    int* fp = reinterpret_cast<int*>(fv + (size_t)seg * 64);
#pragma unroll
    for (int j = 0; j < 64; j++) {
        float v = fmaxf(acc[j] * sg[j] + sb[j], 0.f);
        atomicMax(fp + j, __float_as_int(v));
    }
}

// ---------------- scatter pillars -> dense BEV ----------------
__global__ void scatter_kernel(const int* __restrict__ unq, const float* __restrict__ fv,
                               float* __restrict__ img, float* __restrict__ occ)
{
    int idx = blockIdx.x * blockDim.x + threadIdx.x;
    if (idx >= MPIL * 16) return;
    int m = idx >> 4, k = idx & 15;
    int bb = unq[m * 3], yy = unq[m * 3 + 1], xx = unq[m * 3 + 2];
    float4 v = reinterpret_cast<const float4*>(fv)[m * 16 + k];
    reinterpret_cast<float4*>(img)[((bb * GS + yy) * GS + xx) * 16 + k] = v;
    if (k == 0) occ[(bb * GS + yy) * GS + xx] = 1.0f;
}

// ---------------- occupancy dilations ----------------
__global__ void occ1_kernel(const float* __restrict__ occ, float* __restrict__ occ1) {
    int idx = blockIdx.x * blockDim.x + threadIdx.x;
    if (idx >= BATCH * GS * GS) return;
    int x = idx % GS, y = (idx / GS) % GS, b = idx / (GS * GS);
    float m = 0.f;
#pragma unroll
    for (int dy = -1; dy <= 1; dy++)
#pragma unroll
        for (int dx = -1; dx <= 1; dx++) {
            int yy = y + dy, xx = x + dx;
            if (yy >= 0 && yy < GS && xx >= 0 && xx < GS)
                m = fmaxf(m, occ[(b * GS + yy) * GS + xx]);
        }
    occ1[idx] = m;
}
__global__ void occ2_kernel(const float* __restrict__ occ1, float* __restrict__ occ2) {
    int idx = blockIdx.x * blockDim.x + threadIdx.x;
    if (idx >= BATCH * GS2 * GS2) return;
    int x = idx % GS2, y = (idx / GS2) % GS2, b = idx / (GS2 * GS2);
    float m = 0.f;
#pragma unroll
    for (int dy = -1; dy <= 1; dy++)
#pragma unroll
        for (int dx = -1; dx <= 1; dx++) {
            int yy = 2 * y + dy, xx = 2 * x + dx;
            if (yy >= 0 && yy < GS && xx >= 0 && xx < GS)
                m = fmaxf(m, occ1[(b * GS + yy) * GS + xx]);
        }
    occ2[idx] = m;
}

// ---------------- fused conv3x3 + BN + mask (+residual) ----------------
// one thread = one output pixel x (COUT/NQ) channels; f32x2 packed FFMA
template <int CIN, int COUT, int STRIDE, int TH, int TW, bool RESID>
__global__ __launch_bounds__(256) void conv3x3_kernel(
    const float* __restrict__ in, const float* __restrict__ wgt,
    const float* __restrict__ gm, const float* __restrict__ bt,
    const float* __restrict__ mask, const float* __restrict__ resid,
    float* __restrict__ out, int IH, int IW, int OH, int OW)
{
    constexpr int CCH = 8;
    constexpr int ISZ = (TH - 1) * STRIDE + 3;
    constexpr int P = TH * TW;
    constexpr int NQ = 256 / P;
    constexpr int KPT = COUT / NQ;

    __shared__ __align__(16) float s_in[CCH * ISZ * ISZ];
    __shared__ __align__(16) float s_w[9 * CCH * COUT];

    const int tid = threadIdx.x;
    const int sp = tid % P, q = tid / P;
    const int oy = sp / TW, ox = sp % TW;
    const int oy0 = blockIdx.y * TH, ox0 = blockIdx.x * TW;
    const int bb = blockIdx.z;

    unsigned long long acc[KPT / 2];
#pragma unroll
    for (int j = 0; j < KPT / 2; j++) acc[j] = 0ull;

    for (int c0 = 0; c0 < CIN; c0 += CCH) {
        __syncthreads();
        // stage input chunk, channel-major in smem
        for (int idx = tid; idx < CCH * ISZ * ISZ; idx += 256) {
            int p = idx / CCH, c = idx % CCH;
            int iy = p / ISZ, ix = p % ISZ;
            int gy = oy0 * STRIDE - 1 + iy;
            int gx = ox0 * STRIDE - 1 + ix;
            float v = 0.f;
            if (gy >= 0 && gy < IH && gx >= 0 && gx < IW)
                v = in[((bb * IH + gy) * IW + gx) * CIN + c0 + c];
            s_in[c * ISZ * ISZ + p] = v;
        }
        // stage weight chunk [tap][c][cout]
        for (int idx = tid; idx < 9 * CCH * COUT; idx += 256) {
            int tap = idx / (CCH * COUT);
            int r = idx % (CCH * COUT);
            int c = r / COUT, co = r % COUT;
            s_w[idx] = wgt[(tap * CIN + c0 + c) * COUT + co];
        }
        __syncthreads();
#pragma unroll
        for (int ky = 0; ky < 3; ky++)
#pragma unroll
            for (int kx = 0; kx < 3; kx++) {
                const float* ip = s_in + (oy * STRIDE + ky) * ISZ + (ox * STRIDE + kx);
                const float* wp = s_w + (ky * 3 + kx) * CCH * COUT + q * KPT;
#pragma unroll
                for (int c = 0; c < CCH; c++) {
                    float xv = ip[c * ISZ * ISZ];
                    unsigned long long xv2 = pack2(xv);
                    const ulonglong2* wv = reinterpret_cast<const ulonglong2*>(wp + c * COUT);
#pragma unroll
                    for (int k = 0; k < KPT / 4; k++) {
                        ulonglong2 ww = wv[k];
                        ffma2(acc[2 * k], xv2, ww.x);
                        ffma2(acc[2 * k + 1], xv2, ww.y);
                    }
                }
            }
    }
    // epilogue: BN + mask (+residual) + relu, vectorized store
    const int gy = oy0 + oy, gx = ox0 + ox;
    const float mval = mask[(bb * OH + gy) * OW + gx];
    const int base = ((bb * OH + gy) * OW + gx) * COUT + q * KPT;
#pragma unroll
    for (int k = 0; k < KPT / 4; k++) {
        float v[4];
        unpack2(acc[2 * k], v[0], v[1]);
        unpack2(acc[2 * k + 1], v[2], v[3]);
#pragma unroll
        for (int t = 0; t < 4; t++) {
            int ch = q * KPT + 4 * k + t;
            float val = v[t] * gm[ch] + bt[ch];
            if (RESID) {
                val = fmaxf(resid[base + 4 * k + t] + val * mval, 0.f);
            } else {
                val = fmaxf(val, 0.f) * mval;
            }
            v[t] = val;
        }
        reinterpret_cast<float4*>(out + base)[k] = make_float4(v[0], v[1], v[2], v[3]);
    }
}

// ---------------- bilinear gather: one warp per point, 4 ch per lane ----------------
__global__ __launch_bounds__(256) void gather_kernel(
    const float* __restrict__ feat, const int* __restrict__ unq, const int* __restrict__ inv,
    const float* __restrict__ xb2, float* __restrict__ out)
{
    int gwarp = (blockIdx.x * blockDim.x + threadIdx.x) >> 5;
    int lane = threadIdx.x & 31;
    if (gwarp >= NPTS) return;
    int i = gwarp;
    float f0 = __ldg(feat + (size_t)i * 16);
    float f1 = __ldg(feat + (size_t)i * 16 + 1);
    float px = ((f0 + 51.2f) / 0.4f) * 0.5f;
    float py = ((f1 + 51.2f) / 0.4f) * 0.5f;
    int seg = __ldg(inv + i);
    int bb = __ldg(unq + seg * 3);
    int fx = (int)floorf(px), fy = (int)floorf(py);
    int x0 = min(max(fx, 0), GS2 - 1), x1 = min(max(fx + 1, 0), GS2 - 1);
    int y0 = min(max(fy, 0), GS2 - 1), y1 = min(max(fy + 1, 0), GS2 - 1);
    float x0f = (float)x0, x1f = (float)x1, y0f = (float)y0, y1f = (float)y1;
    float wa = (x1f - px) * (y1f - py);
    float wb = (x1f - px) * (py - y0f);
    float wc = (px - x0f) * (y1f - py);
    float wd = (px - x0f) * (py - y0f);
    const float4* A = reinterpret_cast<const float4*>(xb2 + ((bb * GS2 + y0) * GS2 + x0) * C2) + lane;
    const float4* Bp = reinterpret_cast<const float4*>(xb2 + ((bb * GS2 + y1) * GS2 + x0) * C2) + lane;
    const float4* Cp = reinterpret_cast<const float4*>(xb2 + ((bb * GS2 + y0) * GS2 + x1) * C2) + lane;
    const float4* D = reinterpret_cast<const float4*>(xb2 + ((bb * GS2 + y1) * GS2 + x1) * C2) + lane;
    float4 a = __ldg(A), b = __ldg(Bp), c = __ldg(Cp), d = __ldg(D);
    float4 r;
    r.x = a.x * wa + b.x * wb + c.x * wc + d.x * wd;
    r.y = a.y * wa + b.y * wb + c.y * wc + d.y * wd;
    r.z = a.z * wa + b.z * wb + c.z * wc + d.z * wd;
    r.w = a.w * wa + b.w * wb + c.w * wc + d.w * wd;
    reinterpret_cast<float4*>(out + (size_t)i * C2)[lane] = r;
}

// ---------------- launch ----------------
extern "C" void kernel_launch(void* const* d_in, const int* in_sizes, int n_in,
                              void* d_out, int out_size)
{
    const float* feat = (const float*)d_in[0];
    const int* unq = (const int*)d_in[1];
    const int* inv = (const int*)d_in[2];
    // grid_size may or may not be materialized as a buffer
    int wb = (in_sizes[3] == 1) ? 4 : 3;
    const float* pfn_w0 = (const float*)d_in[wb + 0];
    const float* pfn_g0 = (const float*)d_in[wb + 1];
    const float* pfn_b0 = (const float*)d_in[wb + 2];
    const float* pfn_w1 = (const float*)d_in[wb + 3];
    const float* pfn_g1 = (const float*)d_in[wb + 4];
    const float* pfn_b1 = (const float*)d_in[wb + 5];
    const float* b1_kd = (const float*)d_in[wb + 6];
    const float* b1_gd = (const float*)d_in[wb + 7];
    const float* b1_bd = (const float*)d_in[wb + 8];
    const float* b1_k1 = (const float*)d_in[wb + 9];
    const float* b1_g1 = (const float*)d_in[wb + 10];
    const float* b1_b1 = (const float*)d_in[wb + 11];
    const float* b1_k2 = (const float*)d_in[wb + 12];
    const float* b1_g2 = (const float*)d_in[wb + 13];
    const float* b1_b2 = (const float*)d_in[wb + 14];
    const float* b2_kd = (const float*)d_in[wb + 15];
    const float* b2_gd = (const float*)d_in[wb + 16];
    const float* b2_bd = (const float*)d_in[wb + 17];
    const float* b2_k1 = (const float*)d_in[wb + 18];
    const float* b2_g1 = (const float*)d_in[wb + 19];
    const float* b2_b1 = (const float*)d_in[wb + 20];
    const float* b2_k2 = (const float*)d_in[wb + 21];
    const float* b2_g2 = (const float*)d_in[wb + 22];
    const float* b2_b2 = (const float*)d_in[wb + 23];
    float* out = (float*)d_out;

    float *p_h0, *p_hmax, *p_fv, *p_img, *p_x1, *p_y1, *p_xb1, *p_x2, *p_y2, *p_xb2;
    float *p_occ, *p_occ1, *p_occ2;
    cudaGetSymbolAddress((void**)&p_h0, g_h0);
    cudaGetSymbolAddress((void**)&p_hmax, g_hmax);
    cudaGetSymbolAddress((void**)&p_fv, g_fv);
    cudaGetSymbolAddress((void**)&p_img, g_img);
    cudaGetSymbolAddress((void**)&p_x1, g_x1);
    cudaGetSymbolAddress((void**)&p_y1, g_y1);
    cudaGetSymbolAddress((void**)&p_xb1, g_xb1);
    cudaGetSymbolAddress((void**)&p_x2, g_x2);
    cudaGetSymbolAddress((void**)&p_y2, g_y2);
    cudaGetSymbolAddress((void**)&p_xb2, g_xb2);
    cudaGetSymbolAddress((void**)&p_occ, g_occ);
    cudaGetSymbolAddress((void**)&p_occ1, g_occ1);
    cudaGetSymbolAddress((void**)&p_occ2, g_occ2);

    // zero what accumulates / is sparsely written
    zero4_kernel<<<(BATCH * GS * GS * C1 / 4 + 255) / 256, 256>>>((float4*)p_img, BATCH * GS * GS * C1 / 4);
    zero4_kernel<<<(MPIL * 16 / 4 + 255) / 256, 256>>>((float4*)p_hmax, MPIL * 16 / 4);
    zero4_kernel<<<(MPIL * 64 / 4 + 255) / 256, 256>>>((float4*)p_fv, MPIL * 64 / 4);
    zero4_kernel<<<(BATCH * GS * GS / 4 + 255) / 256, 256>>>((float4*)p_occ, BATCH * GS * GS / 4);

    pfn0_kernel<<<(NPTS + 255) / 256, 256>>>(feat, inv, pfn_w0, pfn_g0, pfn_b0, p_h0, p_hmax);
    pfn1_kernel<<<(NPTS + 127) / 128, 128>>>(inv, pfn_w1, pfn_g1, pfn_b1, p_h0, p_hmax, p_fv);
    scatter_kernel<<<(MPIL * 16 + 255) / 256, 256>>>(unq, p_fv, p_img, p_occ);
    occ1_kernel<<<(BATCH * GS * GS + 255) / 256, 256>>>(p_occ, p_occ1);
    occ2_kernel<<<(BATCH * GS2 * GS2 + 255) / 256, 256>>>(p_occ1, p_occ2);

    dim3 blk(256);
    dim3 grd1(GS / 8, GS / 8, BATCH);
    conv3x3_kernel<64, 64, 1, 8, 8, false><<<grd1, blk>>>(p_img, b1_kd, b1_gd, b1_bd, p_occ1, nullptr, p_x1, GS, GS, GS, GS);
    conv3x3_kernel<64, 64, 1, 8, 8, false><<<grd1, blk>>>(p_x1, b1_k1, b1_g1, b1_b1, p_occ1, nullptr, p_y1, GS, GS, GS, GS);
    conv3x3_kernel<64, 64, 1, 8, 8, true><<<grd1, blk>>>(p_y1, b1_k2, b1_g2, b1_b2, p_occ1, p_x1, p_xb1, GS, GS, GS, GS);

    dim3 grd2(GS2 / 4, GS2 / 4, BATCH);
    conv3x3_kernel<64, 128, 2, 4, 4, false><<<grd2, blk>>>(p_xb1, b2_kd, b2_gd, b2_bd, p_occ2, nullptr, p_x2, GS, GS, GS2, GS2);
    dim3 grd3(GS2 / 8, GS2 / 8, BATCH);
    conv3x3_kernel<128, 128, 1, 8, 8, false><<<grd3, blk>>>(p_x2, b2_k1, b2_g1, b2_b1, p_occ2, nullptr, p_y2, GS2, GS2, GS2, GS2);
    conv3x3_kernel<128, 128, 1, 8, 8, true><<<grd3, blk>>>(p_y2, b2_k2, b2_g2, b2_b2, p_occ2, p_x2, p_xb2, GS2, GS2, GS2, GS2);

    gather_kernel<<<(NPTS * 32 + 255) / 256, 256>>>(feat, unq, inv, p_xb2, out);
    (void)n_in; (void)out_size;
}

// round 2
// speedup vs baseline: 1.5533x; 1.5533x over previous
#include <cuda_runtime.h>
#include <cstdint>

#define NPTS 200000
#define MPIL 30000
#define BATCH 2
#define GS 256
#define GS2 128
#define C1 64
#define C2 128

// ---------------- scratch (static __device__, no allocation) ----------------
__device__ __align__(16) float g_h0  [NPTS * 16];
__device__ __align__(16) float g_hmax[MPIL * 16];
__device__ __align__(16) float g_fv  [MPIL * 64];
__device__ __align__(16) float g_img [BATCH * GS * GS * C1];
__device__ __align__(16) float g_x1  [BATCH * GS * GS * C1];
__device__ __align__(16) float g_y1  [BATCH * GS * GS * C1];
__device__ __align__(16) float g_xb1 [BATCH * GS * GS * C1];
__device__ __align__(16) float g_x2  [BATCH * GS2 * GS2 * C2];
__device__ __align__(16) float g_y2  [BATCH * GS2 * GS2 * C2];
__device__ __align__(16) float g_xb2 [BATCH * GS2 * GS2 * C2];
__device__ __align__(16) float g_occ [BATCH * GS * GS];
__device__ __align__(16) float g_occ1[BATCH * GS * GS];
__device__ __align__(16) float g_occ2[BATCH * GS2 * GS2];

// ---------------- helpers ----------------
__device__ __forceinline__ unsigned long long pack2(float v) {
    unsigned long long r;
    asm("mov.b64 %0, {%1, %1};" : "=l"(r) : "f"(v));
    return r;
}
__device__ __forceinline__ void ffma2(unsigned long long& acc, unsigned long long a,
                                      unsigned long long b) {
    asm("fma.rn.f32x2 %0, %1, %2, %0;" : "+l"(acc) : "l"(a), "l"(b));
}
__device__ __forceinline__ void unpack2(unsigned long long v, float& lo, float& hi) {
    asm("mov.b64 {%0, %1}, %2;" : "=f"(lo), "=f"(hi) : "l"(v));
}

// ---------------- zero ----------------
__global__ void zero4_kernel(float4* __restrict__ p, int n4) {
    int i = blockIdx.x * blockDim.x + threadIdx.x;
    if (i < n4) p[i] = make_float4(0.f, 0.f, 0.f, 0.f);
}

// ---------------- PFN layer 0 ----------------
__global__ __launch_bounds__(256) void pfn0_kernel(
    const float* __restrict__ feat, const int* __restrict__ inv,
    const float* __restrict__ w0, const float* __restrict__ g0, const float* __restrict__ b0,
    float* __restrict__ h0, float* __restrict__ hmax)
{
    __shared__ float sw[256];
    __shared__ float sg[16], sb[16];
    if (threadIdx.x < 256) sw[threadIdx.x] = w0[threadIdx.x];
    if (threadIdx.x < 16) { sg[threadIdx.x] = g0[threadIdx.x]; sb[threadIdx.x] = b0[threadIdx.x]; }
    __syncthreads();
    int i = blockIdx.x * 256 + threadIdx.x;
    if (i >= NPTS) return;
    float f[16];
    const float4* fp = reinterpret_cast<const float4*>(feat + (size_t)i * 16);
#pragma unroll
    for (int t = 0; t < 4; t++) {
        float4 v = fp[t];
        f[4 * t] = v.x; f[4 * t + 1] = v.y; f[4 * t + 2] = v.z; f[4 * t + 3] = v.w;
    }
    float acc[16];
#pragma unroll
    for (int j = 0; j < 16; j++) acc[j] = 0.f;
#pragma unroll
    for (int c = 0; c < 16; c++) {
        float xv = f[c];
#pragma unroll
        for (int j = 0; j < 16; j++) acc[j] += xv * sw[c * 16 + j];
    }
    int seg = inv[i];
    float h[16];
#pragma unroll
    for (int j = 0; j < 16; j++) h[j] = fmaxf(acc[j] * sg[j] + sb[j], 0.f);
    float4* hp = reinterpret_cast<float4*>(h0 + (size_t)i * 16);
#pragma unroll
    for (int t = 0; t < 4; t++) hp[t] = make_float4(h[4 * t], h[4 * t + 1], h[4 * t + 2], h[4 * t + 3]);
    int* hm = reinterpret_cast<int*>(hmax + (size_t)seg * 16);
#pragma unroll
    for (int j = 0; j < 16; j++) atomicMax(hm + j, __float_as_int(h[j]));
}

// ---------------- PFN layer 1 ----------------
__global__ __launch_bounds__(128) void pfn1_kernel(
    const int* __restrict__ inv,
    const float* __restrict__ w1, const float* __restrict__ g1, const float* __restrict__ b1,
    const float* __restrict__ h0, const float* __restrict__ hmax, float* __restrict__ fv)
{
    __shared__ float sw[32 * 64];
    __shared__ float sg[64], sb[64];
    for (int t = threadIdx.x; t < 2048; t += blockDim.x) sw[t] = w1[t];
    if (threadIdx.x < 64) { sg[threadIdx.x] = g1[threadIdx.x]; sb[threadIdx.x] = b1[threadIdx.x]; }
    __syncthreads();
    int i = blockIdx.x * blockDim.x + threadIdx.x;
    if (i >= NPTS) return;
    int seg = inv[i];
    float x[32];
    const float4* hp = reinterpret_cast<const float4*>(h0 + (size_t)i * 16);
    const float4* mp = reinterpret_cast<const float4*>(hmax + (size_t)seg * 16);
#pragma unroll
    for (int t = 0; t < 4; t++) {
        float4 v = hp[t];
        x[4 * t] = v.x; x[4 * t + 1] = v.y; x[4 * t + 2] = v.z; x[4 * t + 3] = v.w;
        float4 u = mp[t];
        x[16 + 4 * t] = u.x; x[16 + 4 * t + 1] = u.y; x[16 + 4 * t + 2] = u.z; x[16 + 4 * t + 3] = u.w;
    }
    float acc[64];
#pragma unroll
    for (int j = 0; j < 64; j++) acc[j] = 0.f;
#pragma unroll
    for (int c = 0; c < 32; c++) {
        float xv = x[c];
        const float4* wr = reinterpret_cast<const float4*>(&sw[c * 64]);
#pragma unroll
        for (int k = 0; k < 16; k++) {
            float4 w = wr[k];
            acc[4 * k] += xv * w.x; acc[4 * k + 1] += xv * w.y;
            acc[4 * k + 2] += xv * w.z; acc[4 * k + 3] += xv * w.w;
        }
    }
    int* fp = reinterpret_cast<int*>(fv + (size_t)seg * 64);
#pragma unroll
    for (int j = 0; j < 64; j++) {
        float v = fmaxf(acc[j] * sg[j] + sb[j], 0.f);
        atomicMax(fp + j, __float_as_int(v));
    }
}

// ---------------- scatter pillars -> dense BEV ----------------
__global__ void scatter_kernel(const int* __restrict__ unq, const float* __restrict__ fv,
                               float* __restrict__ img, float* __restrict__ occ)
{
    int idx = blockIdx.x * blockDim.x + threadIdx.x;
    if (idx >= MPIL * 16) return;
    int m = idx >> 4, k = idx & 15;
    int bb = unq[m * 3], yy = unq[m * 3 + 1], xx = unq[m * 3 + 2];
    float4 v = reinterpret_cast<const float4*>(fv)[m * 16 + k];
    reinterpret_cast<float4*>(img)[((bb * GS + yy) * GS + xx) * 16 + k] = v;
    if (k == 0) occ[(bb * GS + yy) * GS + xx] = 1.0f;
}

// ---------------- occupancy dilations ----------------
__global__ void occ1_kernel(const float* __restrict__ occ, float* __restrict__ occ1) {
    int idx = blockIdx.x * blockDim.x + threadIdx.x;
    if (idx >= BATCH * GS * GS) return;
    int x = idx % GS, y = (idx / GS) % GS, b = idx / (GS * GS);
    float m = 0.f;
#pragma unroll
    for (int dy = -1; dy <= 1; dy++)
#pragma unroll
        for (int dx = -1; dx <= 1; dx++) {
            int yy = y + dy, xx = x + dx;
            if (yy >= 0 && yy < GS && xx >= 0 && xx < GS)
                m = fmaxf(m, occ[(b * GS + yy) * GS + xx]);
        }
    occ1[idx] = m;
}
__global__ void occ2_kernel(const float* __restrict__ occ1, float* __restrict__ occ2) {
    int idx = blockIdx.x * blockDim.x + threadIdx.x;
    if (idx >= BATCH * GS2 * GS2) return;
    int x = idx % GS2, y = (idx / GS2) % GS2, b = idx / (GS2 * GS2);
    float m = 0.f;
#pragma unroll
    for (int dy = -1; dy <= 1; dy++)
#pragma unroll
        for (int dx = -1; dx <= 1; dx++) {
            int yy = 2 * y + dy, xx = 2 * x + dx;
            if (yy >= 0 && yy < GS && xx >= 0 && xx < GS)
                m = fmaxf(m, occ1[(b * GS + yy) * GS + xx]);
        }
    occ2[idx] = m;
}

// ---------------- fused conv3x3 + BN + mask (+residual), 4 px/thread ----------------
// Thread layout: q = channel group (KPT=COUT/NQ channels), sp indexes pixel group.
// Each thread owns PIX=4 x-contiguous output pixels -> weight LDS amortized 4x,
// all weight LDS are warp-uniform broadcasts (whole warp shares q).
template <int CIN, int COUT, int STRIDE, int CCH, int TH, int TW, int NQ, bool RESID>
__global__ __launch_bounds__(256, 2) void conv3x3_kernel(
    const float* __restrict__ in, const float* __restrict__ wgt,
    const float* __restrict__ gm, const float* __restrict__ bt,
    const float* __restrict__ mask, const float* __restrict__ resid,
    float* __restrict__ out, int IH, int IW, int OH, int OW)
{
    constexpr int PIX = 4;
    constexpr int P = 256 / NQ;
    constexpr int XG = TW / PIX;
    static_assert(P == TH * XG, "thread/pixel tiling mismatch");
    constexpr int KPT = COUT / NQ;
    static_assert(KPT % 4 == 0, "KPT must be multiple of 4");
    constexpr int ISZY = (TH - 1) * STRIDE + 3;
    constexpr int ISZX = (TW - 1) * STRIDE + 3;
    constexpr int NIN = (PIX - 1) * STRIDE + 3;
    constexpr int IN_TOT = CCH * ISZY * ISZX;
    constexpr int W_TOT4 = 9 * CCH * COUT / 4;

    __shared__ __align__(16) float s_in[CCH][ISZY][ISZX];
    __shared__ __align__(16) float s_w[9][CCH][COUT];

    const int tid = threadIdx.x;
    const int q = tid / P;
    const int sp = tid % P;
    const int row = sp / XG;
    const int xg = sp % XG;
    const int oy0 = blockIdx.y * TH, ox0 = blockIdx.x * TW;
    const int bb = blockIdx.z;

    unsigned long long acc[PIX][KPT / 2];
#pragma unroll
    for (int j = 0; j < PIX; j++)
#pragma unroll
        for (int k = 0; k < KPT / 2; k++) acc[j][k] = 0ull;

    for (int c0 = 0; c0 < CIN; c0 += CCH) {
        __syncthreads();
        // stage input chunk [c][iy][ix]
#pragma unroll 1
        for (int idx = tid; idx < IN_TOT; idx += 256) {
            int c = idx % CCH, p = idx / CCH;
            int iy = p / ISZX, ix = p % ISZX;
            int gy = oy0 * STRIDE - 1 + iy;
            int gx = ox0 * STRIDE - 1 + ix;
            float v = 0.f;
            if (gy >= 0 && gy < IH && gx >= 0 && gx < IW)
                v = in[((bb * IH + gy) * IW + gx) * CIN + c0 + c];
            s_in[c][iy][ix] = v;
        }
        // stage weight chunk [tap][c][cout], float4 vectorized
#pragma unroll 1
        for (int i4 = tid; i4 < W_TOT4; i4 += 256) {
            int tap = i4 / (CCH * COUT / 4);
            int r = i4 % (CCH * COUT / 4);
            int c = r / (COUT / 4);
            int co4 = r % (COUT / 4);
            float4 wv = reinterpret_cast<const float4*>(wgt)[((tap * CIN + c0 + c) * COUT) / 4 + co4];
            reinterpret_cast<float4*>(&s_w[tap][c][0])[co4] = wv;
        }
        __syncthreads();
#pragma unroll
        for (int c = 0; c < CCH; c++) {
#pragma unroll
            for (int ky = 0; ky < 3; ky++) {
                const float* irow = &s_in[c][row * STRIDE + ky][xg * PIX * STRIDE];
                unsigned long long xin[NIN];
#pragma unroll
                for (int n = 0; n < NIN; n++) xin[n] = pack2(irow[n]);
#pragma unroll
                for (int kx = 0; kx < 3; kx++) {
                    const ulonglong2* wv =
                        reinterpret_cast<const ulonglong2*>(&s_w[ky * 3 + kx][c][q * KPT]);
                    ulonglong2 w[KPT / 4];
#pragma unroll
                    for (int k = 0; k < KPT / 4; k++) w[k] = wv[k];
#pragma unroll
                    for (int j = 0; j < PIX; j++) {
                        unsigned long long xv = xin[j * STRIDE + kx];
#pragma unroll
                        for (int k = 0; k < KPT / 4; k++) {
                            ffma2(acc[j][2 * k], xv, w[k].x);
                            ffma2(acc[j][2 * k + 1], xv, w[k].y);
                        }
                    }
                }
            }
        }
    }
    // epilogue
    float gmv[KPT], btv[KPT];
#pragma unroll
    for (int k = 0; k < KPT; k++) { gmv[k] = gm[q * KPT + k]; btv[k] = bt[q * KPT + k]; }
    const int gy = oy0 + row;
#pragma unroll
    for (int j = 0; j < PIX; j++) {
        const int gx = ox0 + xg * PIX + j;
        const float mval = mask[(bb * OH + gy) * OW + gx];
        const int base = ((bb * OH + gy) * OW + gx) * COUT + q * KPT;
#pragma unroll
        for (int k = 0; k < KPT / 4; k++) {
            float v[4];
            unpack2(acc[j][2 * k], v[0], v[1]);
            unpack2(acc[j][2 * k + 1], v[2], v[3]);
#pragma unroll
            for (int t = 0; t < 4; t++) {
                float val = v[t] * gmv[4 * k + t] + btv[4 * k + t];
                if (RESID) val = fmaxf(resid[base + 4 * k + t] + val * mval, 0.f);
                else       val = fmaxf(val, 0.f) * mval;
                v[t] = val;
            }
            reinterpret_cast<float4*>(out + base)[k] = make_float4(v[0], v[1], v[2], v[3]);
        }
    }
}

// ---------------- bilinear gather ----------------
__global__ __launch_bounds__(256) void gather_kernel(
    const float* __restrict__ feat, const int* __restrict__ unq, const int* __restrict__ inv,
    const float* __restrict__ xb2, float* __restrict__ out)
{
    int gwarp = (blockIdx.x * blockDim.x + threadIdx.x) >> 5;
    int lane = threadIdx.x & 31;
    if (gwarp >= NPTS) return;
    int i = gwarp;
    float f0 = __ldg(feat + (size_t)i * 16);
    float f1 = __ldg(feat + (size_t)i * 16 + 1);
    float px = ((f0 + 51.2f) / 0.4f) * 0.5f;
    float py = ((f1 + 51.2f) / 0.4f) * 0.5f;
    int seg = __ldg(inv + i);
    int bb = __ldg(unq + seg * 3);
    int fx = (int)floorf(px), fy = (int)floorf(py);
    int x0 = min(max(fx, 0), GS2 - 1), x1 = min(max(fx + 1, 0), GS2 - 1);
    int y0 = min(max(fy, 0), GS2 - 1), y1 = min(max(fy + 1, 0), GS2 - 1);
    float x0f = (float)x0, x1f = (float)x1, y0f = (float)y0, y1f = (float)y1;
    float wa = (x1f - px) * (y1f - py);
    float wb = (x1f - px) * (py - y0f);
    float wc = (px - x0f) * (y1f - py);
    float wd = (px - x0f) * (py - y0f);
    const float4* A = reinterpret_cast<const float4*>(xb2 + ((bb * GS2 + y0) * GS2 + x0) * C2) + lane;
    const float4* Bp = reinterpret_cast<const float4*>(xb2 + ((bb * GS2 + y1) * GS2 + x0) * C2) + lane;
    const float4* Cp = reinterpret_cast<const float4*>(xb2 + ((bb * GS2 + y0) * GS2 + x1) * C2) + lane;
    const float4* D = reinterpret_cast<const float4*>(xb2 + ((bb * GS2 + y1) * GS2 + x1) * C2) + lane;
    float4 a = __ldg(A), b = __ldg(Bp), c = __ldg(Cp), d = __ldg(D);
    float4 r;
    r.x = a.x * wa + b.x * wb + c.x * wc + d.x * wd;
    r.y = a.y * wa + b.y * wb + c.y * wc + d.y * wd;
    r.z = a.z * wa + b.z * wb + c.z * wc + d.z * wd;
    r.w = a.w * wa + b.w * wb + c.w * wc + d.w * wd;
    reinterpret_cast<float4*>(out + (size_t)i * C2)[lane] = r;
}

// ---------------- launch ----------------
extern "C" void kernel_launch(void* const* d_in, const int* in_sizes, int n_in,
                              void* d_out, int out_size)
{
    const float* feat = (const float*)d_in[0];
    const int* unq = (const int*)d_in[1];
    const int* inv = (const int*)d_in[2];
    int wb = (in_sizes[3] == 1) ? 4 : 3;
    const float* pfn_w0 = (const float*)d_in[wb + 0];
    const float* pfn_g0 = (const float*)d_in[wb + 1];
    const float* pfn_b0 = (const float*)d_in[wb + 2];
    const float* pfn_w1 = (const float*)d_in[wb + 3];
    const float* pfn_g1 = (const float*)d_in[wb + 4];
    const float* pfn_b1 = (const float*)d_in[wb + 5];
    const float* b1_kd = (const float*)d_in[wb + 6];
    const float* b1_gd = (const float*)d_in[wb + 7];
    const float* b1_bd = (const float*)d_in[wb + 8];
    const float* b1_k1 = (const float*)d_in[wb + 9];
    const float* b1_g1 = (const float*)d_in[wb + 10];
    const float* b1_b1 = (const float*)d_in[wb + 11];
    const float* b1_k2 = (const float*)d_in[wb + 12];
    const float* b1_g2 = (const float*)d_in[wb + 13];
    const float* b1_b2 = (const float*)d_in[wb + 14];
    const float* b2_kd = (const float*)d_in[wb + 15];
    const float* b2_gd = (const float*)d_in[wb + 16];
    const float* b2_bd = (const float*)d_in[wb + 17];
    const float* b2_k1 = (const float*)d_in[wb + 18];
    const float* b2_g1 = (const float*)d_in[wb + 19];
    const float* b2_b1 = (const float*)d_in[wb + 20];
    const float* b2_k2 = (const float*)d_in[wb + 21];
    const float* b2_g2 = (const float*)d_in[wb + 22];
    const float* b2_b2 = (const float*)d_in[wb + 23];
    float* out = (float*)d_out;

    float *p_h0, *p_hmax, *p_fv, *p_img, *p_x1, *p_y1, *p_xb1, *p_x2, *p_y2, *p_xb2;
    float *p_occ, *p_occ1, *p_occ2;
    cudaGetSymbolAddress((void**)&p_h0, g_h0);
    cudaGetSymbolAddress((void**)&p_hmax, g_hmax);
    cudaGetSymbolAddress((void**)&p_fv, g_fv);
    cudaGetSymbolAddress((void**)&p_img, g_img);
    cudaGetSymbolAddress((void**)&p_x1, g_x1);
    cudaGetSymbolAddress((void**)&p_y1, g_y1);
    cudaGetSymbolAddress((void**)&p_xb1, g_xb1);
    cudaGetSymbolAddress((void**)&p_x2, g_x2);
    cudaGetSymbolAddress((void**)&p_y2, g_y2);
    cudaGetSymbolAddress((void**)&p_xb2, g_xb2);
    cudaGetSymbolAddress((void**)&p_occ, g_occ);
    cudaGetSymbolAddress((void**)&p_occ1, g_occ1);
    cudaGetSymbolAddress((void**)&p_occ2, g_occ2);

    zero4_kernel<<<(BATCH * GS * GS * C1 / 4 + 255) / 256, 256>>>((float4*)p_img, BATCH * GS * GS * C1 / 4);
    zero4_kernel<<<(MPIL * 16 / 4 + 255) / 256, 256>>>((float4*)p_hmax, MPIL * 16 / 4);
    zero4_kernel<<<(MPIL * 64 / 4 + 255) / 256, 256>>>((float4*)p_fv, MPIL * 64 / 4);
    zero4_kernel<<<(BATCH * GS * GS / 4 + 255) / 256, 256>>>((float4*)p_occ, BATCH * GS * GS / 4);

    pfn0_kernel<<<(NPTS + 255) / 256, 256>>>(feat, inv, pfn_w0, pfn_g0, pfn_b0, p_h0, p_hmax);
    pfn1_kernel<<<(NPTS + 127) / 128, 128>>>(inv, pfn_w1, pfn_g1, pfn_b1, p_h0, p_hmax, p_fv);
    scatter_kernel<<<(MPIL * 16 + 255) / 256, 256>>>(unq, p_fv, p_img, p_occ);
    occ1_kernel<<<(BATCH * GS * GS + 255) / 256, 256>>>(p_occ, p_occ1);
    occ2_kernel<<<(BATCH * GS2 * GS2 + 255) / 256, 256>>>(p_occ1, p_occ2);

    dim3 blk(256);
    // block1: 64->64 stride1, tile 16x16, NQ=4, CCH=8
    dim3 grd1(GS / 16, GS / 16, BATCH);
    conv3x3_kernel<64, 64, 1, 8, 16, 16, 4, false><<<grd1, blk>>>(p_img, b1_kd, b1_gd, b1_bd, p_occ1, nullptr, p_x1, GS, GS, GS, GS);
    conv3x3_kernel<64, 64, 1, 8, 16, 16, 4, false><<<grd1, blk>>>(p_x1, b1_k1, b1_g1, b1_b1, p_occ1, nullptr, p_y1, GS, GS, GS, GS);
    conv3x3_kernel<64, 64, 1, 8, 16, 16, 4, true><<<grd1, blk>>>(p_y1, b1_k2, b1_g2, b1_b2, p_occ1, p_x1, p_xb1, GS, GS, GS, GS);

    // block2 down: 64->128 stride2, out tile 8x16, NQ=8, CCH=4
    dim3 grd2(GS2 / 16, GS2 / 8, BATCH);
    conv3x3_kernel<64, 128, 2, 4, 8, 16, 8, false><<<grd2, blk>>>(p_xb1, b2_kd, b2_gd, b2_bd, p_occ2, nullptr, p_x2, GS, GS, GS2, GS2);
    // block2 residual convs: 128->128 stride1, out tile 8x16, NQ=8, CCH=4
    dim3 grd3(GS2 / 16, GS2 / 8, BATCH);
    conv3x3_kernel<128, 128, 1, 4, 8, 16, 8, false><<<grd3, blk>>>(p_x2, b2_k1, b2_g1, b2_b1, p_occ2, nullptr, p_y2, GS2, GS2, GS2, GS2);
    conv3x3_kernel<128, 128, 1, 4, 8, 16, 8, true><<<grd3, blk>>>(p_y2, b2_k2, b2_g2, b2_b2, p_occ2, p_x2, p_xb2, GS2, GS2, GS2, GS2);

    gather_kernel<<<(NPTS * 32 + 255) / 256, 256>>>(feat, unq, inv, p_xb2, out);
    (void)n_in; (void)out_size;
}

// round 3
// speedup vs baseline: 1.6283x; 1.0482x over previous
#include <cuda_runtime.h>
#include <cstdint>

#define NPTS 200000
#define MPIL 30000
#define BATCH 2
#define GS 256
#define GS2 128
#define C1 64
#define C2 128

// ---------------- scratch (static __device__, no allocation) ----------------
__device__ __align__(16) float g_h0  [NPTS * 16];
__device__ __align__(16) float g_hmax[MPIL * 16];
__device__ __align__(16) float g_fv  [MPIL * 64];
__device__ __align__(16) float g_img [BATCH * GS * GS * C1];
__device__ __align__(16) float g_x1  [BATCH * GS * GS * C1];
__device__ __align__(16) float g_y1  [BATCH * GS * GS * C1];
__device__ __align__(16) float g_xb1 [BATCH * GS * GS * C1];
__device__ __align__(16) float g_x2  [BATCH * GS2 * GS2 * C2];
__device__ __align__(16) float g_y2  [BATCH * GS2 * GS2 * C2];
__device__ __align__(16) float g_xb2 [BATCH * GS2 * GS2 * C2];
__device__ __align__(16) float g_occ [BATCH * GS * GS];
__device__ __align__(16) float g_occ1[BATCH * GS * GS];
__device__ __align__(16) float g_occ2[BATCH * GS2 * GS2];

// ---------------- helpers ----------------
__device__ __forceinline__ unsigned long long pack2(float v) {
    unsigned long long r;
    asm("mov.b64 %0, {%1, %1};" : "=l"(r) : "f"(v));
    return r;
}
__device__ __forceinline__ void ffma2(unsigned long long& acc, unsigned long long a,
                                      unsigned long long b) {
    asm("fma.rn.f32x2 %0, %1, %2, %0;" : "+l"(acc) : "l"(a), "l"(b));
}
__device__ __forceinline__ void unpack2(unsigned long long v, float& lo, float& hi) {
    asm("mov.b64 {%0, %1}, %2;" : "=f"(lo), "=f"(hi) : "l"(v));
}

// ---------------- zero ----------------
__global__ void zero4_kernel(float4* __restrict__ p, int n4) {
    int i = blockIdx.x * blockDim.x + threadIdx.x;
    if (i < n4) p[i] = make_float4(0.f, 0.f, 0.f, 0.f);
}

// ---------------- PFN layer 0 ----------------
__global__ __launch_bounds__(256) void pfn0_kernel(
    const float* __restrict__ feat, const int* __restrict__ inv,
    const float* __restrict__ w0, const float* __restrict__ g0, const float* __restrict__ b0,
    float* __restrict__ h0, float* __restrict__ hmax)
{
    __shared__ float sw[256];
    __shared__ float sg[16], sb[16];
    if (threadIdx.x < 256) sw[threadIdx.x] = w0[threadIdx.x];
    if (threadIdx.x < 16) { sg[threadIdx.x] = g0[threadIdx.x]; sb[threadIdx.x] = b0[threadIdx.x]; }
    __syncthreads();
    int i = blockIdx.x * 256 + threadIdx.x;
    if (i >= NPTS) return;
    float f[16];
    const float4* fp = reinterpret_cast<const float4*>(feat + (size_t)i * 16);
#pragma unroll
    for (int t = 0; t < 4; t++) {
        float4 v = fp[t];
        f[4 * t] = v.x; f[4 * t + 1] = v.y; f[4 * t + 2] = v.z; f[4 * t + 3] = v.w;
    }
    float acc[16];
#pragma unroll
    for (int j = 0; j < 16; j++) acc[j] = 0.f;
#pragma unroll
    for (int c = 0; c < 16; c++) {
        float xv = f[c];
#pragma unroll
        for (int j = 0; j < 16; j++) acc[j] += xv * sw[c * 16 + j];
    }
    int seg = inv[i];
    float h[16];
#pragma unroll
    for (int j = 0; j < 16; j++) h[j] = fmaxf(acc[j] * sg[j] + sb[j], 0.f);
    float4* hp = reinterpret_cast<float4*>(h0 + (size_t)i * 16);
#pragma unroll
    for (int t = 0; t < 4; t++) hp[t] = make_float4(h[4 * t], h[4 * t + 1], h[4 * t + 2], h[4 * t + 3]);
    int* hm = reinterpret_cast<int*>(hmax + (size_t)seg * 16);
#pragma unroll
    for (int j = 0; j < 16; j++) atomicMax(hm + j, __float_as_int(h[j]));
}

// ---------------- PFN layer 1 ----------------
__global__ __launch_bounds__(128) void pfn1_kernel(
    const int* __restrict__ inv,
    const float* __restrict__ w1, const float* __restrict__ g1, const float* __restrict__ b1,
    const float* __restrict__ h0, const float* __restrict__ hmax, float* __restrict__ fv)
{
    __shared__ float sw[32 * 64];
    __shared__ float sg[64], sb[64];
    for (int t = threadIdx.x; t < 2048; t += blockDim.x) sw[t] = w1[t];
    if (threadIdx.x < 64) { sg[threadIdx.x] = g1[threadIdx.x]; sb[threadIdx.x] = b1[threadIdx.x]; }
    __syncthreads();
    int i = blockIdx.x * blockDim.x + threadIdx.x;
    if (i >= NPTS) return;
    int seg = inv[i];
    float x[32];
    const float4* hp = reinterpret_cast<const float4*>(h0 + (size_t)i * 16);
    const float4* mp = reinterpret_cast<const float4*>(hmax + (size_t)seg * 16);
#pragma unroll
    for (int t = 0; t < 4; t++) {
        float4 v = hp[t];
        x[4 * t] = v.x; x[4 * t + 1] = v.y; x[4 * t + 2] = v.z; x[4 * t + 3] = v.w;
        float4 u = mp[t];
        x[16 + 4 * t] = u.x; x[16 + 4 * t + 1] = u.y; x[16 + 4 * t + 2] = u.z; x[16 + 4 * t + 3] = u.w;
    }
    float acc[64];
#pragma unroll
    for (int j = 0; j < 64; j++) acc[j] = 0.f;
#pragma unroll
    for (int c = 0; c < 32; c++) {
        float xv = x[c];
        const float4* wr = reinterpret_cast<const float4*>(&sw[c * 64]);
#pragma unroll
        for (int k = 0; k < 16; k++) {
            float4 w = wr[k];
            acc[4 * k] += xv * w.x; acc[4 * k + 1] += xv * w.y;
            acc[4 * k + 2] += xv * w.z; acc[4 * k + 3] += xv * w.w;
        }
    }
    int* fp = reinterpret_cast<int*>(fv + (size_t)seg * 64);
#pragma unroll
    for (int j = 0; j < 64; j++) {
        float v = fmaxf(acc[j] * sg[j] + sb[j], 0.f);
        atomicMax(fp + j, __float_as_int(v));
    }
}

// ---------------- scatter pillars -> dense BEV ----------------
__global__ void scatter_kernel(const int* __restrict__ unq, const float* __restrict__ fv,
                               float* __restrict__ img, float* __restrict__ occ)
{
    int idx = blockIdx.x * blockDim.x + threadIdx.x;
    if (idx >= MPIL * 16) return;
    int m = idx >> 4, k = idx & 15;
    int bb = unq[m * 3], yy = unq[m * 3 + 1], xx = unq[m * 3 + 2];
    float4 v = reinterpret_cast<const float4*>(fv)[m * 16 + k];
    reinterpret_cast<float4*>(img)[((bb * GS + yy) * GS + xx) * 16 + k] = v;
    if (k == 0) occ[(bb * GS + yy) * GS + xx] = 1.0f;
}

// ---------------- occupancy dilations ----------------
__global__ void occ1_kernel(const float* __restrict__ occ, float* __restrict__ occ1) {
    int idx = blockIdx.x * blockDim.x + threadIdx.x;
    if (idx >= BATCH * GS * GS) return;
    int x = idx % GS, y = (idx / GS) % GS, b = idx / (GS * GS);
    float m = 0.f;
#pragma unroll
    for (int dy = -1; dy <= 1; dy++)
#pragma unroll
        for (int dx = -1; dx <= 1; dx++) {
            int yy = y + dy, xx = x + dx;
            if (yy >= 0 && yy < GS && xx >= 0 && xx < GS)
                m = fmaxf(m, occ[(b * GS + yy) * GS + xx]);
        }
    occ1[idx] = m;
}
__global__ void occ2_kernel(const float* __restrict__ occ1, float* __restrict__ occ2) {
    int idx = blockIdx.x * blockDim.x + threadIdx.x;
    if (idx >= BATCH * GS2 * GS2) return;
    int x = idx % GS2, y = (idx / GS2) % GS2, b = idx / (GS2 * GS2);
    float m = 0.f;
#pragma unroll
    for (int dy = -1; dy <= 1; dy++)
#pragma unroll
        for (int dx = -1; dx <= 1; dx++) {
            int yy = 2 * y + dy, xx = 2 * x + dx;
            if (yy >= 0 && yy < GS && xx >= 0 && xx < GS)
                m = fmaxf(m, occ1[(b * GS + yy) * GS + xx]);
        }
    occ2[idx] = m;
}

// ---------------- fused conv3x3 + BN + mask (+residual), 4 px/thread ----------------
// Thread layout: q = channel group (KPT=COUT/NQ channels), sp indexes pixel group.
// Each thread owns PIX=4 x-contiguous output pixels -> weight LDS amortized 4x,
// all weight LDS are warp-uniform broadcasts (whole warp shares q).
template <int CIN, int COUT, int STRIDE, int CCH, int TH, int TW, int NQ, bool RESID>
__global__ __launch_bounds__(256, 2) void conv3x3_kernel(
    const float* __restrict__ in, const float* __restrict__ wgt,
    const float* __restrict__ gm, const float* __restrict__ bt,
    const float* __restrict__ mask, const float* __restrict__ resid,
    float* __restrict__ out, int IH, int IW, int OH, int OW)
{
    constexpr int PIX = 4;
    constexpr int P = 256 / NQ;
    constexpr int XG = TW / PIX;
    static_assert(P == TH * XG, "thread/pixel tiling mismatch");
    constexpr int KPT = COUT / NQ;
    static_assert(KPT % 4 == 0, "KPT must be multiple of 4");
    constexpr int ISZY = (TH - 1) * STRIDE + 3;
    constexpr int ISZX = (TW - 1) * STRIDE + 3;
    constexpr int NIN = (PIX - 1) * STRIDE + 3;
    constexpr int IN_TOT = CCH * ISZY * ISZX;
    constexpr int W_TOT4 = 9 * CCH * COUT / 4;

    __shared__ __align__(16) float s_in[CCH][ISZY][ISZX];
    __shared__ __align__(16) float s_w[9][CCH][COUT];

    const int tid = threadIdx.x;
    const int q = tid / P;
    const int sp = tid % P;
    const int row = sp / XG;
    const int xg = sp % XG;
    const int oy0 = blockIdx.y * TH, ox0 = blockIdx.x * TW;
    const int bb = blockIdx.z;

    unsigned long long acc[PIX][KPT / 2];
#pragma unroll
    for (int j = 0; j < PIX; j++)
#pragma unroll
        for (int k = 0; k < KPT / 2; k++) acc[j][k] = 0ull;

    for (int c0 = 0; c0 < CIN; c0 += CCH) {
        __syncthreads();
        // stage input chunk [c][iy][ix]
#pragma unroll 1
        for (int idx = tid; idx < IN_TOT; idx += 256) {
            int c = idx % CCH, p = idx / CCH;
            int iy = p / ISZX, ix = p % ISZX;
            int gy = oy0 * STRIDE - 1 + iy;
            int gx = ox0 * STRIDE - 1 + ix;
            float v = 0.f;
            if (gy >= 0 && gy < IH && gx >= 0 && gx < IW)
                v = in[((bb * IH + gy) * IW + gx) * CIN + c0 + c];
            s_in[c][iy][ix] = v;
        }
        // stage weight chunk [tap][c][cout], float4 vectorized
#pragma unroll 1
        for (int i4 = tid; i4 < W_TOT4; i4 += 256) {
            int tap = i4 / (CCH * COUT / 4);
            int r = i4 % (CCH * COUT / 4);
            int c = r / (COUT / 4);
            int co4 = r % (COUT / 4);
            float4 wv = reinterpret_cast<const float4*>(wgt)[((tap * CIN + c0 + c) * COUT) / 4 + co4];
            reinterpret_cast<float4*>(&s_w[tap][c][0])[co4] = wv;
        }
        __syncthreads();
#pragma unroll
        for (int c = 0; c < CCH; c++) {
#pragma unroll
            for (int ky = 0; ky < 3; ky++) {
                const float* irow = &s_in[c][row * STRIDE + ky][xg * PIX * STRIDE];
                unsigned long long xin[NIN];
#pragma unroll
                for (int n = 0; n < NIN; n++) xin[n] = pack2(irow[n]);
#pragma unroll
                for (int kx = 0; kx < 3; kx++) {
                    const ulonglong2* wv =
                        reinterpret_cast<const ulonglong2*>(&s_w[ky * 3 + kx][c][q * KPT]);
                    ulonglong2 w[KPT / 4];
#pragma unroll
                    for (int k = 0; k < KPT / 4; k++) w[k] = wv[k];
#pragma unroll
                    for (int j = 0; j < PIX; j++) {
                        unsigned long long xv = xin[j * STRIDE + kx];
#pragma unroll
                        for (int k = 0; k < KPT / 4; k++) {
                            ffma2(acc[j][2 * k], xv, w[k].x);
                            ffma2(acc[j][2 * k + 1], xv, w[k].y);
                        }
                    }
                }
            }
        }
    }
    // epilogue
    float gmv[KPT], btv[KPT];
#pragma unroll
    for (int k = 0; k < KPT; k++) { gmv[k] = gm[q * KPT + k]; btv[k] = bt[q * KPT + k]; }
    const int gy = oy0 + row;
#pragma unroll
    for (int j = 0; j < PIX; j++) {
        const int gx = ox0 + xg * PIX + j;
        const float mval = mask[(bb * OH + gy) * OW + gx];
        const int base = ((bb * OH + gy) * OW + gx) * COUT + q * KPT;
#pragma unroll
        for (int k = 0; k < KPT / 4; k++) {
            float v[4];
            unpack2(acc[j][2 * k], v[0], v[1]);
            unpack2(acc[j][2 * k + 1], v[2], v[3]);
#pragma unroll
            for (int t = 0; t < 4; t++) {
                float val = v[t] * gmv[4 * k + t] + btv[4 * k + t];
                if (RESID) val = fmaxf(resid[base + 4 * k + t] + val * mval, 0.f);
                else       val = fmaxf(val, 0.f) * mval;
                v[t] = val;
            }
            reinterpret_cast<float4*>(out + base)[k] = make_float4(v[0], v[1], v[2], v[3]);
        }
    }
}

// ---------------- bilinear gather ----------------
__global__ __launch_bounds__(256) void gather_kernel(
    const float* __restrict__ feat, const int* __restrict__ unq, const int* __restrict__ inv,
    const float* __restrict__ xb2, float* __restrict__ out)
{
    int gwarp = (blockIdx.x * blockDim.x + threadIdx.x) >> 5;
    int lane = threadIdx.x & 31;
    if (gwarp >= NPTS) return;
    int i = gwarp;
    float f0 = __ldg(feat + (size_t)i * 16);
    float f1 = __ldg(feat + (size_t)i * 16 + 1);
    float px = ((f0 + 51.2f) / 0.4f) * 0.5f;
    float py = ((f1 + 51.2f) / 0.4f) * 0.5f;
    int seg = __ldg(inv + i);
    int bb = __ldg(unq + seg * 3);
    int fx = (int)floorf(px), fy = (int)floorf(py);
    int x0 = min(max(fx, 0), GS2 - 1), x1 = min(max(fx + 1, 0), GS2 - 1);
    int y0 = min(max(fy, 0), GS2 - 1), y1 = min(max(fy + 1, 0), GS2 - 1);
    float x0f = (float)x0, x1f = (float)x1, y0f = (float)y0, y1f = (float)y1;
    float wa = (x1f - px) * (y1f - py);
    float wb = (x1f - px) * (py - y0f);
    float wc = (px - x0f) * (y1f - py);
    float wd = (px - x0f) * (py - y0f);
    const float4* A = reinterpret_cast<const float4*>(xb2 + ((bb * GS2 + y0) * GS2 + x0) * C2) + lane;
    const float4* Bp = reinterpret_cast<const float4*>(xb2 + ((bb * GS2 + y1) * GS2 + x0) * C2) + lane;
    const float4* Cp = reinterpret_cast<const float4*>(xb2 + ((bb * GS2 + y0) * GS2 + x1) * C2) + lane;
    const float4* D = reinterpret_cast<const float4*>(xb2 + ((bb * GS2 + y1) * GS2 + x1) * C2) + lane;
    float4 a = __ldg(A), b = __ldg(Bp), c = __ldg(Cp), d = __ldg(D);
    float4 r;
    r.x = a.x * wa + b.x * wb + c.x * wc + d.x * wd;
    r.y = a.y * wa + b.y * wb + c.y * wc + d.y * wd;
    r.z = a.z * wa + b.z * wb + c.z * wc + d.z * wd;
    r.w = a.w * wa + b.w * wb + c.w * wc + d.w * wd;
    reinterpret_cast<float4*>(out + (size_t)i * C2)[lane] = r;
}

// ---------------- launch ----------------
extern "C" void kernel_launch(void* const* d_in, const int* in_sizes, int n_in,
                              void* d_out, int out_size)
{
    const float* feat = (const float*)d_in[0];
    const int* unq = (const int*)d_in[1];
    const int* inv = (const int*)d_in[2];
    int wb = (in_sizes[3] == 1) ? 4 : 3;
    const float* pfn_w0 = (const float*)d_in[wb + 0];
    const float* pfn_g0 = (const float*)d_in[wb + 1];
    const float* pfn_b0 = (const float*)d_in[wb + 2];
    const float* pfn_w1 = (const float*)d_in[wb + 3];
    const float* pfn_g1 = (const float*)d_in[wb + 4];
    const float* pfn_b1 = (const float*)d_in[wb + 5];
    const float* b1_kd = (const float*)d_in[wb + 6];
    const float* b1_gd = (const float*)d_in[wb + 7];
    const float* b1_bd = (const float*)d_in[wb + 8];
    const float* b1_k1 = (const float*)d_in[wb + 9];
    const float* b1_g1 = (const float*)d_in[wb + 10];
    const float* b1_b1 = (const float*)d_in[wb + 11];
    const float* b1_k2 = (const float*)d_in[wb + 12];
    const float* b1_g2 = (const float*)d_in[wb + 13];
    const float* b1_b2 = (const float*)d_in[wb + 14];
    const float* b2_kd = (const float*)d_in[wb + 15];
    const float* b2_gd = (const float*)d_in[wb + 16];
    const float* b2_bd = (const float*)d_in[wb + 17];
    const float* b2_k1 = (const float*)d_in[wb + 18];
    const float* b2_g1 = (const float*)d_in[wb + 19];
    const float* b2_b1 = (const float*)d_in[wb + 20];
    const float* b2_k2 = (const float*)d_in[wb + 21];
    const float* b2_g2 = (const float*)d_in[wb + 22];
    const float* b2_b2 = (const float*)d_in[wb + 23];
    float* out = (float*)d_out;

    float *p_h0, *p_hmax, *p_fv, *p_img, *p_x1, *p_y1, *p_xb1, *p_x2, *p_y2, *p_xb2;
    float *p_occ, *p_occ1, *p_occ2;
    cudaGetSymbolAddress((void**)&p_h0, g_h0);
    cudaGetSymbolAddress((void**)&p_hmax, g_hmax);
    cudaGetSymbolAddress((void**)&p_fv, g_fv);
    cudaGetSymbolAddress((void**)&p_img, g_img);
    cudaGetSymbolAddress((void**)&p_x1, g_x1);
    cudaGetSymbolAddress((void**)&p_y1, g_y1);
    cudaGetSymbolAddress((void**)&p_xb1, g_xb1);
    cudaGetSymbolAddress((void**)&p_x2, g_x2);
    cudaGetSymbolAddress((void**)&p_y2, g_y2);
    cudaGetSymbolAddress((void**)&p_xb2, g_xb2);
    cudaGetSymbolAddress((void**)&p_occ, g_occ);
    cudaGetSymbolAddress((void**)&p_occ1, g_occ1);
    cudaGetSymbolAddress((void**)&p_occ2, g_occ2);

    zero4_kernel<<<(BATCH * GS * GS * C1 / 4 + 255) / 256, 256>>>((float4*)p_img, BATCH * GS * GS * C1 / 4);
    zero4_kernel<<<(MPIL * 16 / 4 + 255) / 256, 256>>>((float4*)p_hmax, MPIL * 16 / 4);
    zero4_kernel<<<(MPIL * 64 / 4 + 255) / 256, 256>>>((float4*)p_fv, MPIL * 64 / 4);
    zero4_kernel<<<(BATCH * GS * GS / 4 + 255) / 256, 256>>>((float4*)p_occ, BATCH * GS * GS / 4);

    pfn0_kernel<<<(NPTS + 255) / 256, 256>>>(feat, inv, pfn_w0, pfn_g0, pfn_b0, p_h0, p_hmax);
    pfn1_kernel<<<(NPTS + 127) / 128, 128>>>(inv, pfn_w1, pfn_g1, pfn_b1, p_h0, p_hmax, p_fv);
    scatter_kernel<<<(MPIL * 16 + 255) / 256, 256>>>(unq, p_fv, p_img, p_occ);
    occ1_kernel<<<(BATCH * GS * GS + 255) / 256, 256>>>(p_occ, p_occ1);
    occ2_kernel<<<(BATCH * GS2 * GS2 + 255) / 256, 256>>>(p_occ1, p_occ2);

    dim3 blk(256);
    // block1: 64->64 stride1, tile 16x16, NQ=4, CCH=8
    dim3 grd1(GS / 16, GS / 16, BATCH);
    conv3x3_kernel<64, 64, 1, 8, 16, 16, 4, false><<<grd1, blk>>>(p_img, b1_kd, b1_gd, b1_bd, p_occ1, nullptr, p_x1, GS, GS, GS, GS);
    conv3x3_kernel<64, 64, 1, 8, 16, 16, 4, false><<<grd1, blk>>>(p_x1, b1_k1, b1_g1, b1_b1, p_occ1, nullptr, p_y1, GS, GS, GS, GS);
    conv3x3_kernel<64, 64, 1, 8, 16, 16, 4, true><<<grd1, blk>>>(p_y1, b1_k2, b1_g2, b1_b2, p_occ1, p_x1, p_xb1, GS, GS, GS, GS);

    // block2 down: 64->128 stride2, out tile 8x16, NQ=8, CCH=4
    dim3 grd2(GS2 / 16, GS2 / 8, BATCH);
    conv3x3_kernel<64, 128, 2, 4, 8, 16, 8, false><<<grd2, blk>>>(p_xb1, b2_kd, b2_gd, b2_bd, p_occ2, nullptr, p_x2, GS, GS, GS2, GS2);
    // block2 residual convs: 128->128 stride1, out tile 8x16, NQ=8, CCH=4
    dim3 grd3(GS2 / 16, GS2 / 8, BATCH);
    conv3x3_kernel<128, 128, 1, 4, 8, 16, 8, false><<<grd3, blk>>>(p_x2, b2_k1, b2_g1, b2_b1, p_occ2, nullptr, p_y2, GS2, GS2, GS2, GS2);
    conv3x3_kernel<128, 128, 1, 4, 8, 16, 8, true><<<grd3, blk>>>(p_y2, b2_k2, b2_g2, b2_b2, p_occ2, p_x2, p_xb2, GS2, GS2, GS2, GS2);

    gather_kernel<<<(NPTS * 32 + 255) / 256, 256>>>(feat, unq, inv, p_xb2, out);
    (void)n_in; (void)out_size;
}

// round 5
// speedup vs baseline: 2.4493x; 1.5043x over previous
#include <cuda_runtime.h>
#include <cuda_bf16.h>
#include <cstdint>

#define NPTS 200000
#define MPIL 30000
#define BATCH 2
#define GS 256
#define GS2 128
#define C1 64
#define C2 128

// ---------------- scratch ----------------
__device__ __align__(16) __nv_bfloat16 g_a0h[BATCH*GS*GS*C1];
__device__ __align__(16) __nv_bfloat16 g_a0l[BATCH*GS*GS*C1];
__device__ __align__(16) __nv_bfloat16 g_a1h[BATCH*GS*GS*C1];
__device__ __align__(16) __nv_bfloat16 g_a1l[BATCH*GS*GS*C1];
__device__ __align__(16) __nv_bfloat16 g_a2h[BATCH*GS*GS*C1];
__device__ __align__(16) __nv_bfloat16 g_a2l[BATCH*GS*GS*C1];
__device__ __align__(16) __nv_bfloat16 g_a3h[BATCH*GS*GS*C1];
__device__ __align__(16) __nv_bfloat16 g_a3l[BATCH*GS*GS*C1];
__device__ __align__(16) __nv_bfloat16 g_a4h[BATCH*GS2*GS2*C2];
__device__ __align__(16) __nv_bfloat16 g_a4l[BATCH*GS2*GS2*C2];
__device__ __align__(16) __nv_bfloat16 g_a5h[BATCH*GS2*GS2*C2];
__device__ __align__(16) __nv_bfloat16 g_a5l[BATCH*GS2*GS2*C2];
__device__ __align__(16) float g_x1 [BATCH*GS*GS*C1];
__device__ __align__(16) float g_x2 [BATCH*GS2*GS2*C2];
__device__ __align__(16) float g_xb2[BATCH*GS2*GS2*C2];
__device__ __align__(16) float g_h0  [NPTS*16];
__device__ __align__(16) float g_hmax[MPIL*16];
__device__ __align__(16) float g_fv  [MPIL*64];
__device__ __align__(16) float g_occ [BATCH*GS*GS];
__device__ __align__(16) float g_occ1[BATCH*GS*GS];
__device__ __align__(16) float g_occ2[BATCH*GS2*GS2];

// B-fragment store: per layer, [tap][chunk][ntile] blocks of 64 uint2
// (32 lanes hi-plane, 32 lanes lo-plane), each uint2 = mma B regs {b0,b1}.
// sizes (uint2): L1..3: 9*4*8*64=18432 each; L4: 9*4*16*64=36864; L5,6: 9*8*16*64=73728 each
#define FOFF1 0
#define FOFF2 (FOFF1 + 18432)
#define FOFF3 (FOFF2 + 18432)
#define FOFF4 (FOFF3 + 18432)
#define FOFF5 (FOFF4 + 36864)
#define FOFF6 (FOFF5 + 73728)
#define FTOT  (FOFF6 + 73728)
__device__ __align__(16) uint2 g_wfrag[FTOT];

// ---------------- helpers ----------------
__device__ __forceinline__ void split_pair(float f0, float f1, uint32_t& hi2, uint32_t& lo2) {
    asm("cvt.rn.bf16x2.f32 %0, %1, %2;" : "=r"(hi2) : "f"(f1), "f"(f0));
    float f1h = __int_as_float(hi2 & 0xFFFF0000u);
    float f0h = __int_as_float(hi2 << 16);
    asm("cvt.rn.bf16x2.f32 %0, %1, %2;" : "=r"(lo2) : "f"(f1 - f1h), "f"(f0 - f0h));
}
__device__ __forceinline__ void mma16816(float* c, uint32_t a0, uint32_t a1, uint32_t a2, uint32_t a3,
                                         uint32_t b0, uint32_t b1) {
    asm volatile("mma.sync.aligned.m16n8k16.row.col.f32.bf16.bf16.f32 "
        "{%0,%1,%2,%3}, {%4,%5,%6,%7}, {%8,%9}, {%0,%1,%2,%3};"
        : "+f"(c[0]), "+f"(c[1]), "+f"(c[2]), "+f"(c[3])
        : "r"(a0), "r"(a1), "r"(a2), "r"(a3), "r"(b0), "r"(b1));
}

// ---------------- zero ----------------
__global__ void zero4_kernel(uint4* __restrict__ p, int n4) {
    int i = blockIdx.x * blockDim.x + threadIdx.x;
    if (i < n4) p[i] = make_uint4(0u, 0u, 0u, 0u);
}

// ---------------- weight prep -> mma B fragments (split hi/lo) ----------------
template <int CIN, int COUT>
__global__ void wprep_kernel(const float* __restrict__ w, uint2* __restrict__ dst) {
    constexpr int CHUNKS = CIN / 16;
    constexpr int NTTOT = COUT / 8;
    int idx = blockIdx.x * blockDim.x + threadIdx.x;
    if (idx >= 9 * CHUNKS * NTTOT * 32) return;
    int lane = idx & 31;
    int t = idx >> 5;
    int nt = t % NTTOT;
    int t2 = t / NTTOT;
    int ch = t2 % CHUNKS;
    int tap = t2 / CHUNKS;
    int n = nt * 8 + (lane >> 2);
    int k0 = (lane & 3) * 2;
    int cib = ch * 16;
    float w00 = w[((size_t)tap * CIN + cib + k0)     * COUT + n];
    float w01 = w[((size_t)tap * CIN + cib + k0 + 1) * COUT + n];
    float w10 = w[((size_t)tap * CIN + cib + k0 + 8) * COUT + n];
    float w11 = w[((size_t)tap * CIN + cib + k0 + 9) * COUT + n];
    uint32_t r0h, r0l, r1h, r1l;
    split_pair(w00, w01, r0h, r0l);
    split_pair(w10, w11, r1h, r1l);
    uint2* blk = dst + (size_t)((tap * CHUNKS + ch) * NTTOT + nt) * 64;
    blk[lane]      = make_uint2(r0h, r1h);
    blk[32 + lane] = make_uint2(r0l, r1l);
}

// ---------------- PFN layer 0 ----------------
__global__ __launch_bounds__(256) void pfn0_kernel(
    const float* __restrict__ feat, const int* __restrict__ inv,
    const float* __restrict__ w0, const float* __restrict__ g0, const float* __restrict__ b0,
    float* __restrict__ h0, float* __restrict__ hmax)
{
    __shared__ float sw[256];
    __shared__ float sg[16], sb[16];
    if (threadIdx.x < 256) sw[threadIdx.x] = w0[threadIdx.x];
    if (threadIdx.x < 16) { sg[threadIdx.x] = g0[threadIdx.x]; sb[threadIdx.x] = b0[threadIdx.x]; }
    __syncthreads();
    int i = blockIdx.x * 256 + threadIdx.x;
    if (i >= NPTS) return;
    float f[16];
    const float4* fp = reinterpret_cast<const float4*>(feat + (size_t)i * 16);
#pragma unroll
    for (int t = 0; t < 4; t++) {
        float4 v = fp[t];
        f[4*t]=v.x; f[4*t+1]=v.y; f[4*t+2]=v.z; f[4*t+3]=v.w;
    }
    float acc[16];
#pragma unroll
    for (int j = 0; j < 16; j++) acc[j] = 0.f;
#pragma unroll
    for (int c = 0; c < 16; c++) {
        float xv = f[c];
#pragma unroll
        for (int j = 0; j < 16; j++) acc[j] += xv * sw[c * 16 + j];
    }
    int seg = inv[i];
    float h[16];
#pragma unroll
    for (int j = 0; j < 16; j++) h[j] = fmaxf(acc[j] * sg[j] + sb[j], 0.f);
    float4* hp = reinterpret_cast<float4*>(h0 + (size_t)i * 16);
#pragma unroll
    for (int t = 0; t < 4; t++) hp[t] = make_float4(h[4*t], h[4*t+1], h[4*t+2], h[4*t+3]);
    int* hm = reinterpret_cast<int*>(hmax + (size_t)seg * 16);
#pragma unroll
    for (int j = 0; j < 16; j++) atomicMax(hm + j, __float_as_int(h[j]));
}

// ---------------- PFN layer 1 ----------------
__global__ __launch_bounds__(128) void pfn1_kernel(
    const int* __restrict__ inv,
    const float* __restrict__ w1, const float* __restrict__ g1, const float* __restrict__ b1,
    const float* __restrict__ h0, const float* __restrict__ hmax, float* __restrict__ fv)
{
    __shared__ float sw[32 * 64];
    __shared__ float sg[64], sb[64];
    for (int t = threadIdx.x; t < 2048; t += blockDim.x) sw[t] = w1[t];
    if (threadIdx.x < 64) { sg[threadIdx.x] = g1[threadIdx.x]; sb[threadIdx.x] = b1[threadIdx.x]; }
    __syncthreads();
    int i = blockIdx.x * blockDim.x + threadIdx.x;
    if (i >= NPTS) return;
    int seg = inv[i];
    float x[32];
    const float4* hp = reinterpret_cast<const float4*>(h0 + (size_t)i * 16);
    const float4* mp = reinterpret_cast<const float4*>(hmax + (size_t)seg * 16);
#pragma unroll
    for (int t = 0; t < 4; t++) {
        float4 v = hp[t];
        x[4*t]=v.x; x[4*t+1]=v.y; x[4*t+2]=v.z; x[4*t+3]=v.w;
        float4 u = mp[t];
        x[16+4*t]=u.x; x[16+4*t+1]=u.y; x[16+4*t+2]=u.z; x[16+4*t+3]=u.w;
    }
    float acc[64];
#pragma unroll
    for (int j = 0; j < 64; j++) acc[j] = 0.f;
#pragma unroll
    for (int c = 0; c < 32; c++) {
        float xv = x[c];
        const float4* wr = reinterpret_cast<const float4*>(&sw[c * 64]);
#pragma unroll
        for (int k = 0; k < 16; k++) {
            float4 w = wr[k];
            acc[4*k] += xv*w.x; acc[4*k+1] += xv*w.y;
            acc[4*k+2] += xv*w.z; acc[4*k+3] += xv*w.w;
        }
    }
    int* fp = reinterpret_cast<int*>(fv + (size_t)seg * 64);
#pragma unroll
    for (int j = 0; j < 64; j++) {
        float v = fmaxf(acc[j] * sg[j] + sb[j], 0.f);
        atomicMax(fp + j, __float_as_int(v));
    }
}

// ---------------- scatter pillars -> split bf16 planes + occ ----------------
__global__ void scatter_kernel(const int* __restrict__ unq, const float* __restrict__ fv,
                               __nv_bfloat16* __restrict__ ah, __nv_bfloat16* __restrict__ al,
                               float* __restrict__ occ)
{
    int idx = blockIdx.x * blockDim.x + threadIdx.x;
    if (idx >= MPIL * 8) return;
    int m = idx >> 3, k = idx & 7;
    int bb = unq[m*3], yy = unq[m*3+1], xx = unq[m*3+2];
    const float4* fp = reinterpret_cast<const float4*>(fv) + m * 16 + 2 * k;
    float4 a = fp[0], b = fp[1];
    uint4 hw, lw;
    split_pair(a.x, a.y, hw.x, lw.x);
    split_pair(a.z, a.w, hw.y, lw.y);
    split_pair(b.x, b.y, hw.z, lw.z);
    split_pair(b.z, b.w, hw.w, lw.w);
    size_t pix = ((size_t)(bb * GS + yy) * GS + xx) * 64;
    reinterpret_cast<uint4*>(ah + pix)[k] = hw;
    reinterpret_cast<uint4*>(al + pix)[k] = lw;
    if (k == 0) occ[(bb * GS + yy) * GS + xx] = 1.0f;
}

// ---------------- occupancy dilations ----------------
__global__ void occ1_kernel(const float* __restrict__ occ, float* __restrict__ occ1) {
    int idx = blockIdx.x * blockDim.x + threadIdx.x;
    if (idx >= BATCH * GS * GS) return;
    int x = idx % GS, y = (idx / GS) % GS, b = idx / (GS * GS);
    float m = 0.f;
#pragma unroll
    for (int dy = -1; dy <= 1; dy++)
#pragma unroll
        for (int dx = -1; dx <= 1; dx++) {
            int yy = y + dy, xx = x + dx;
            if (yy >= 0 && yy < GS && xx >= 0 && xx < GS)
                m = fmaxf(m, occ[(b * GS + yy) * GS + xx]);
        }
    occ1[idx] = m;
}
__global__ void occ2_kernel(const float* __restrict__ occ1, float* __restrict__ occ2) {
    int idx = blockIdx.x * blockDim.x + threadIdx.x;
    if (idx >= BATCH * GS2 * GS2) return;
    int x = idx % GS2, y = (idx / GS2) % GS2, b = idx / (GS2 * GS2);
    float m = 0.f;
#pragma unroll
    for (int dy = -1; dy <= 1; dy++)
#pragma unroll
        for (int dx = -1; dx <= 1; dx++) {
            int yy = 2 * y + dy, xx = 2 * x + dx;
            if (yy >= 0 && yy < GS && xx >= 0 && xx < GS)
                m = fmaxf(m, occ1[(b * GS + yy) * GS + xx]);
        }
    occ2[idx] = m;
}

// ---------------- HMMA conv3x3 (split bf16, mma.sync m16n8k16) ----------------
// Block: 256 thr = 8 warps: mwarp=wid>>1 (4 x 16px), nwarp=wid&1 (2 x COUT/2).
// Output tile: one y row, 64 x-pixels, all COUT.
template <int CIN, int COUT, int STRIDE, bool RESID, bool OUTF32, bool PLANES>
__global__ __launch_bounds__(256) void conv_mma(
    const __nv_bfloat16* __restrict__ inh, const __nv_bfloat16* __restrict__ inl,
    const uint2* __restrict__ wfrag,
    const float* __restrict__ gm, const float* __restrict__ bt,
    const float* __restrict__ mask, const float* __restrict__ resid,
    float* __restrict__ outf, __nv_bfloat16* __restrict__ outh, __nv_bfloat16* __restrict__ outl,
    int IH, int IW, int OH, int OW)
{
    constexpr int CHUNKS = CIN / 16;
    constexpr int NTTOT = COUT / 8;
    constexpr int NT = COUT / 16;        // ntiles per n-warp
    constexpr int PXW = 64 * STRIDE + 2; // staged input pixels per row
    constexpr int NV = 2 * 3 * PXW * 2;  // uint4 staging ops (2 planes, 3 ky, 2 halves)

    __shared__ __nv_bfloat16 s_in[2][3][PXW][16];

    const int tid = threadIdx.x;
    const int wid = tid >> 5, lane = tid & 31;
    const int mwarp = wid >> 1, nwarp = wid & 1;
    const int g = lane >> 2, q = lane & 3;
    const int y = blockIdx.y;
    const int xb = blockIdx.x * 64;
    const int bb = blockIdx.z;

    float acc[NT][4];
#pragma unroll
    for (int nt = 0; nt < NT; nt++)
#pragma unroll
        for (int j = 0; j < 4; j++) acc[nt][j] = 0.f;

#pragma unroll 1
    for (int ch = 0; ch < CHUNKS; ch++) {
        __syncthreads();
        // stage 3 input rows x PXW px x 16 ch, hi+lo planes
#pragma unroll 1
        for (int i = tid; i < NV; i += 256) {
            int half = i & 1;
            int r = i >> 1;
            int px = r % PXW;
            int ky = (r / PXW) % 3;
            int plane = r / (PXW * 3);
            int iy = y * STRIDE + ky - 1;
            int ix = xb * STRIDE - 1 + px;
            uint4 v = make_uint4(0u, 0u, 0u, 0u);
            if (iy >= 0 && iy < IH && ix >= 0 && ix < IW) {
                const uint4* src = reinterpret_cast<const uint4*>(plane ? inl : inh)
                    + ((size_t)(bb * IH + iy) * IW + ix) * (CIN / 8) + ch * 2 + half;
                v = __ldg(src);
            }
            *reinterpret_cast<uint4*>(&s_in[plane][ky][px][half * 8]) = v;
        }
        __syncthreads();
#pragma unroll
        for (int ky = 0; ky < 3; ky++) {
#pragma unroll
            for (int kx = 0; kx < 3; kx++) {
                const int pxa = (mwarp * 16 + g) * STRIDE + kx;
                const __nv_bfloat16* pAh = &s_in[0][ky][pxa][q * 2];
                const __nv_bfloat16* pAl = &s_in[1][ky][pxa][q * 2];
                uint32_t ah0 = *reinterpret_cast<const uint32_t*>(pAh);
                uint32_t ah2 = *reinterpret_cast<const uint32_t*>(pAh + 8);
                uint32_t ah1 = *reinterpret_cast<const uint32_t*>(pAh + 8 * STRIDE * 16);
                uint32_t ah3 = *reinterpret_cast<const uint32_t*>(pAh + 8 * STRIDE * 16 + 8);
                uint32_t al0 = *reinterpret_cast<const uint32_t*>(pAl);
                uint32_t al2 = *reinterpret_cast<const uint32_t*>(pAl + 8);
                uint32_t al1 = *reinterpret_cast<const uint32_t*>(pAl + 8 * STRIDE * 16);
                uint32_t al3 = *reinterpret_cast<const uint32_t*>(pAl + 8 * STRIDE * 16 + 8);
                const uint2* bbase = wfrag
                    + (size_t)(((ky * 3 + kx) * CHUNKS + ch) * NTTOT + nwarp * NT) * 64;
#pragma unroll
                for (int nt = 0; nt < NT; nt++) {
                    uint2 bh = __ldg(bbase + nt * 64 + lane);
                    uint2 bl = __ldg(bbase + nt * 64 + 32 + lane);
                    mma16816(acc[nt], ah0, ah1, ah2, ah3, bh.x, bh.y);
                    mma16816(acc[nt], ah0, ah1, ah2, ah3, bl.x, bl.y);
                    mma16816(acc[nt], al0, al1, al2, al3, bh.x, bh.y);
                }
            }
        }
    }
    // epilogue: thread owns rows (xa, xa+8), cols co=nwarp*COUT/2 + nt*8 + 2q (+1)
    const int xa = xb + mwarp * 16 + g;
    const size_t pa = (size_t)(bb * OH + y) * OW + xa;
    const size_t pb = pa + 8;
    const float mva = mask[pa];
    const float mvb = mask[pb];
#pragma unroll
    for (int nt = 0; nt < NT; nt++) {
        const int co = nwarp * (COUT / 2) + nt * 8 + 2 * q;
        const float g0 = __ldg(gm + co), g1 = __ldg(gm + co + 1);
        const float b0 = __ldg(bt + co), b1 = __ldg(bt + co + 1);
        float v0 = acc[nt][0] * g0 + b0;
        float v1 = acc[nt][1] * g1 + b1;
        float v2 = acc[nt][2] * g0 + b0;
        float v3 = acc[nt][3] * g1 + b1;
        if (RESID) {
            float2 ra = *reinterpret_cast<const float2*>(resid + pa * COUT + co);
            float2 rb = *reinterpret_cast<const float2*>(resid + pb * COUT + co);
            v0 = fmaxf(ra.x + v0 * mva, 0.f);
            v1 = fmaxf(ra.y + v1 * mva, 0.f);
            v2 = fmaxf(rb.x + v2 * mvb, 0.f);
            v3 = fmaxf(rb.y + v3 * mvb, 0.f);
        } else {
            v0 = fmaxf(v0, 0.f) * mva;
            v1 = fmaxf(v1, 0.f) * mva;
            v2 = fmaxf(v2, 0.f) * mvb;
            v3 = fmaxf(v3, 0.f) * mvb;
        }
        if (OUTF32) {
            *reinterpret_cast<float2*>(outf + pa * COUT + co) = make_float2(v0, v1);
            *reinterpret_cast<float2*>(outf + pb * COUT + co) = make_float2(v2, v3);
        }
        if (PLANES) {
            uint32_t h2, l2;
            split_pair(v0, v1, h2, l2);
            *reinterpret_cast<uint32_t*>(outh + pa * COUT + co) = h2;
            *reinterpret_cast<uint32_t*>(outl + pa * COUT + co) = l2;
            split_pair(v2, v3, h2, l2);
            *reinterpret_cast<uint32_t*>(outh + pb * COUT + co) = h2;
            *reinterpret_cast<uint32_t*>(outl + pb * COUT + co) = l2;
        }
    }
}

// ---------------- bilinear gather ----------------
__global__ __launch_bounds__(256) void gather_kernel(
    const float* __restrict__ feat, const int* __restrict__ unq, const int* __restrict__ inv,
    const float* __restrict__ xb2, float* __restrict__ out)
{
    int gwarp = (blockIdx.x * blockDim.x + threadIdx.x) >> 5;
    int lane = threadIdx.x & 31;
    if (gwarp >= NPTS) return;
    int i = gwarp;
    float f0 = __ldg(feat + (size_t)i * 16);
    float f1 = __ldg(feat + (size_t)i * 16 + 1);
    float px = ((f0 + 51.2f) / 0.4f) * 0.5f;
    float py = ((f1 + 51.2f) / 0.4f) * 0.5f;
    int seg = __ldg(inv + i);
    int bb = __ldg(unq + seg * 3);
    int fx = (int)floorf(px), fy = (int)floorf(py);
    int x0 = min(max(fx, 0), GS2 - 1), x1 = min(max(fx + 1, 0), GS2 - 1);
    int y0 = min(max(fy, 0), GS2 - 1), y1 = min(max(fy + 1, 0), GS2 - 1);
    float x0f = (float)x0, x1f = (float)x1, y0f = (float)y0, y1f = (float)y1;
    float wa = (x1f - px) * (y1f - py);
    float wb = (x1f - px) * (py - y0f);
    float wc = (px - x0f) * (y1f - py);
    float wd = (px - x0f) * (py - y0f);
    const float4* A  = reinterpret_cast<const float4*>(xb2 + ((size_t)(bb*GS2+y0)*GS2+x0)*C2) + lane;
    const float4* Bp = reinterpret_cast<const float4*>(xb2 + ((size_t)(bb*GS2+y1)*GS2+x0)*C2) + lane;
    const float4* Cp = reinterpret_cast<const float4*>(xb2 + ((size_t)(bb*GS2+y0)*GS2+x1)*C2) + lane;
    const float4* D  = reinterpret_cast<const float4*>(xb2 + ((size_t)(bb*GS2+y1)*GS2+x1)*C2) + lane;
    float4 a = __ldg(A), b = __ldg(Bp), c = __ldg(Cp), d = __ldg(D);
    float4 r;
    r.x = a.x*wa + b.x*wb + c.x*wc + d.x*wd;
    r.y = a.y*wa + b.y*wb + c.y*wc + d.y*wd;
    r.z = a.z*wa + b.z*wb + c.z*wc + d.z*wd;
    r.w = a.w*wa + b.w*wb + c.w*wc + d.w*wd;
    reinterpret_cast<float4*>(out + (size_t)i * C2)[lane] = r;
}

// ---------------- launch ----------------
extern "C" void kernel_launch(void* const* d_in, const int* in_sizes, int n_in,
                              void* d_out, int out_size)
{
    const float* feat = (const float*)d_in[0];
    const int* unq = (const int*)d_in[1];
    const int* inv = (const int*)d_in[2];
    int wb = (in_sizes[3] == 1) ? 4 : 3;
    const float* W[24];
    for (int i = 0; i < 24; i++) W[i] = (const float*)d_in[wb + i];
    float* out = (float*)d_out;

    float *p_h0, *p_hmax, *p_fv, *p_x1, *p_x2, *p_xb2, *p_occ, *p_occ1, *p_occ2;
    __nv_bfloat16 *a0h, *a0l, *a1h, *a1l, *a2h, *a2l, *a3h, *a3l, *a4h, *a4l, *a5h, *a5l;
    uint2* p_wf;
    cudaGetSymbolAddress((void**)&p_h0, g_h0);
    cudaGetSymbolAddress((void**)&p_hmax, g_hmax);
    cudaGetSymbolAddress((void**)&p_fv, g_fv);
    cudaGetSymbolAddress((void**)&p_x1, g_x1);
    cudaGetSymbolAddress((void**)&p_x2, g_x2);
    cudaGetSymbolAddress((void**)&p_xb2, g_xb2);
    cudaGetSymbolAddress((void**)&p_occ, g_occ);
    cudaGetSymbolAddress((void**)&p_occ1, g_occ1);
    cudaGetSymbolAddress((void**)&p_occ2, g_occ2);
    cudaGetSymbolAddress((void**)&a0h, g_a0h); cudaGetSymbolAddress((void**)&a0l, g_a0l);
    cudaGetSymbolAddress((void**)&a1h, g_a1h); cudaGetSymbolAddress((void**)&a1l, g_a1l);
    cudaGetSymbolAddress((void**)&a2h, g_a2h); cudaGetSymbolAddress((void**)&a2l, g_a2l);
    cudaGetSymbolAddress((void**)&a3h, g_a3h); cudaGetSymbolAddress((void**)&a3l, g_a3l);
    cudaGetSymbolAddress((void**)&a4h, g_a4h); cudaGetSymbolAddress((void**)&a4l, g_a4l);
    cudaGetSymbolAddress((void**)&a5h, g_a5h); cudaGetSymbolAddress((void**)&a5l, g_a5l);
    cudaGetSymbolAddress((void**)&p_wf, g_wfrag);

    // zero sparse-written buffers
    zero4_kernel<<<(BATCH*GS*GS*C1*2/16 + 255)/256, 256>>>((uint4*)a0h, BATCH*GS*GS*C1*2/16);
    zero4_kernel<<<(BATCH*GS*GS*C1*2/16 + 255)/256, 256>>>((uint4*)a0l, BATCH*GS*GS*C1*2/16);
    zero4_kernel<<<(MPIL*16*4/16 + 255)/256, 256>>>((uint4*)p_hmax, MPIL*16*4/16);
    zero4_kernel<<<(MPIL*64*4/16 + 255)/256, 256>>>((uint4*)p_fv, MPIL*64*4/16);
    zero4_kernel<<<(BATCH*GS*GS*4/16 + 255)/256, 256>>>((uint4*)p_occ, BATCH*GS*GS*4/16);

    // weight fragment prep
    wprep_kernel<64,64><<<(9*4*8*32 + 255)/256, 256>>>(W[6],  p_wf + FOFF1);
    wprep_kernel<64,64><<<(9*4*8*32 + 255)/256, 256>>>(W[9],  p_wf + FOFF2);
    wprep_kernel<64,64><<<(9*4*8*32 + 255)/256, 256>>>(W[12], p_wf + FOFF3);
    wprep_kernel<64,128><<<(9*4*16*32 + 255)/256, 256>>>(W[15], p_wf + FOFF4);
    wprep_kernel<128,128><<<(9*8*16*32 + 255)/256, 256>>>(W[18], p_wf + FOFF5);
    wprep_kernel<128,128><<<(9*8*16*32 + 255)/256, 256>>>(W[21], p_wf + FOFF6);

    pfn0_kernel<<<(NPTS + 255)/256, 256>>>(feat, inv, W[0], W[1], W[2], p_h0, p_hmax);
    pfn1_kernel<<<(NPTS + 127)/128, 128>>>(inv, W[3], W[4], W[5], p_h0, p_hmax, p_fv);
    scatter_kernel<<<(MPIL*8 + 255)/256, 256>>>(unq, p_fv, a0h, a0l, p_occ);
    occ1_kernel<<<(BATCH*GS*GS + 255)/256, 256>>>(p_occ, p_occ1);
    occ2_kernel<<<(BATCH*GS2*GS2 + 255)/256, 256>>>(p_occ1, p_occ2);

    dim3 blk(256);
    dim3 g1(GS/64, GS, BATCH);
    conv_mma<64,64,1,false,true,true><<<g1, blk>>>(
        a0h, a0l, p_wf + FOFF1, W[7], W[8], p_occ1, nullptr, p_x1, a1h, a1l, GS, GS, GS, GS);
    conv_mma<64,64,1,false,false,true><<<g1, blk>>>(
        a1h, a1l, p_wf + FOFF2, W[10], W[11], p_occ1, nullptr, nullptr, a2h, a2l, GS, GS, GS, GS);
    conv_mma<64,64,1,true,false,true><<<g1, blk>>>(
        a2h, a2l, p_wf + FOFF3, W[13], W[14], p_occ1, p_x1, nullptr, a3h, a3l, GS, GS, GS, GS);

    dim3 g2(GS2/64, GS2, BATCH);
    conv_mma<64,128,2,false,true,true><<<g2, blk>>>(
        a3h, a3l, p_wf + FOFF4, W[16], W[17], p_occ2, nullptr, p_x2, a4h, a4l, GS, GS, GS2, GS2);
    conv_mma<128,128,1,false,false,true><<<g2, blk>>>(
        a4h, a4l, p_wf + FOFF5, W[19], W[20], p_occ2, nullptr, nullptr, a5h, a5l, GS2, GS2, GS2, GS2);
    conv_mma<128,128,1,true,true,false><<<g2, blk>>>(
        a5h, a5l, p_wf + FOFF6, W[22], W[23], p_occ2, p_x2, p_xb2, nullptr, nullptr, GS2, GS2, GS2, GS2);

    gather_kernel<<<(NPTS*32 + 255)/256, 256>>>(feat, unq, inv, p_xb2, out);
    (void)n_in; (void)out_size;
}

// round 6
// speedup vs baseline: 2.9135x; 1.1895x over previous
#include <cuda_runtime.h>
#include <cuda_bf16.h>
#include <cstdint>

#define NPTS 200000
#define MPIL 30000
#define BATCH 2
#define GS 256
#define GS2 128
#define C1 64
#define C2 128

// ---------------- scratch ----------------
__device__ __align__(16) __nv_bfloat16 g_a0h[BATCH*GS*GS*C1];
__device__ __align__(16) __nv_bfloat16 g_a0l[BATCH*GS*GS*C1];
__device__ __align__(16) __nv_bfloat16 g_a1h[BATCH*GS*GS*C1];
__device__ __align__(16) __nv_bfloat16 g_a1l[BATCH*GS*GS*C1];
__device__ __align__(16) __nv_bfloat16 g_a2h[BATCH*GS*GS*C1];
__device__ __align__(16) __nv_bfloat16 g_a2l[BATCH*GS*GS*C1];
__device__ __align__(16) __nv_bfloat16 g_a3h[BATCH*GS*GS*C1];
__device__ __align__(16) __nv_bfloat16 g_a3l[BATCH*GS*GS*C1];
__device__ __align__(16) __nv_bfloat16 g_a4h[BATCH*GS2*GS2*C2];
__device__ __align__(16) __nv_bfloat16 g_a4l[BATCH*GS2*GS2*C2];
__device__ __align__(16) __nv_bfloat16 g_a5h[BATCH*GS2*GS2*C2];
__device__ __align__(16) __nv_bfloat16 g_a5l[BATCH*GS2*GS2*C2];
__device__ __align__(16) float g_x1 [BATCH*GS*GS*C1];
__device__ __align__(16) float g_x2 [BATCH*GS2*GS2*C2];
__device__ __align__(16) float g_xb2[BATCH*GS2*GS2*C2];
__device__ __align__(16) float g_h0  [NPTS*16];
__device__ __align__(16) float g_hmax[MPIL*16];
__device__ __align__(16) float g_fv  [MPIL*64];
__device__ __align__(16) float g_occ [BATCH*GS*GS];
__device__ __align__(16) float g_occ1[BATCH*GS*GS];
__device__ __align__(16) float g_occ2[BATCH*GS2*GS2];

// B-fragment store (see wprep): [tap][chunk][ntile] blocks of 64 uint2
#define FOFF1 0
#define FOFF2 (FOFF1 + 18432)
#define FOFF3 (FOFF2 + 18432)
#define FOFF4 (FOFF3 + 18432)
#define FOFF5 (FOFF4 + 36864)
#define FOFF6 (FOFF5 + 73728)
#define FTOT  (FOFF6 + 73728)
__device__ __align__(16) uint2 g_wfrag[FTOT];

// ---------------- helpers ----------------
__device__ __forceinline__ uint32_t smem_u32(const void* p) {
    uint32_t a;
    asm("{ .reg .u64 t; cvta.to.shared.u64 t, %1; cvt.u32.u64 %0, t; }" : "=r"(a) : "l"(p));
    return a;
}
__device__ __forceinline__ void split_pair(float f0, float f1, uint32_t& hi2, uint32_t& lo2) {
    asm("cvt.rn.bf16x2.f32 %0, %1, %2;" : "=r"(hi2) : "f"(f1), "f"(f0));
    float f1h = __int_as_float(hi2 & 0xFFFF0000u);
    float f0h = __int_as_float(hi2 << 16);
    asm("cvt.rn.bf16x2.f32 %0, %1, %2;" : "=r"(lo2) : "f"(f1 - f1h), "f"(f0 - f0h));
}
__device__ __forceinline__ void mma16816(float* c, uint32_t a0, uint32_t a1, uint32_t a2, uint32_t a3,
                                         uint32_t b0, uint32_t b1) {
    asm volatile("mma.sync.aligned.m16n8k16.row.col.f32.bf16.bf16.f32 "
        "{%0,%1,%2,%3}, {%4,%5,%6,%7}, {%8,%9}, {%0,%1,%2,%3};"
        : "+f"(c[0]), "+f"(c[1]), "+f"(c[2]), "+f"(c[3])
        : "r"(a0), "r"(a1), "r"(a2), "r"(a3), "r"(b0), "r"(b1));
}
__device__ __forceinline__ void cp16(uint32_t dst, const void* src, bool ok) {
    int sz = ok ? 16 : 0;
    asm volatile("cp.async.cg.shared.global [%0], [%1], 16, %2;"
        :: "r"(dst), "l"(src), "r"(sz) : "memory");
}
__device__ __forceinline__ void cp_commit() {
    asm volatile("cp.async.commit_group;" ::: "memory");
}
template <int N>
__device__ __forceinline__ void cp_wait() {
    asm volatile("cp.async.wait_group %0;" :: "n"(N) : "memory");
}

// ---------------- zero ----------------
__global__ void zero4_kernel(uint4* __restrict__ p, int n4) {
    int i = blockIdx.x * blockDim.x + threadIdx.x;
    if (i < n4) p[i] = make_uint4(0u, 0u, 0u, 0u);
}

// ---------------- weight prep -> mma B fragments (split hi/lo) ----------------
template <int CIN, int COUT>
__global__ void wprep_kernel(const float* __restrict__ w, uint2* __restrict__ dst) {
    constexpr int CHUNKS = CIN / 16;
    constexpr int NTTOT = COUT / 8;
    int idx = blockIdx.x * blockDim.x + threadIdx.x;
    if (idx >= 9 * CHUNKS * NTTOT * 32) return;
    int lane = idx & 31;
    int t = idx >> 5;
    int nt = t % NTTOT;
    int t2 = t / NTTOT;
    int ch = t2 % CHUNKS;
    int tap = t2 / CHUNKS;
    int n = nt * 8 + (lane >> 2);
    int k0 = (lane & 3) * 2;
    int cib = ch * 16;
    float w00 = w[((size_t)tap * CIN + cib + k0)     * COUT + n];
    float w01 = w[((size_t)tap * CIN + cib + k0 + 1) * COUT + n];
    float w10 = w[((size_t)tap * CIN + cib + k0 + 8) * COUT + n];
    float w11 = w[((size_t)tap * CIN + cib + k0 + 9) * COUT + n];
    uint32_t r0h, r0l, r1h, r1l;
    split_pair(w00, w01, r0h, r0l);
    split_pair(w10, w11, r1h, r1l);
    uint2* blk = dst + (size_t)((tap * CHUNKS + ch) * NTTOT + nt) * 64;
    blk[lane]      = make_uint2(r0h, r1h);
    blk[32 + lane] = make_uint2(r0l, r1l);
}

// ---------------- PFN layer 0 ----------------
__global__ __launch_bounds__(256) void pfn0_kernel(
    const float* __restrict__ feat, const int* __restrict__ inv,
    const float* __restrict__ w0, const float* __restrict__ g0, const float* __restrict__ b0,
    float* __restrict__ h0, float* __restrict__ hmax)
{
    __shared__ float sw[256];
    __shared__ float sg[16], sb[16];
    if (threadIdx.x < 256) sw[threadIdx.x] = w0[threadIdx.x];
    if (threadIdx.x < 16) { sg[threadIdx.x] = g0[threadIdx.x]; sb[threadIdx.x] = b0[threadIdx.x]; }
    __syncthreads();
    int i = blockIdx.x * 256 + threadIdx.x;
    if (i >= NPTS) return;
    float f[16];
    const float4* fp = reinterpret_cast<const float4*>(feat + (size_t)i * 16);
#pragma unroll
    for (int t = 0; t < 4; t++) {
        float4 v = fp[t];
        f[4*t]=v.x; f[4*t+1]=v.y; f[4*t+2]=v.z; f[4*t+3]=v.w;
    }
    float acc[16];
#pragma unroll
    for (int j = 0; j < 16; j++) acc[j] = 0.f;
#pragma unroll
    for (int c = 0; c < 16; c++) {
        float xv = f[c];
#pragma unroll
        for (int j = 0; j < 16; j++) acc[j] += xv * sw[c * 16 + j];
    }
    int seg = inv[i];
    float h[16];
#pragma unroll
    for (int j = 0; j < 16; j++) h[j] = fmaxf(acc[j] * sg[j] + sb[j], 0.f);
    float4* hp = reinterpret_cast<float4*>(h0 + (size_t)i * 16);
#pragma unroll
    for (int t = 0; t < 4; t++) hp[t] = make_float4(h[4*t], h[4*t+1], h[4*t+2], h[4*t+3]);
    int* hm = reinterpret_cast<int*>(hmax + (size_t)seg * 16);
#pragma unroll
    for (int j = 0; j < 16; j++) atomicMax(hm + j, __float_as_int(h[j]));
}

// ---------------- PFN layer 1 ----------------
__global__ __launch_bounds__(128) void pfn1_kernel(
    const int* __restrict__ inv,
    const float* __restrict__ w1, const float* __restrict__ g1, const float* __restrict__ b1,
    const float* __restrict__ h0, const float* __restrict__ hmax, float* __restrict__ fv)
{
    __shared__ float sw[32 * 64];
    __shared__ float sg[64], sb[64];
    for (int t = threadIdx.x; t < 2048; t += blockDim.x) sw[t] = w1[t];
    if (threadIdx.x < 64) { sg[threadIdx.x] = g1[threadIdx.x]; sb[threadIdx.x] = b1[threadIdx.x]; }
    __syncthreads();
    int i = blockIdx.x * blockDim.x + threadIdx.x;
    if (i >= NPTS) return;
    int seg = inv[i];
    float x[32];
    const float4* hp = reinterpret_cast<const float4*>(h0 + (size_t)i * 16);
    const float4* mp = reinterpret_cast<const float4*>(hmax + (size_t)seg * 16);
#pragma unroll
    for (int t = 0; t < 4; t++) {
        float4 v = hp[t];
        x[4*t]=v.x; x[4*t+1]=v.y; x[4*t+2]=v.z; x[4*t+3]=v.w;
        float4 u = mp[t];
        x[16+4*t]=u.x; x[16+4*t+1]=u.y; x[16+4*t+2]=u.z; x[16+4*t+3]=u.w;
    }
    float acc[64];
#pragma unroll
    for (int j = 0; j < 64; j++) acc[j] = 0.f;
#pragma unroll
    for (int c = 0; c < 32; c++) {
        float xv = x[c];
        const float4* wr = reinterpret_cast<const float4*>(&sw[c * 64]);
#pragma unroll
        for (int k = 0; k < 16; k++) {
            float4 w = wr[k];
            acc[4*k] += xv*w.x; acc[4*k+1] += xv*w.y;
            acc[4*k+2] += xv*w.z; acc[4*k+3] += xv*w.w;
        }
    }
    int* fp = reinterpret_cast<int*>(fv + (size_t)seg * 64);
#pragma unroll
    for (int j = 0; j < 64; j++) {
        float v = fmaxf(acc[j] * sg[j] + sb[j], 0.f);
        atomicMax(fp + j, __float_as_int(v));
    }
}

// ---------------- scatter pillars -> split bf16 planes + occ ----------------
__global__ void scatter_kernel(const int* __restrict__ unq, const float* __restrict__ fv,
                               __nv_bfloat16* __restrict__ ah, __nv_bfloat16* __restrict__ al,
                               float* __restrict__ occ)
{
    int idx = blockIdx.x * blockDim.x + threadIdx.x;
    if (idx >= MPIL * 8) return;
    int m = idx >> 3, k = idx & 7;
    int bb = unq[m*3], yy = unq[m*3+1], xx = unq[m*3+2];
    const float4* fp = reinterpret_cast<const float4*>(fv) + m * 16 + 2 * k;
    float4 a = fp[0], b = fp[1];
    uint4 hw, lw;
    split_pair(a.x, a.y, hw.x, lw.x);
    split_pair(a.z, a.w, hw.y, lw.y);
    split_pair(b.x, b.y, hw.z, lw.z);
    split_pair(b.z, b.w, hw.w, lw.w);
    size_t pix = ((size_t)(bb * GS + yy) * GS + xx) * 64;
    reinterpret_cast<uint4*>(ah + pix)[k] = hw;
    reinterpret_cast<uint4*>(al + pix)[k] = lw;
    if (k == 0) occ[(bb * GS + yy) * GS + xx] = 1.0f;
}

// ---------------- occupancy dilations ----------------
__global__ void occ1_kernel(const float* __restrict__ occ, float* __restrict__ occ1) {
    int idx = blockIdx.x * blockDim.x + threadIdx.x;
    if (idx >= BATCH * GS * GS) return;
    int x = idx % GS, y = (idx / GS) % GS, b = idx / (GS * GS);
    float m = 0.f;
#pragma unroll
    for (int dy = -1; dy <= 1; dy++)
#pragma unroll
        for (int dx = -1; dx <= 1; dx++) {
            int yy = y + dy, xx = x + dx;
            if (yy >= 0 && yy < GS && xx >= 0 && xx < GS)
                m = fmaxf(m, occ[(b * GS + yy) * GS + xx]);
        }
    occ1[idx] = m;
}
__global__ void occ2_kernel(const float* __restrict__ occ1, float* __restrict__ occ2) {
    int idx = blockIdx.x * blockDim.x + threadIdx.x;
    if (idx >= BATCH * GS2 * GS2) return;
    int x = idx % GS2, y = (idx / GS2) % GS2, b = idx / (GS2 * GS2);
    float m = 0.f;
#pragma unroll
    for (int dy = -1; dy <= 1; dy++)
#pragma unroll
        for (int dx = -1; dx <= 1; dx++) {
            int yy = 2 * y + dy, xx = 2 * x + dx;
            if (yy >= 0 && yy < GS && xx >= 0 && xx < GS)
                m = fmaxf(m, occ1[(b * GS + yy) * GS + xx]);
        }
    occ2[idx] = m;
}

// ---------------- HMMA conv3x3 (split bf16, mma.sync), cp.async pipelined ----------------
// Block: 8 warps: mwarp=wid>>1 (4 x 16px along x), nwarp=wid&1 (2 x COUT/2).
// Tile: TM output rows x 64 x-pixels x COUT. BUFS=2 -> double-buffered cp.async.
template <int CIN, int COUT, int STRIDE, int TM, int BUFS, bool RESID, bool OUTF32, bool PLANES>
__global__ __launch_bounds__(256) void conv_mma(
    const __nv_bfloat16* __restrict__ inh, const __nv_bfloat16* __restrict__ inl,
    const uint2* __restrict__ wfrag,
    const float* __restrict__ gm, const float* __restrict__ bt,
    const float* __restrict__ mask, const float* __restrict__ resid,
    float* __restrict__ outf, __nv_bfloat16* __restrict__ outh, __nv_bfloat16* __restrict__ outl,
    int IH, int IW, int OH, int OW)
{
    constexpr int CHUNKS = CIN / 16;
    constexpr int NTTOT = COUT / 8;
    constexpr int NT = COUT / 16;
    constexpr int R = (TM - 1) * STRIDE + 3;     // staged input rows
    constexpr int PXW = 64 * STRIDE + 2;         // staged input pixels per row
    constexpr int NV = 2 * R * PXW * 2;          // 16B cp.async ops per chunk

    __shared__ __align__(16) __nv_bfloat16 s_in[BUFS][2][R][PXW][16];

    const int tid = threadIdx.x;
    const int wid = tid >> 5, lane = tid & 31;
    const int mwarp = wid >> 1, nwarp = wid & 1;
    const int g = lane >> 2, q = lane & 3;
    const int y0 = blockIdx.y * TM;
    const int xb = blockIdx.x * 64;
    const int bb = blockIdx.z;

    float acc[TM][NT][4];
#pragma unroll
    for (int r = 0; r < TM; r++)
#pragma unroll
        for (int nt = 0; nt < NT; nt++)
#pragma unroll
            for (int j = 0; j < 4; j++) acc[r][nt][j] = 0.f;

    auto stage = [&](int ch, int buf) {
#pragma unroll 1
        for (int i = tid; i < NV; i += 256) {
            int half = i & 1;
            int r2 = i >> 1;
            int px = r2 % PXW;
            int ry = (r2 / PXW) % R;
            int plane = r2 / (PXW * R);
            int iy = y0 * STRIDE + ry - 1;
            int ix = xb * STRIDE + px - 1;
            bool ok = (iy >= 0) && (iy < IH) && (ix >= 0) && (ix < IW);
            const __nv_bfloat16* base = plane ? inl : inh;
            const void* src = ok
                ? (const void*)(base + ((size_t)(bb * IH + iy) * IW + ix) * CIN + ch * 16 + half * 8)
                : (const void*)base;
            cp16(smem_u32(&s_in[buf][plane][ry][px][half * 8]), src, ok);
        }
        cp_commit();
    };

    if (BUFS == 2) stage(0, 0);

#pragma unroll 1
    for (int ch = 0; ch < CHUNKS; ch++) {
        const int buf = (BUFS == 2) ? (ch & 1) : 0;
        if (BUFS == 2) {
            if (ch + 1 < CHUNKS) {
                stage(ch + 1, (ch + 1) & 1);
                cp_wait<1>();
            } else {
                cp_wait<0>();
            }
            __syncthreads();
        } else {
            __syncthreads();
            stage(ch, 0);
            cp_wait<0>();
            __syncthreads();
        }
#pragma unroll
        for (int ky = 0; ky < 3; ky++) {
#pragma unroll
            for (int kx = 0; kx < 3; kx++) {
                const uint2* bbase = wfrag
                    + (size_t)(((ky * 3 + kx) * CHUNKS + ch) * NTTOT + nwarp * NT) * 64;
                uint2 bh[NT], bl[NT];
#pragma unroll
                for (int nt = 0; nt < NT; nt++) {
                    bh[nt] = __ldg(bbase + nt * 64 + lane);
                    bl[nt] = __ldg(bbase + nt * 64 + 32 + lane);
                }
                const int pxa = (mwarp * 16 + g) * STRIDE + kx;
#pragma unroll
                for (int r = 0; r < TM; r++) {
                    const int row = r * STRIDE + ky;
                    const __nv_bfloat16* pAh = &s_in[buf][0][row][pxa][q * 2];
                    const __nv_bfloat16* pAl = &s_in[buf][1][row][pxa][q * 2];
                    uint32_t ah0 = *reinterpret_cast<const uint32_t*>(pAh);
                    uint32_t ah2 = *reinterpret_cast<const uint32_t*>(pAh + 8);
                    uint32_t ah1 = *reinterpret_cast<const uint32_t*>(pAh + 8 * STRIDE * 16);
                    uint32_t ah3 = *reinterpret_cast<const uint32_t*>(pAh + 8 * STRIDE * 16 + 8);
                    uint32_t al0 = *reinterpret_cast<const uint32_t*>(pAl);
                    uint32_t al2 = *reinterpret_cast<const uint32_t*>(pAl + 8);
                    uint32_t al1 = *reinterpret_cast<const uint32_t*>(pAl + 8 * STRIDE * 16);
                    uint32_t al3 = *reinterpret_cast<const uint32_t*>(pAl + 8 * STRIDE * 16 + 8);
#pragma unroll
                    for (int nt = 0; nt < NT; nt++) {
                        mma16816(acc[r][nt], ah0, ah1, ah2, ah3, bh[nt].x, bh[nt].y);
                        mma16816(acc[r][nt], ah0, ah1, ah2, ah3, bl[nt].x, bl[nt].y);
                        mma16816(acc[r][nt], al0, al1, al2, al3, bh[nt].x, bh[nt].y);
                    }
                }
            }
        }
        __syncthreads();
    }

    // epilogue
    const int xa = xb + mwarp * 16 + g;
#pragma unroll
    for (int r = 0; r < TM; r++) {
        const int y = y0 + r;
        const size_t pa = (size_t)(bb * OH + y) * OW + xa;
        const size_t pb = pa + 8;
        const float mva = mask[pa];
        const float mvb = mask[pb];
#pragma unroll
        for (int nt = 0; nt < NT; nt++) {
            const int co = nwarp * (COUT / 2) + nt * 8 + 2 * q;
            const float g0 = __ldg(gm + co), g1 = __ldg(gm + co + 1);
            const float b0 = __ldg(bt + co), b1 = __ldg(bt + co + 1);
            float v0 = acc[r][nt][0] * g0 + b0;
            float v1 = acc[r][nt][1] * g1 + b1;
            float v2 = acc[r][nt][2] * g0 + b0;
            float v3 = acc[r][nt][3] * g1 + b1;
            if (RESID) {
                float2 ra = *reinterpret_cast<const float2*>(resid + pa * COUT + co);
                float2 rb = *reinterpret_cast<const float2*>(resid + pb * COUT + co);
                v0 = fmaxf(ra.x + v0 * mva, 0.f);
                v1 = fmaxf(ra.y + v1 * mva, 0.f);
                v2 = fmaxf(rb.x + v2 * mvb, 0.f);
                v3 = fmaxf(rb.y + v3 * mvb, 0.f);
            } else {
                v0 = fmaxf(v0, 0.f) * mva;
                v1 = fmaxf(v1, 0.f) * mva;
                v2 = fmaxf(v2, 0.f) * mvb;
                v3 = fmaxf(v3, 0.f) * mvb;
            }
            if (OUTF32) {
                *reinterpret_cast<float2*>(outf + pa * COUT + co) = make_float2(v0, v1);
                *reinterpret_cast<float2*>(outf + pb * COUT + co) = make_float2(v2, v3);
            }
            if (PLANES) {
                uint32_t h2, l2;
                split_pair(v0, v1, h2, l2);
                *reinterpret_cast<uint32_t*>(outh + pa * COUT + co) = h2;
                *reinterpret_cast<uint32_t*>(outl + pa * COUT + co) = l2;
                split_pair(v2, v3, h2, l2);
                *reinterpret_cast<uint32_t*>(outh + pb * COUT + co) = h2;
                *reinterpret_cast<uint32_t*>(outl + pb * COUT + co) = l2;
            }
        }
    }
}

// ---------------- bilinear gather ----------------
__global__ __launch_bounds__(256) void gather_kernel(
    const float* __restrict__ feat, const int* __restrict__ unq, const int* __restrict__ inv,
    const float* __restrict__ xb2, float* __restrict__ out)
{
    int gwarp = (blockIdx.x * blockDim.x + threadIdx.x) >> 5;
    int lane = threadIdx.x & 31;
    if (gwarp >= NPTS) return;
    int i = gwarp;
    float f0 = __ldg(feat + (size_t)i * 16);
    float f1 = __ldg(feat + (size_t)i * 16 + 1);
    float px = ((f0 + 51.2f) / 0.4f) * 0.5f;
    float py = ((f1 + 51.2f) / 0.4f) * 0.5f;
    int seg = __ldg(inv + i);
    int bb = __ldg(unq + seg * 3);
    int fx = (int)floorf(px), fy = (int)floorf(py);
    int x0 = min(max(fx, 0), GS2 - 1), x1 = min(max(fx + 1, 0), GS2 - 1);
    int y0 = min(max(fy, 0), GS2 - 1), y1 = min(max(fy + 1, 0), GS2 - 1);
    float x0f = (float)x0, x1f = (float)x1, y0f = (float)y0, y1f = (float)y1;
    float wa = (x1f - px) * (y1f - py);
    float wb = (x1f - px) * (py - y0f);
    float wc = (px - x0f) * (y1f - py);
    float wd = (px - x0f) * (py - y0f);
    const float4* A  = reinterpret_cast<const float4*>(xb2 + ((size_t)(bb*GS2+y0)*GS2+x0)*C2) + lane;
    const float4* Bp = reinterpret_cast<const float4*>(xb2 + ((size_t)(bb*GS2+y1)*GS2+x0)*C2) + lane;
    const float4* Cp = reinterpret_cast<const float4*>(xb2 + ((size_t)(bb*GS2+y0)*GS2+x1)*C2) + lane;
    const float4* D  = reinterpret_cast<const float4*>(xb2 + ((size_t)(bb*GS2+y1)*GS2+x1)*C2) + lane;
    float4 a = __ldg(A), b = __ldg(Bp), c = __ldg(Cp), d = __ldg(D);
    float4 r;
    r.x = a.x*wa + b.x*wb + c.x*wc + d.x*wd;
    r.y = a.y*wa + b.y*wb + c.y*wc + d.y*wd;
    r.z = a.z*wa + b.z*wb + c.z*wc + d.z*wd;
    r.w = a.w*wa + b.w*wb + c.w*wc + d.w*wd;
    reinterpret_cast<float4*>(out + (size_t)i * C2)[lane] = r;
}

// ---------------- launch ----------------
extern "C" void kernel_launch(void* const* d_in, const int* in_sizes, int n_in,
                              void* d_out, int out_size)
{
    const float* feat = (const float*)d_in[0];
    const int* unq = (const int*)d_in[1];
    const int* inv = (const int*)d_in[2];
    int wb = (in_sizes[3] == 1) ? 4 : 3;
    const float* W[24];
    for (int i = 0; i < 24; i++) W[i] = (const float*)d_in[wb + i];
    float* out = (float*)d_out;

    float *p_h0, *p_hmax, *p_fv, *p_x1, *p_x2, *p_xb2, *p_occ, *p_occ1, *p_occ2;
    __nv_bfloat16 *a0h, *a0l, *a1h, *a1l, *a2h, *a2l, *a3h, *a3l, *a4h, *a4l, *a5h, *a5l;
    uint2* p_wf;
    cudaGetSymbolAddress((void**)&p_h0, g_h0);
    cudaGetSymbolAddress((void**)&p_hmax, g_hmax);
    cudaGetSymbolAddress((void**)&p_fv, g_fv);
    cudaGetSymbolAddress((void**)&p_x1, g_x1);
    cudaGetSymbolAddress((void**)&p_x2, g_x2);
    cudaGetSymbolAddress((void**)&p_xb2, g_xb2);
    cudaGetSymbolAddress((void**)&p_occ, g_occ);
    cudaGetSymbolAddress((void**)&p_occ1, g_occ1);
    cudaGetSymbolAddress((void**)&p_occ2, g_occ2);
    cudaGetSymbolAddress((void**)&a0h, g_a0h); cudaGetSymbolAddress((void**)&a0l, g_a0l);
    cudaGetSymbolAddress((void**)&a1h, g_a1h); cudaGetSymbolAddress((void**)&a1l, g_a1l);
    cudaGetSymbolAddress((void**)&a2h, g_a2h); cudaGetSymbolAddress((void**)&a2l, g_a2l);
    cudaGetSymbolAddress((void**)&a3h, g_a3h); cudaGetSymbolAddress((void**)&a3l, g_a3l);
    cudaGetSymbolAddress((void**)&a4h, g_a4h); cudaGetSymbolAddress((void**)&a4l, g_a4l);
    cudaGetSymbolAddress((void**)&a5h, g_a5h); cudaGetSymbolAddress((void**)&a5l, g_a5l);
    cudaGetSymbolAddress((void**)&p_wf, g_wfrag);

    // zero sparse-written buffers
    zero4_kernel<<<(BATCH*GS*GS*C1*2/16 + 255)/256, 256>>>((uint4*)a0h, BATCH*GS*GS*C1*2/16);
    zero4_kernel<<<(BATCH*GS*GS*C1*2/16 + 255)/256, 256>>>((uint4*)a0l, BATCH*GS*GS*C1*2/16);
    zero4_kernel<<<(MPIL*16*4/16 + 255)/256, 256>>>((uint4*)p_hmax, MPIL*16*4/16);
    zero4_kernel<<<(MPIL*64*4/16 + 255)/256, 256>>>((uint4*)p_fv, MPIL*64*4/16);
    zero4_kernel<<<(BATCH*GS*GS*4/16 + 255)/256, 256>>>((uint4*)p_occ, BATCH*GS*GS*4/16);

    // weight fragment prep
    wprep_kernel<64,64><<<(9*4*8*32 + 255)/256, 256>>>(W[6],  p_wf + FOFF1);
    wprep_kernel<64,64><<<(9*4*8*32 + 255)/256, 256>>>(W[9],  p_wf + FOFF2);
    wprep_kernel<64,64><<<(9*4*8*32 + 255)/256, 256>>>(W[12], p_wf + FOFF3);
    wprep_kernel<64,128><<<(9*4*16*32 + 255)/256, 256>>>(W[15], p_wf + FOFF4);
    wprep_kernel<128,128><<<(9*8*16*32 + 255)/256, 256>>>(W[18], p_wf + FOFF5);
    wprep_kernel<128,128><<<(9*8*16*32 + 255)/256, 256>>>(W[21], p_wf + FOFF6);

    pfn0_kernel<<<(NPTS + 255)/256, 256>>>(feat, inv, W[0], W[1], W[2], p_h0, p_hmax);
    pfn1_kernel<<<(NPTS + 127)/128, 128>>>(inv, W[3], W[4], W[5], p_h0, p_hmax, p_fv);
    scatter_kernel<<<(MPIL*8 + 255)/256, 256>>>(unq, p_fv, a0h, a0l, p_occ);
    occ1_kernel<<<(BATCH*GS*GS + 255)/256, 256>>>(p_occ, p_occ1);
    occ2_kernel<<<(BATCH*GS2*GS2 + 255)/256, 256>>>(p_occ1, p_occ2);

    dim3 blk(256);
    // L1-3: 64->64 s1, TM=2, double-buffered: grid (4, 128, 2)
    dim3 g1(GS/64, GS/2, BATCH);
    conv_mma<64,64,1,2,2,false,true,true><<<g1, blk>>>(
        a0h, a0l, p_wf + FOFF1, W[7], W[8], p_occ1, nullptr, p_x1, a1h, a1l, GS, GS, GS, GS);
    conv_mma<64,64,1,2,2,false,false,true><<<g1, blk>>>(
        a1h, a1l, p_wf + FOFF2, W[10], W[11], p_occ1, nullptr, nullptr, a2h, a2l, GS, GS, GS, GS);
    conv_mma<64,64,1,2,2,true,false,true><<<g1, blk>>>(
        a2h, a2l, p_wf + FOFF3, W[13], W[14], p_occ1, p_x1, nullptr, a3h, a3l, GS, GS, GS, GS);

    // L4: 64->128 s2, TM=1, single-buffer (smem): grid (2, 128, 2)
    dim3 g2(GS2/64, GS2, BATCH);
    conv_mma<64,128,2,1,1,false,true,true><<<g2, blk>>>(
        a3h, a3l, p_wf + FOFF4, W[16], W[17], p_occ2, nullptr, p_x2, a4h, a4l, GS, GS, GS2, GS2);
    // L5/6: 128->128 s1, TM=1, double-buffered: grid (2, 128, 2)
    conv_mma<128,128,1,1,2,false,false,true><<<g2, blk>>>(
        a4h, a4l, p_wf + FOFF5, W[19], W[20], p_occ2, nullptr, nullptr, a5h, a5l, GS2, GS2, GS2, GS2);
    conv_mma<128,128,1,1,2,true,true,false><<<g2, blk>>>(
        a5h, a5l, p_wf + FOFF6, W[22], W[23], p_occ2, p_x2, p_xb2, nullptr, nullptr, GS2, GS2, GS2, GS2);

    gather_kernel<<<(NPTS*32 + 255)/256, 256>>>(feat, unq, inv, p_xb2, out);
    (void)n_in; (void)out_size;
}

// round 7
// speedup vs baseline: 3.0250x; 1.0383x over previous
#include <cuda_runtime.h>
#include <cuda_bf16.h>
#include <cstdint>

#define NPTS 200000
#define MPIL 30000
#define BATCH 2
#define GS 256
#define GS2 128
#define C1 64
#define C2 128

// ---------------- scratch ----------------
__device__ __align__(16) __nv_bfloat16 g_a0h[BATCH*GS*GS*C1];
__device__ __align__(16) __nv_bfloat16 g_a0l[BATCH*GS*GS*C1];
__device__ __align__(16) __nv_bfloat16 g_a1h[BATCH*GS*GS*C1];
__device__ __align__(16) __nv_bfloat16 g_a1l[BATCH*GS*GS*C1];
__device__ __align__(16) __nv_bfloat16 g_a2h[BATCH*GS*GS*C1];
__device__ __align__(16) __nv_bfloat16 g_a2l[BATCH*GS*GS*C1];
__device__ __align__(16) __nv_bfloat16 g_a3h[BATCH*GS*GS*C1];
__device__ __align__(16) __nv_bfloat16 g_a3l[BATCH*GS*GS*C1];
__device__ __align__(16) __nv_bfloat16 g_a4h[BATCH*GS2*GS2*C2];
__device__ __align__(16) __nv_bfloat16 g_a4l[BATCH*GS2*GS2*C2];
__device__ __align__(16) __nv_bfloat16 g_a5h[BATCH*GS2*GS2*C2];
__device__ __align__(16) __nv_bfloat16 g_a5l[BATCH*GS2*GS2*C2];
__device__ __align__(16) float g_x1 [BATCH*GS*GS*C1];
__device__ __align__(16) float g_x2 [BATCH*GS2*GS2*C2];
__device__ __align__(16) float g_xb2[BATCH*GS2*GS2*C2];
__device__ __align__(16) float g_h0  [NPTS*16];
__device__ __align__(16) float g_hmax[MPIL*16];
__device__ __align__(16) float g_fv  [MPIL*64];
__device__ __align__(16) float g_occ [BATCH*GS*GS];
__device__ __align__(16) float g_occ1[BATCH*GS*GS];
__device__ __align__(16) float g_occ2[BATCH*GS2*GS2];

// B-fragment store (see wprep): [tap][chunk][ntile] blocks of 64 uint2
#define FOFF1 0
#define FOFF2 (FOFF1 + 18432)
#define FOFF3 (FOFF2 + 18432)
#define FOFF4 (FOFF3 + 18432)
#define FOFF5 (FOFF4 + 36864)
#define FOFF6 (FOFF5 + 73728)
#define FTOT  (FOFF6 + 73728)
__device__ __align__(16) uint2 g_wfrag[FTOT];

// ---------------- helpers ----------------
__device__ __forceinline__ uint32_t smem_u32(const void* p) {
    uint32_t a;
    asm("{ .reg .u64 t; cvta.to.shared.u64 t, %1; cvt.u32.u64 %0, t; }" : "=r"(a) : "l"(p));
    return a;
}
__device__ __forceinline__ void split_pair(float f0, float f1, uint32_t& hi2, uint32_t& lo2) {
    asm("cvt.rn.bf16x2.f32 %0, %1, %2;" : "=r"(hi2) : "f"(f1), "f"(f0));
    float f1h = __int_as_float(hi2 & 0xFFFF0000u);
    float f0h = __int_as_float(hi2 << 16);
    asm("cvt.rn.bf16x2.f32 %0, %1, %2;" : "=r"(lo2) : "f"(f1 - f1h), "f"(f0 - f0h));
}
__device__ __forceinline__ void mma16816(float* c, uint32_t a0, uint32_t a1, uint32_t a2, uint32_t a3,
                                         uint32_t b0, uint32_t b1) {
    asm volatile("mma.sync.aligned.m16n8k16.row.col.f32.bf16.bf16.f32 "
        "{%0,%1,%2,%3}, {%4,%5,%6,%7}, {%8,%9}, {%0,%1,%2,%3};"
        : "+f"(c[0]), "+f"(c[1]), "+f"(c[2]), "+f"(c[3])
        : "r"(a0), "r"(a1), "r"(a2), "r"(a3), "r"(b0), "r"(b1));
}
__device__ __forceinline__ void cp16(uint32_t dst, const void* src, bool ok) {
    int sz = ok ? 16 : 0;
    asm volatile("cp.async.cg.shared.global [%0], [%1], 16, %2;"
        :: "r"(dst), "l"(src), "r"(sz) : "memory");
}
__device__ __forceinline__ void cp_commit() {
    asm volatile("cp.async.commit_group;" ::: "memory");
}
template <int N>
__device__ __forceinline__ void cp_wait() {
    asm volatile("cp.async.wait_group %0;" :: "n"(N) : "memory");
}

// ---------------- zero ----------------
__global__ void zero4_kernel(uint4* __restrict__ p, int n4) {
    int i = blockIdx.x * blockDim.x + threadIdx.x;
    if (i < n4) p[i] = make_uint4(0u, 0u, 0u, 0u);
}

// ---------------- weight prep -> mma B fragments (split hi/lo) ----------------
template <int CIN, int COUT>
__global__ void wprep_kernel(const float* __restrict__ w, uint2* __restrict__ dst) {
    constexpr int CHUNKS = CIN / 16;
    constexpr int NTTOT = COUT / 8;
    int idx = blockIdx.x * blockDim.x + threadIdx.x;
    if (idx >= 9 * CHUNKS * NTTOT * 32) return;
    int lane = idx & 31;
    int t = idx >> 5;
    int nt = t % NTTOT;
    int t2 = t / NTTOT;
    int ch = t2 % CHUNKS;
    int tap = t2 / CHUNKS;
    int n = nt * 8 + (lane >> 2);
    int k0 = (lane & 3) * 2;
    int cib = ch * 16;
    float w00 = w[((size_t)tap * CIN + cib + k0)     * COUT + n];
    float w01 = w[((size_t)tap * CIN + cib + k0 + 1) * COUT + n];
    float w10 = w[((size_t)tap * CIN + cib + k0 + 8) * COUT + n];
    float w11 = w[((size_t)tap * CIN + cib + k0 + 9) * COUT + n];
    uint32_t r0h, r0l, r1h, r1l;
    split_pair(w00, w01, r0h, r0l);
    split_pair(w10, w11, r1h, r1l);
    uint2* blk = dst + (size_t)((tap * CHUNKS + ch) * NTTOT + nt) * 64;
    blk[lane]      = make_uint2(r0h, r1h);
    blk[32 + lane] = make_uint2(r0l, r1l);
}

// ---------------- PFN layer 0 ----------------
__global__ __launch_bounds__(256) void pfn0_kernel(
    const float* __restrict__ feat, const int* __restrict__ inv,
    const float* __restrict__ w0, const float* __restrict__ g0, const float* __restrict__ b0,
    float* __restrict__ h0, float* __restrict__ hmax)
{
    __shared__ float sw[256];
    __shared__ float sg[16], sb[16];
    if (threadIdx.x < 256) sw[threadIdx.x] = w0[threadIdx.x];
    if (threadIdx.x < 16) { sg[threadIdx.x] = g0[threadIdx.x]; sb[threadIdx.x] = b0[threadIdx.x]; }
    __syncthreads();
    int i = blockIdx.x * 256 + threadIdx.x;
    if (i >= NPTS) return;
    float f[16];
    const float4* fp = reinterpret_cast<const float4*>(feat + (size_t)i * 16);
#pragma unroll
    for (int t = 0; t < 4; t++) {
        float4 v = fp[t];
        f[4*t]=v.x; f[4*t+1]=v.y; f[4*t+2]=v.z; f[4*t+3]=v.w;
    }
    float acc[16];
#pragma unroll
    for (int j = 0; j < 16; j++) acc[j] = 0.f;
#pragma unroll
    for (int c = 0; c < 16; c++) {
        float xv = f[c];
#pragma unroll
        for (int j = 0; j < 16; j++) acc[j] += xv * sw[c * 16 + j];
    }
    int seg = inv[i];
    float h[16];
#pragma unroll
    for (int j = 0; j < 16; j++) h[j] = fmaxf(acc[j] * sg[j] + sb[j], 0.f);
    float4* hp = reinterpret_cast<float4*>(h0 + (size_t)i * 16);
#pragma unroll
    for (int t = 0; t < 4; t++) hp[t] = make_float4(h[4*t], h[4*t+1], h[4*t+2], h[4*t+3]);
    int* hm = reinterpret_cast<int*>(hmax + (size_t)seg * 16);
#pragma unroll
    for (int j = 0; j < 16; j++) atomicMax(hm + j, __float_as_int(h[j]));
}

// ---------------- PFN layer 1 ----------------
__global__ __launch_bounds__(128) void pfn1_kernel(
    const int* __restrict__ inv,
    const float* __restrict__ w1, const float* __restrict__ g1, const float* __restrict__ b1,
    const float* __restrict__ h0, const float* __restrict__ hmax, float* __restrict__ fv)
{
    __shared__ float sw[32 * 64];
    __shared__ float sg[64], sb[64];
    for (int t = threadIdx.x; t < 2048; t += blockDim.x) sw[t] = w1[t];
    if (threadIdx.x < 64) { sg[threadIdx.x] = g1[threadIdx.x]; sb[threadIdx.x] = b1[threadIdx.x]; }
    __syncthreads();
    int i = blockIdx.x * blockDim.x + threadIdx.x;
    if (i >= NPTS) return;
    int seg = inv[i];
    float x[32];
    const float4* hp = reinterpret_cast<const float4*>(h0 + (size_t)i * 16);
    const float4* mp = reinterpret_cast<const float4*>(hmax + (size_t)seg * 16);
#pragma unroll
    for (int t = 0; t < 4; t++) {
        float4 v = hp[t];
        x[4*t]=v.x; x[4*t+1]=v.y; x[4*t+2]=v.z; x[4*t+3]=v.w;
        float4 u = mp[t];
        x[16+4*t]=u.x; x[16+4*t+1]=u.y; x[16+4*t+2]=u.z; x[16+4*t+3]=u.w;
    }
    float acc[64];
#pragma unroll
    for (int j = 0; j < 64; j++) acc[j] = 0.f;
#pragma unroll
    for (int c = 0; c < 32; c++) {
        float xv = x[c];
        const float4* wr = reinterpret_cast<const float4*>(&sw[c * 64]);
#pragma unroll
        for (int k = 0; k < 16; k++) {
            float4 w = wr[k];
            acc[4*k] += xv*w.x; acc[4*k+1] += xv*w.y;
            acc[4*k+2] += xv*w.z; acc[4*k+3] += xv*w.w;
        }
    }
    int* fp = reinterpret_cast<int*>(fv + (size_t)seg * 64);
#pragma unroll
    for (int j = 0; j < 64; j++) {
        float v = fmaxf(acc[j] * sg[j] + sb[j], 0.f);
        atomicMax(fp + j, __float_as_int(v));
    }
}

// ---------------- scatter pillars -> split bf16 planes + occ ----------------
__global__ void scatter_kernel(const int* __restrict__ unq, const float* __restrict__ fv,
                               __nv_bfloat16* __restrict__ ah, __nv_bfloat16* __restrict__ al,
                               float* __restrict__ occ)
{
    int idx = blockIdx.x * blockDim.x + threadIdx.x;
    if (idx >= MPIL * 8) return;
    int m = idx >> 3, k = idx & 7;
    int bb = unq[m*3], yy = unq[m*3+1], xx = unq[m*3+2];
    const float4* fp = reinterpret_cast<const float4*>(fv) + m * 16 + 2 * k;
    float4 a = fp[0], b = fp[1];
    uint4 hw, lw;
    split_pair(a.x, a.y, hw.x, lw.x);
    split_pair(a.z, a.w, hw.y, lw.y);
    split_pair(b.x, b.y, hw.z, lw.z);
    split_pair(b.z, b.w, hw.w, lw.w);
    size_t pix = ((size_t)(bb * GS + yy) * GS + xx) * 64;
    reinterpret_cast<uint4*>(ah + pix)[k] = hw;
    reinterpret_cast<uint4*>(al + pix)[k] = lw;
    if (k == 0) occ[(bb * GS + yy) * GS + xx] = 1.0f;
}

// ---------------- occupancy dilations ----------------
__global__ void occ1_kernel(const float* __restrict__ occ, float* __restrict__ occ1) {
    int idx = blockIdx.x * blockDim.x + threadIdx.x;
    if (idx >= BATCH * GS * GS) return;
    int x = idx % GS, y = (idx / GS) % GS, b = idx / (GS * GS);
    float m = 0.f;
#pragma unroll
    for (int dy = -1; dy <= 1; dy++)
#pragma unroll
        for (int dx = -1; dx <= 1; dx++) {
            int yy = y + dy, xx = x + dx;
            if (yy >= 0 && yy < GS && xx >= 0 && xx < GS)
                m = fmaxf(m, occ[(b * GS + yy) * GS + xx]);
        }
    occ1[idx] = m;
}
__global__ void occ2_kernel(const float* __restrict__ occ1, float* __restrict__ occ2) {
    int idx = blockIdx.x * blockDim.x + threadIdx.x;
    if (idx >= BATCH * GS2 * GS2) return;
    int x = idx % GS2, y = (idx / GS2) % GS2, b = idx / (GS2 * GS2);
    float m = 0.f;
#pragma unroll
    for (int dy = -1; dy <= 1; dy++)
#pragma unroll
        for (int dx = -1; dx <= 1; dx++) {
            int yy = 2 * y + dy, xx = 2 * x + dx;
            if (yy >= 0 && yy < GS && xx >= 0 && xx < GS)
                m = fmaxf(m, occ1[(b * GS + yy) * GS + xx]);
        }
    occ2[idx] = m;
}

// ---------------- HMMA conv3x3 (split bf16, mma.sync), cp.async pipelined ----------------
template <int CIN, int COUT, int STRIDE, int TM, int BUFS, bool RESID, bool OUTF32, bool PLANES>
__global__ __launch_bounds__(256) void conv_mma(
    const __nv_bfloat16* __restrict__ inh, const __nv_bfloat16* __restrict__ inl,
    const uint2* __restrict__ wfrag,
    const float* __restrict__ gm, const float* __restrict__ bt,
    const float* __restrict__ mask, const float* __restrict__ resid,
    float* __restrict__ outf, __nv_bfloat16* __restrict__ outh, __nv_bfloat16* __restrict__ outl,
    int IH, int IW, int OH, int OW)
{
    constexpr int CHUNKS = CIN / 16;
    constexpr int NTTOT = COUT / 8;
    constexpr int NT = COUT / 16;
    constexpr int R = (TM - 1) * STRIDE + 3;
    constexpr int PXW = 64 * STRIDE + 2;
    constexpr int NV = 2 * R * PXW * 2;

    __shared__ __align__(16) __nv_bfloat16 s_in[BUFS][2][R][PXW][16];

    const int tid = threadIdx.x;
    const int wid = tid >> 5, lane = tid & 31;
    const int mwarp = wid >> 1, nwarp = wid & 1;
    const int g = lane >> 2, q = lane & 3;
    const int y0 = blockIdx.y * TM;
    const int xb = blockIdx.x * 64;
    const int bb = blockIdx.z;

    float acc[TM][NT][4];
#pragma unroll
    for (int r = 0; r < TM; r++)
#pragma unroll
        for (int nt = 0; nt < NT; nt++)
#pragma unroll
            for (int j = 0; j < 4; j++) acc[r][nt][j] = 0.f;

    auto stage = [&](int ch, int buf) {
#pragma unroll 1
        for (int i = tid; i < NV; i += 256) {
            int half = i & 1;
            int r2 = i >> 1;
            int px = r2 % PXW;
            int ry = (r2 / PXW) % R;
            int plane = r2 / (PXW * R);
            int iy = y0 * STRIDE + ry - 1;
            int ix = xb * STRIDE + px - 1;
            bool ok = (iy >= 0) && (iy < IH) && (ix >= 0) && (ix < IW);
            const __nv_bfloat16* base = plane ? inl : inh;
            const void* src = ok
                ? (const void*)(base + ((size_t)(bb * IH + iy) * IW + ix) * CIN + ch * 16 + half * 8)
                : (const void*)base;
            cp16(smem_u32(&s_in[buf][plane][ry][px][half * 8]), src, ok);
        }
        cp_commit();
    };

    if (BUFS == 2) stage(0, 0);

#pragma unroll 1
    for (int ch = 0; ch < CHUNKS; ch++) {
        const int buf = (BUFS == 2) ? (ch & 1) : 0;
        if (BUFS == 2) {
            if (ch + 1 < CHUNKS) {
                stage(ch + 1, (ch + 1) & 1);
                cp_wait<1>();
            } else {
                cp_wait<0>();
            }
            __syncthreads();
        } else {
            __syncthreads();
            stage(ch, 0);
            cp_wait<0>();
            __syncthreads();
        }
#pragma unroll
        for (int ky = 0; ky < 3; ky++) {
#pragma unroll
            for (int kx = 0; kx < 3; kx++) {
                const uint2* bbase = wfrag
                    + (size_t)(((ky * 3 + kx) * CHUNKS + ch) * NTTOT + nwarp * NT) * 64;
                uint2 bh[NT], bl[NT];
#pragma unroll
                for (int nt = 0; nt < NT; nt++) {
                    bh[nt] = __ldg(bbase + nt * 64 + lane);
                    bl[nt] = __ldg(bbase + nt * 64 + 32 + lane);
                }
                const int pxa = (mwarp * 16 + g) * STRIDE + kx;
#pragma unroll
                for (int r = 0; r < TM; r++) {
                    const int row = r * STRIDE + ky;
                    const __nv_bfloat16* pAh = &s_in[buf][0][row][pxa][q * 2];
                    const __nv_bfloat16* pAl = &s_in[buf][1][row][pxa][q * 2];
                    uint32_t ah0 = *reinterpret_cast<const uint32_t*>(pAh);
                    uint32_t ah2 = *reinterpret_cast<const uint32_t*>(pAh + 8);
                    uint32_t ah1 = *reinterpret_cast<const uint32_t*>(pAh + 8 * STRIDE * 16);
                    uint32_t ah3 = *reinterpret_cast<const uint32_t*>(pAh + 8 * STRIDE * 16 + 8);
                    uint32_t al0 = *reinterpret_cast<const uint32_t*>(pAl);
                    uint32_t al2 = *reinterpret_cast<const uint32_t*>(pAl + 8);
                    uint32_t al1 = *reinterpret_cast<const uint32_t*>(pAl + 8 * STRIDE * 16);
                    uint32_t al3 = *reinterpret_cast<const uint32_t*>(pAl + 8 * STRIDE * 16 + 8);
#pragma unroll
                    for (int nt = 0; nt < NT; nt++) {
                        mma16816(acc[r][nt], ah0, ah1, ah2, ah3, bh[nt].x, bh[nt].y);
                        mma16816(acc[r][nt], ah0, ah1, ah2, ah3, bl[nt].x, bl[nt].y);
                        mma16816(acc[r][nt], al0, al1, al2, al3, bh[nt].x, bh[nt].y);
                    }
                }
            }
        }
        __syncthreads();
    }

    // epilogue
    const int xa = xb + mwarp * 16 + g;
#pragma unroll
    for (int r = 0; r < TM; r++) {
        const int y = y0 + r;
        const size_t pa = (size_t)(bb * OH + y) * OW + xa;
        const size_t pb = pa + 8;
        const float mva = mask[pa];
        const float mvb = mask[pb];
#pragma unroll
        for (int nt = 0; nt < NT; nt++) {
            const int co = nwarp * (COUT / 2) + nt * 8 + 2 * q;
            const float g0 = __ldg(gm + co), g1 = __ldg(gm + co + 1);
            const float b0 = __ldg(bt + co), b1 = __ldg(bt + co + 1);
            float v0 = acc[r][nt][0] * g0 + b0;
            float v1 = acc[r][nt][1] * g1 + b1;
            float v2 = acc[r][nt][2] * g0 + b0;
            float v3 = acc[r][nt][3] * g1 + b1;
            if (RESID) {
                float2 ra = *reinterpret_cast<const float2*>(resid + pa * COUT + co);
                float2 rb = *reinterpret_cast<const float2*>(resid + pb * COUT + co);
                v0 = fmaxf(ra.x + v0 * mva, 0.f);
                v1 = fmaxf(ra.y + v1 * mva, 0.f);
                v2 = fmaxf(rb.x + v2 * mvb, 0.f);
                v3 = fmaxf(rb.y + v3 * mvb, 0.f);
            } else {
                v0 = fmaxf(v0, 0.f) * mva;
                v1 = fmaxf(v1, 0.f) * mva;
                v2 = fmaxf(v2, 0.f) * mvb;
                v3 = fmaxf(v3, 0.f) * mvb;
            }
            if (OUTF32) {
                *reinterpret_cast<float2*>(outf + pa * COUT + co) = make_float2(v0, v1);
                *reinterpret_cast<float2*>(outf + pb * COUT + co) = make_float2(v2, v3);
            }
            if (PLANES) {
                uint32_t h2, l2;
                split_pair(v0, v1, h2, l2);
                *reinterpret_cast<uint32_t*>(outh + pa * COUT + co) = h2;
                *reinterpret_cast<uint32_t*>(outl + pa * COUT + co) = l2;
                split_pair(v2, v3, h2, l2);
                *reinterpret_cast<uint32_t*>(outh + pb * COUT + co) = h2;
                *reinterpret_cast<uint32_t*>(outl + pb * COUT + co) = l2;
            }
        }
    }
}

// ---------------- bilinear gather ----------------
__global__ __launch_bounds__(256) void gather_kernel(
    const float* __restrict__ feat, const int* __restrict__ unq, const int* __restrict__ inv,
    const float* __restrict__ xb2, float* __restrict__ out)
{
    int gwarp = (blockIdx.x * blockDim.x + threadIdx.x) >> 5;
    int lane = threadIdx.x & 31;
    if (gwarp >= NPTS) return;
    int i = gwarp;
    float f0 = __ldg(feat + (size_t)i * 16);
    float f1 = __ldg(feat + (size_t)i * 16 + 1);
    float px = ((f0 + 51.2f) / 0.4f) * 0.5f;
    float py = ((f1 + 51.2f) / 0.4f) * 0.5f;
    int seg = __ldg(inv + i);
    int bb = __ldg(unq + seg * 3);
    int fx = (int)floorf(px), fy = (int)floorf(py);
    int x0 = min(max(fx, 0), GS2 - 1), x1 = min(max(fx + 1, 0), GS2 - 1);
    int y0 = min(max(fy, 0), GS2 - 1), y1 = min(max(fy + 1, 0), GS2 - 1);
    float x0f = (float)x0, x1f = (float)x1, y0f = (float)y0, y1f = (float)y1;
    float wa = (x1f - px) * (y1f - py);
    float wb = (x1f - px) * (py - y0f);
    float wc = (px - x0f) * (y1f - py);
    float wd = (px - x0f) * (py - y0f);
    const float4* A  = reinterpret_cast<const float4*>(xb2 + ((size_t)(bb*GS2+y0)*GS2+x0)*C2) + lane;
    const float4* Bp = reinterpret_cast<const float4*>(xb2 + ((size_t)(bb*GS2+y1)*GS2+x0)*C2) + lane;
    const float4* Cp = reinterpret_cast<const float4*>(xb2 + ((size_t)(bb*GS2+y0)*GS2+x1)*C2) + lane;
    const float4* D  = reinterpret_cast<const float4*>(xb2 + ((size_t)(bb*GS2+y1)*GS2+x1)*C2) + lane;
    float4 a = __ldg(A), b = __ldg(Bp), c = __ldg(Cp), d = __ldg(D);
    float4 r;
    r.x = a.x*wa + b.x*wb + c.x*wc + d.x*wd;
    r.y = a.y*wa + b.y*wb + c.y*wc + d.y*wd;
    r.z = a.z*wa + b.z*wb + c.z*wc + d.z*wd;
    r.w = a.w*wa + b.w*wb + c.w*wc + d.w*wd;
    reinterpret_cast<float4*>(out + (size_t)i * C2)[lane] = r;
}

// ---------------- launch ----------------
extern "C" void kernel_launch(void* const* d_in, const int* in_sizes, int n_in,
                              void* d_out, int out_size)
{
    const float* feat = (const float*)d_in[0];
    const int* unq = (const int*)d_in[1];
    const int* inv = (const int*)d_in[2];
    int wb = (in_sizes[3] == 1) ? 4 : 3;
    const float* W[24];
    for (int i = 0; i < 24; i++) W[i] = (const float*)d_in[wb + i];
    float* out = (float*)d_out;

    float *p_h0, *p_hmax, *p_fv, *p_x1, *p_x2, *p_xb2, *p_occ, *p_occ1, *p_occ2;
    __nv_bfloat16 *a0h, *a0l, *a1h, *a1l, *a2h, *a2l, *a3h, *a3l, *a4h, *a4l, *a5h, *a5l;
    uint2* p_wf;
    cudaGetSymbolAddress((void**)&p_h0, g_h0);
    cudaGetSymbolAddress((void**)&p_hmax, g_hmax);
    cudaGetSymbolAddress((void**)&p_fv, g_fv);
    cudaGetSymbolAddress((void**)&p_x1, g_x1);
    cudaGetSymbolAddress((void**)&p_x2, g_x2);
    cudaGetSymbolAddress((void**)&p_xb2, g_xb2);
    cudaGetSymbolAddress((void**)&p_occ, g_occ);
    cudaGetSymbolAddress((void**)&p_occ1, g_occ1);
    cudaGetSymbolAddress((void**)&p_occ2, g_occ2);
    cudaGetSymbolAddress((void**)&a0h, g_a0h); cudaGetSymbolAddress((void**)&a0l, g_a0l);
    cudaGetSymbolAddress((void**)&a1h, g_a1h); cudaGetSymbolAddress((void**)&a1l, g_a1l);
    cudaGetSymbolAddress((void**)&a2h, g_a2h); cudaGetSymbolAddress((void**)&a2l, g_a2l);
    cudaGetSymbolAddress((void**)&a3h, g_a3h); cudaGetSymbolAddress((void**)&a3l, g_a3l);
    cudaGetSymbolAddress((void**)&a4h, g_a4h); cudaGetSymbolAddress((void**)&a4l, g_a4l);
    cudaGetSymbolAddress((void**)&a5h, g_a5h); cudaGetSymbolAddress((void**)&a5l, g_a5l);
    cudaGetSymbolAddress((void**)&p_wf, g_wfrag);

    zero4_kernel<<<(BATCH*GS*GS*C1*2/16 + 255)/256, 256>>>((uint4*)a0h, BATCH*GS*GS*C1*2/16);
    zero4_kernel<<<(BATCH*GS*GS*C1*2/16 + 255)/256, 256>>>((uint4*)a0l, BATCH*GS*GS*C1*2/16);
    zero4_kernel<<<(MPIL*16*4/16 + 255)/256, 256>>>((uint4*)p_hmax, MPIL*16*4/16);
    zero4_kernel<<<(MPIL*64*4/16 + 255)/256, 256>>>((uint4*)p_fv, MPIL*64*4/16);
    zero4_kernel<<<(BATCH*GS*GS*4/16 + 255)/256, 256>>>((uint4*)p_occ, BATCH*GS*GS*4/16);

    wprep_kernel<64,64><<<(9*4*8*32 + 255)/256, 256>>>(W[6],  p_wf + FOFF1);
    wprep_kernel<64,64><<<(9*4*8*32 + 255)/256, 256>>>(W[9],  p_wf + FOFF2);
    wprep_kernel<64,64><<<(9*4*8*32 + 255)/256, 256>>>(W[12], p_wf + FOFF3);
    wprep_kernel<64,128><<<(9*4*16*32 + 255)/256, 256>>>(W[15], p_wf + FOFF4);
    wprep_kernel<128,128><<<(9*8*16*32 + 255)/256, 256>>>(W[18], p_wf + FOFF5);
    wprep_kernel<128,128><<<(9*8*16*32 + 255)/256, 256>>>(W[21], p_wf + FOFF6);

    pfn0_kernel<<<(NPTS + 255)/256, 256>>>(feat, inv, W[0], W[1], W[2], p_h0, p_hmax);
    pfn1_kernel<<<(NPTS + 127)/128, 128>>>(inv, W[3], W[4], W[5], p_h0, p_hmax, p_fv);
    scatter_kernel<<<(MPIL*8 + 255)/256, 256>>>(unq, p_fv, a0h, a0l, p_occ);
    occ1_kernel<<<(BATCH*GS*GS + 255)/256, 256>>>(p_occ, p_occ1);
    occ2_kernel<<<(BATCH*GS2*GS2 + 255)/256, 256>>>(p_occ1, p_occ2);

    dim3 blk(256);
    // L1-3: 64->64 s1, TM=4, double-buffered: grid (4, 64, 2)
    dim3 g1(GS/64, GS/4, BATCH);
    conv_mma<64,64,1,4,2,false,true,true><<<g1, blk>>>(
        a0h, a0l, p_wf + FOFF1, W[7], W[8], p_occ1, nullptr, p_x1, a1h, a1l, GS, GS, GS, GS);
    conv_mma<64,64,1,4,2,false,false,true><<<g1, blk>>>(
        a1h, a1l, p_wf + FOFF2, W[10], W[11], p_occ1, nullptr, nullptr, a2h, a2l, GS, GS, GS, GS);
    conv_mma<64,64,1,4,2,true,false,true><<<g1, blk>>>(
        a2h, a2l, p_wf + FOFF3, W[13], W[14], p_occ1, p_x1, nullptr, a3h, a3l, GS, GS, GS, GS);

    // L4: 64->128 s2, TM=2, double-buffered: grid (2, 64, 2)
    dim3 g2(GS2/64, GS2/2, BATCH);
    conv_mma<64,128,2,2,2,false,true,true><<<g2, blk>>>(
        a3h, a3l, p_wf + FOFF4, W[16], W[17], p_occ2, nullptr, p_x2, a4h, a4l, GS, GS, GS2, GS2);
    // L5/6: 128->128 s1, TM=2, double-buffered: grid (2, 64, 2)
    conv_mma<128,128,1,2,2,false,false,true><<<g2, blk>>>(
        a4h, a4l, p_wf + FOFF5, W[19], W[20], p_occ2, nullptr, nullptr, a5h, a5l, GS2, GS2, GS2, GS2);
    conv_mma<128,128,1,2,2,true,true,false><<<g2, blk>>>(
        a5h, a5l, p_wf + FOFF6, W[22], W[23], p_occ2, p_x2, p_xb2, nullptr, nullptr, GS2, GS2, GS2, GS2);

    gather_kernel<<<(NPTS*32 + 255)/256, 256>>>(feat, unq, inv, p_xb2, out);
    (void)n_in; (void)out_size;
}

// round 8
// speedup vs baseline: 3.1216x; 1.0319x over previous
#include <cuda_runtime.h>
#include <cuda_bf16.h>
#include <cstdint>

#define NPTS 200000
#define MPIL 30000
#define BATCH 2
#define GS 256
#define GS2 128
#define C1 64
#define C2 128

// ---------------- scratch ----------------
__device__ __align__(16) __nv_bfloat16 g_a0h[BATCH*GS*GS*C1];
__device__ __align__(16) __nv_bfloat16 g_a0l[BATCH*GS*GS*C1];
__device__ __align__(16) __nv_bfloat16 g_a1h[BATCH*GS*GS*C1];
__device__ __align__(16) __nv_bfloat16 g_a1l[BATCH*GS*GS*C1];
__device__ __align__(16) __nv_bfloat16 g_a2h[BATCH*GS*GS*C1];
__device__ __align__(16) __nv_bfloat16 g_a2l[BATCH*GS*GS*C1];
__device__ __align__(16) __nv_bfloat16 g_a3h[BATCH*GS*GS*C1];
__device__ __align__(16) __nv_bfloat16 g_a3l[BATCH*GS*GS*C1];
__device__ __align__(16) __nv_bfloat16 g_a4h[BATCH*GS2*GS2*C2];
__device__ __align__(16) __nv_bfloat16 g_a4l[BATCH*GS2*GS2*C2];
__device__ __align__(16) __nv_bfloat16 g_a5h[BATCH*GS2*GS2*C2];
__device__ __align__(16) __nv_bfloat16 g_a5l[BATCH*GS2*GS2*C2];
__device__ __align__(16) float g_x1 [BATCH*GS*GS*C1];
__device__ __align__(16) float g_x2 [BATCH*GS2*GS2*C2];
__device__ __align__(16) float g_xb2[BATCH*GS2*GS2*C2];
__device__ __align__(16) float g_h0  [NPTS*16];
__device__ __align__(16) float g_hmax[MPIL*16];
__device__ __align__(16) float g_fv  [MPIL*64];
__device__ __align__(16) float g_occ [BATCH*GS*GS];
__device__ __align__(16) float g_occ1[BATCH*GS*GS];
__device__ __align__(16) float g_occ2[BATCH*GS2*GS2];

// B-fragment store (see wprep): [tap][chunk][ntile] blocks of 64 uint2
#define FOFF1 0
#define FOFF2 (FOFF1 + 18432)
#define FOFF3 (FOFF2 + 18432)
#define FOFF4 (FOFF3 + 18432)
#define FOFF5 (FOFF4 + 36864)
#define FOFF6 (FOFF5 + 73728)
#define FTOT  (FOFF6 + 73728)
__device__ __align__(16) uint2 g_wfrag[FTOT];

// ---------------- helpers ----------------
__device__ __forceinline__ uint32_t smem_u32(const void* p) {
    uint32_t a;
    asm("{ .reg .u64 t; cvta.to.shared.u64 t, %1; cvt.u32.u64 %0, t; }" : "=r"(a) : "l"(p));
    return a;
}
__device__ __forceinline__ void split_pair(float f0, float f1, uint32_t& hi2, uint32_t& lo2) {
    asm("cvt.rn.bf16x2.f32 %0, %1, %2;" : "=r"(hi2) : "f"(f1), "f"(f0));
    float f1h = __int_as_float(hi2 & 0xFFFF0000u);
    float f0h = __int_as_float(hi2 << 16);
    asm("cvt.rn.bf16x2.f32 %0, %1, %2;" : "=r"(lo2) : "f"(f1 - f1h), "f"(f0 - f0h));
}
__device__ __forceinline__ void mma16816(float* c, const uint32_t* a,
                                         uint32_t b0, uint32_t b1) {
    asm volatile("mma.sync.aligned.m16n8k16.row.col.f32.bf16.bf16.f32 "
        "{%0,%1,%2,%3}, {%4,%5,%6,%7}, {%8,%9}, {%0,%1,%2,%3};"
        : "+f"(c[0]), "+f"(c[1]), "+f"(c[2]), "+f"(c[3])
        : "r"(a[0]), "r"(a[1]), "r"(a[2]), "r"(a[3]), "r"(b0), "r"(b1));
}
__device__ __forceinline__ void cp16(uint32_t dst, const void* src, bool ok) {
    int sz = ok ? 16 : 0;
    asm volatile("cp.async.cg.shared.global [%0], [%1], 16, %2;"
        :: "r"(dst), "l"(src), "r"(sz) : "memory");
}
__device__ __forceinline__ void cp_commit() {
    asm volatile("cp.async.commit_group;" ::: "memory");
}
template <int N>
__device__ __forceinline__ void cp_wait() {
    asm volatile("cp.async.wait_group %0;" :: "n"(N) : "memory");
}

// ---------------- zero ----------------
__global__ void zero4_kernel(uint4* __restrict__ p, int n4) {
    int i = blockIdx.x * blockDim.x + threadIdx.x;
    if (i < n4) p[i] = make_uint4(0u, 0u, 0u, 0u);
}

// ---------------- weight prep -> mma B fragments (split hi/lo) ----------------
template <int CIN, int COUT>
__global__ void wprep_kernel(const float* __restrict__ w, uint2* __restrict__ dst) {
    constexpr int CHUNKS = CIN / 16;
    constexpr int NTTOT = COUT / 8;
    int idx = blockIdx.x * blockDim.x + threadIdx.x;
    if (idx >= 9 * CHUNKS * NTTOT * 32) return;
    int lane = idx & 31;
    int t = idx >> 5;
    int nt = t % NTTOT;
    int t2 = t / NTTOT;
    int ch = t2 % CHUNKS;
    int tap = t2 / CHUNKS;
    int n = nt * 8 + (lane >> 2);
    int k0 = (lane & 3) * 2;
    int cib = ch * 16;
    float w00 = w[((size_t)tap * CIN + cib + k0)     * COUT + n];
    float w01 = w[((size_t)tap * CIN + cib + k0 + 1) * COUT + n];
    float w10 = w[((size_t)tap * CIN + cib + k0 + 8) * COUT + n];
    float w11 = w[((size_t)tap * CIN + cib + k0 + 9) * COUT + n];
    uint32_t r0h, r0l, r1h, r1l;
    split_pair(w00, w01, r0h, r0l);
    split_pair(w10, w11, r1h, r1l);
    uint2* blk = dst + (size_t)((tap * CHUNKS + ch) * NTTOT + nt) * 64;
    blk[lane]      = make_uint2(r0h, r1h);
    blk[32 + lane] = make_uint2(r0l, r1l);
}

// ---------------- PFN layer 0 ----------------
__global__ __launch_bounds__(256) void pfn0_kernel(
    const float* __restrict__ feat, const int* __restrict__ inv,
    const float* __restrict__ w0, const float* __restrict__ g0, const float* __restrict__ b0,
    float* __restrict__ h0, float* __restrict__ hmax)
{
    __shared__ float sw[256];
    __shared__ float sg[16], sb[16];
    if (threadIdx.x < 256) sw[threadIdx.x] = w0[threadIdx.x];
    if (threadIdx.x < 16) { sg[threadIdx.x] = g0[threadIdx.x]; sb[threadIdx.x] = b0[threadIdx.x]; }
    __syncthreads();
    int i = blockIdx.x * 256 + threadIdx.x;
    if (i >= NPTS) return;
    float f[16];
    const float4* fp = reinterpret_cast<const float4*>(feat + (size_t)i * 16);
#pragma unroll
    for (int t = 0; t < 4; t++) {
        float4 v = fp[t];
        f[4*t]=v.x; f[4*t+1]=v.y; f[4*t+2]=v.z; f[4*t+3]=v.w;
    }
    float acc[16];
#pragma unroll
    for (int j = 0; j < 16; j++) acc[j] = 0.f;
#pragma unroll
    for (int c = 0; c < 16; c++) {
        float xv = f[c];
#pragma unroll
        for (int j = 0; j < 16; j++) acc[j] += xv * sw[c * 16 + j];
    }
    int seg = inv[i];
    float h[16];
#pragma unroll
    for (int j = 0; j < 16; j++) h[j] = fmaxf(acc[j] * sg[j] + sb[j], 0.f);
    float4* hp = reinterpret_cast<float4*>(h0 + (size_t)i * 16);
#pragma unroll
    for (int t = 0; t < 4; t++) hp[t] = make_float4(h[4*t], h[4*t+1], h[4*t+2], h[4*t+3]);
    int* hm = reinterpret_cast<int*>(hmax + (size_t)seg * 16);
#pragma unroll
    for (int j = 0; j < 16; j++) atomicMax(hm + j, __float_as_int(h[j]));
}

// ---------------- PFN layer 1 ----------------
__global__ __launch_bounds__(128) void pfn1_kernel(
    const int* __restrict__ inv,
    const float* __restrict__ w1, const float* __restrict__ g1, const float* __restrict__ b1,
    const float* __restrict__ h0, const float* __restrict__ hmax, float* __restrict__ fv)
{
    __shared__ float sw[32 * 64];
    __shared__ float sg[64], sb[64];
    for (int t = threadIdx.x; t < 2048; t += blockDim.x) sw[t] = w1[t];
    if (threadIdx.x < 64) { sg[threadIdx.x] = g1[threadIdx.x]; sb[threadIdx.x] = b1[threadIdx.x]; }
    __syncthreads();
    int i = blockIdx.x * blockDim.x + threadIdx.x;
    if (i >= NPTS) return;
    int seg = inv[i];
    float x[32];
    const float4* hp = reinterpret_cast<const float4*>(h0 + (size_t)i * 16);
    const float4* mp = reinterpret_cast<const float4*>(hmax + (size_t)seg * 16);
#pragma unroll
    for (int t = 0; t < 4; t++) {
        float4 v = hp[t];
        x[4*t]=v.x; x[4*t+1]=v.y; x[4*t+2]=v.z; x[4*t+3]=v.w;
        float4 u = mp[t];
        x[16+4*t]=u.x; x[16+4*t+1]=u.y; x[16+4*t+2]=u.z; x[16+4*t+3]=u.w;
    }
    float acc[64];
#pragma unroll
    for (int j = 0; j < 64; j++) acc[j] = 0.f;
#pragma unroll
    for (int c = 0; c < 32; c++) {
        float xv = x[c];
        const float4* wr = reinterpret_cast<const float4*>(&sw[c * 64]);
#pragma unroll
        for (int k = 0; k < 16; k++) {
            float4 w = wr[k];
            acc[4*k] += xv*w.x; acc[4*k+1] += xv*w.y;
            acc[4*k+2] += xv*w.z; acc[4*k+3] += xv*w.w;
        }
    }
    int* fp = reinterpret_cast<int*>(fv + (size_t)seg * 64);
#pragma unroll
    for (int j = 0; j < 64; j++) {
        float v = fmaxf(acc[j] * sg[j] + sb[j], 0.f);
        atomicMax(fp + j, __float_as_int(v));
    }
}

// ---------------- scatter pillars -> split bf16 planes + occ ----------------
__global__ void scatter_kernel(const int* __restrict__ unq, const float* __restrict__ fv,
                               __nv_bfloat16* __restrict__ ah, __nv_bfloat16* __restrict__ al,
                               float* __restrict__ occ)
{
    int idx = blockIdx.x * blockDim.x + threadIdx.x;
    if (idx >= MPIL * 8) return;
    int m = idx >> 3, k = idx & 7;
    int bb = unq[m*3], yy = unq[m*3+1], xx = unq[m*3+2];
    const float4* fp = reinterpret_cast<const float4*>(fv) + m * 16 + 2 * k;
    float4 a = fp[0], b = fp[1];
    uint4 hw, lw;
    split_pair(a.x, a.y, hw.x, lw.x);
    split_pair(a.z, a.w, hw.y, lw.y);
    split_pair(b.x, b.y, hw.z, lw.z);
    split_pair(b.z, b.w, hw.w, lw.w);
    size_t pix = ((size_t)(bb * GS + yy) * GS + xx) * 64;
    reinterpret_cast<uint4*>(ah + pix)[k] = hw;
    reinterpret_cast<uint4*>(al + pix)[k] = lw;
    if (k == 0) occ[(bb * GS + yy) * GS + xx] = 1.0f;
}

// ---------------- occupancy dilations ----------------
__global__ void occ1_kernel(const float* __restrict__ occ, float* __restrict__ occ1) {
    int idx = blockIdx.x * blockDim.x + threadIdx.x;
    if (idx >= BATCH * GS * GS) return;
    int x = idx % GS, y = (idx / GS) % GS, b = idx / (GS * GS);
    float m = 0.f;
#pragma unroll
    for (int dy = -1; dy <= 1; dy++)
#pragma unroll
        for (int dx = -1; dx <= 1; dx++) {
            int yy = y + dy, xx = x + dx;
            if (yy >= 0 && yy < GS && xx >= 0 && xx < GS)
                m = fmaxf(m, occ[(b * GS + yy) * GS + xx]);
        }
    occ1[idx] = m;
}
__global__ void occ2_kernel(const float* __restrict__ occ1, float* __restrict__ occ2) {
    int idx = blockIdx.x * blockDim.x + threadIdx.x;
    if (idx >= BATCH * GS2 * GS2) return;
    int x = idx % GS2, y = (idx / GS2) % GS2, b = idx / (GS2 * GS2);
    float m = 0.f;
#pragma unroll
    for (int dy = -1; dy <= 1; dy++)
#pragma unroll
        for (int dx = -1; dx <= 1; dx++) {
            int yy = 2 * y + dy, xx = 2 * x + dx;
            if (yy >= 0 && yy < GS && xx >= 0 && xx < GS)
                m = fmaxf(m, occ1[(b * GS + yy) * GS + xx]);
        }
    occ2[idx] = m;
}

// ---------------- HMMA conv3x3 (split bf16), cp.async pipelined, ILP-reordered ----------------
// BUFS==3: depth-1 prefetch, SINGLE sync per chunk. BUFS==2: classic two-sync.
template <int CIN, int COUT, int STRIDE, int TM, int BUFS, bool RESID, bool OUTF32, bool PLANES>
__global__ __launch_bounds__(256) void conv_mma(
    const __nv_bfloat16* __restrict__ inh, const __nv_bfloat16* __restrict__ inl,
    const uint2* __restrict__ wfrag,
    const float* __restrict__ gm, const float* __restrict__ bt,
    const float* __restrict__ mask, const float* __restrict__ resid,
    float* __restrict__ outf, __nv_bfloat16* __restrict__ outh, __nv_bfloat16* __restrict__ outl,
    int IH, int IW, int OH, int OW)
{
    constexpr int CHUNKS = CIN / 16;
    constexpr int NTTOT = COUT / 8;
    constexpr int NT = COUT / 16;
    constexpr int R = (TM - 1) * STRIDE + 3;
    constexpr int PXW = 64 * STRIDE + 2;
    constexpr int NV = 2 * R * PXW * 2;

    extern __shared__ __align__(16) char smem_raw[];
    __nv_bfloat16* s_in = reinterpret_cast<__nv_bfloat16*>(smem_raw);
    // layout: [buf][plane][ry][px][16]
    auto sidx = [&](int buf, int plane, int ry, int px) {
        return (((buf * 2 + plane) * R + ry) * PXW + px) * 16;
    };

    const int tid = threadIdx.x;
    const int wid = tid >> 5, lane = tid & 31;
    const int mwarp = wid >> 1, nwarp = wid & 1;
    const int g = lane >> 2, q = lane & 3;
    const int y0 = blockIdx.y * TM;
    const int xb = blockIdx.x * 64;
    const int bb = blockIdx.z;

    float acc[TM][NT][4];
#pragma unroll
    for (int r = 0; r < TM; r++)
#pragma unroll
        for (int nt = 0; nt < NT; nt++)
#pragma unroll
            for (int j = 0; j < 4; j++) acc[r][nt][j] = 0.f;

    auto stage = [&](int ch, int buf) {
#pragma unroll 1
        for (int i = tid; i < NV; i += 256) {
            int half = i & 1;
            int r2 = i >> 1;
            int px = r2 % PXW;
            int ry = (r2 / PXW) % R;
            int plane = r2 / (PXW * R);
            int iy = y0 * STRIDE + ry - 1;
            int ix = xb * STRIDE + px - 1;
            bool ok = (iy >= 0) && (iy < IH) && (ix >= 0) && (ix < IW);
            const __nv_bfloat16* base = plane ? inl : inh;
            const void* src = ok
                ? (const void*)(base + ((size_t)(bb * IH + iy) * IW + ix) * CIN + ch * 16 + half * 8)
                : (const void*)base;
            cp16(smem_u32(s_in + sidx(buf, plane, ry, px) + half * 8), src, ok);
        }
        cp_commit();
    };

    stage(0, 0);

#pragma unroll 1
    for (int ch = 0; ch < CHUNKS; ch++) {
        const int buf = (BUFS == 3) ? (ch % 3) : (ch & 1);
        if (ch + 1 < CHUNKS) {
            stage(ch + 1, (BUFS == 3) ? ((ch + 1) % 3) : ((ch + 1) & 1));
            cp_wait<1>();
        } else {
            cp_wait<0>();
        }
        __syncthreads();
#pragma unroll
        for (int ky = 0; ky < 3; ky++) {
#pragma unroll
            for (int kx = 0; kx < 3; kx++) {
                const uint2* bbase = wfrag
                    + (size_t)(((ky * 3 + kx) * CHUNKS + ch) * NTTOT + nwarp * NT) * 64;
                uint2 bh[NT], bl[NT];
#pragma unroll
                for (int nt = 0; nt < NT; nt++) {
                    bh[nt] = __ldg(bbase + nt * 64 + lane);
                    bl[nt] = __ldg(bbase + nt * 64 + 32 + lane);
                }
                const int pxa = (mwarp * 16 + g) * STRIDE + kx;
                uint32_t Ah[TM][4], Al[TM][4];
#pragma unroll
                for (int r = 0; r < TM; r++) {
                    const int row = r * STRIDE + ky;
                    const __nv_bfloat16* pAh = s_in + sidx(buf, 0, row, pxa) + q * 2;
                    const __nv_bfloat16* pAl = s_in + sidx(buf, 1, row, pxa) + q * 2;
                    Ah[r][0] = *reinterpret_cast<const uint32_t*>(pAh);
                    Ah[r][2] = *reinterpret_cast<const uint32_t*>(pAh + 8);
                    Ah[r][1] = *reinterpret_cast<const uint32_t*>(pAh + 8 * STRIDE * 16);
                    Ah[r][3] = *reinterpret_cast<const uint32_t*>(pAh + 8 * STRIDE * 16 + 8);
                    Al[r][0] = *reinterpret_cast<const uint32_t*>(pAl);
                    Al[r][2] = *reinterpret_cast<const uint32_t*>(pAl + 8);
                    Al[r][1] = *reinterpret_cast<const uint32_t*>(pAl + 8 * STRIDE * 16);
                    Al[r][3] = *reinterpret_cast<const uint32_t*>(pAl + 8 * STRIDE * 16 + 8);
                }
                // three product sweeps; acc reuse distance = TM*NT independent MMAs
#pragma unroll
                for (int r = 0; r < TM; r++)
#pragma unroll
                    for (int nt = 0; nt < NT; nt++)
                        mma16816(acc[r][nt], Ah[r], bh[nt].x, bh[nt].y);
#pragma unroll
                for (int r = 0; r < TM; r++)
#pragma unroll
                    for (int nt = 0; nt < NT; nt++)
                        mma16816(acc[r][nt], Ah[r], bl[nt].x, bl[nt].y);
#pragma unroll
                for (int r = 0; r < TM; r++)
#pragma unroll
                    for (int nt = 0; nt < NT; nt++)
                        mma16816(acc[r][nt], Al[r], bh[nt].x, bh[nt].y);
            }
        }
        if (BUFS == 2) __syncthreads();
    }

    // epilogue
    const int xa = xb + mwarp * 16 + g;
#pragma unroll
    for (int r = 0; r < TM; r++) {
        const int y = y0 + r;
        const size_t pa = (size_t)(bb * OH + y) * OW + xa;
        const size_t pb = pa + 8;
        const float mva = mask[pa];
        const float mvb = mask[pb];
#pragma unroll
        for (int nt = 0; nt < NT; nt++) {
            const int co = nwarp * (COUT / 2) + nt * 8 + 2 * q;
            const float g0 = __ldg(gm + co), g1 = __ldg(gm + co + 1);
            const float b0 = __ldg(bt + co), b1 = __ldg(bt + co + 1);
            float v0 = acc[r][nt][0] * g0 + b0;
            float v1 = acc[r][nt][1] * g1 + b1;
            float v2 = acc[r][nt][2] * g0 + b0;
            float v3 = acc[r][nt][3] * g1 + b1;
            if (RESID) {
                float2 ra = *reinterpret_cast<const float2*>(resid + pa * COUT + co);
                float2 rb = *reinterpret_cast<const float2*>(resid + pb * COUT + co);
                v0 = fmaxf(ra.x + v0 * mva, 0.f);
                v1 = fmaxf(ra.y + v1 * mva, 0.f);
                v2 = fmaxf(rb.x + v2 * mvb, 0.f);
                v3 = fmaxf(rb.y + v3 * mvb, 0.f);
            } else {
                v0 = fmaxf(v0, 0.f) * mva;
                v1 = fmaxf(v1, 0.f) * mva;
                v2 = fmaxf(v2, 0.f) * mvb;
                v3 = fmaxf(v3, 0.f) * mvb;
            }
            if (OUTF32) {
                *reinterpret_cast<float2*>(outf + pa * COUT + co) = make_float2(v0, v1);
                *reinterpret_cast<float2*>(outf + pb * COUT + co) = make_float2(v2, v3);
            }
            if (PLANES) {
                uint32_t h2, l2;
                split_pair(v0, v1, h2, l2);
                *reinterpret_cast<uint32_t*>(outh + pa * COUT + co) = h2;
                *reinterpret_cast<uint32_t*>(outl + pa * COUT + co) = l2;
                split_pair(v2, v3, h2, l2);
                *reinterpret_cast<uint32_t*>(outh + pb * COUT + co) = h2;
                *reinterpret_cast<uint32_t*>(outl + pb * COUT + co) = l2;
            }
        }
    }
}

// ---------------- bilinear gather ----------------
__global__ __launch_bounds__(256) void gather_kernel(
    const float* __restrict__ feat, const int* __restrict__ unq, const int* __restrict__ inv,
    const float* __restrict__ xb2, float* __restrict__ out)
{
    int gwarp = (blockIdx.x * blockDim.x + threadIdx.x) >> 5;
    int lane = threadIdx.x & 31;
    if (gwarp >= NPTS) return;
    int i = gwarp;
    float f0 = __ldg(feat + (size_t)i * 16);
    float f1 = __ldg(feat + (size_t)i * 16 + 1);
    float px = ((f0 + 51.2f) / 0.4f) * 0.5f;
    float py = ((f1 + 51.2f) / 0.4f) * 0.5f;
    int seg = __ldg(inv + i);
    int bb = __ldg(unq + seg * 3);
    int fx = (int)floorf(px), fy = (int)floorf(py);
    int x0 = min(max(fx, 0), GS2 - 1), x1 = min(max(fx + 1, 0), GS2 - 1);
    int y0 = min(max(fy, 0), GS2 - 1), y1 = min(max(fy + 1, 0), GS2 - 1);
    float x0f = (float)x0, x1f = (float)x1, y0f = (float)y0, y1f = (float)y1;
    float wa = (x1f - px) * (y1f - py);
    float wb = (x1f - px) * (py - y0f);
    float wc = (px - x0f) * (y1f - py);
    float wd = (px - x0f) * (py - y0f);
    const float4* A  = reinterpret_cast<const float4*>(xb2 + ((size_t)(bb*GS2+y0)*GS2+x0)*C2) + lane;
    const float4* Bp = reinterpret_cast<const float4*>(xb2 + ((size_t)(bb*GS2+y1)*GS2+x0)*C2) + lane;
    const float4* Cp = reinterpret_cast<const float4*>(xb2 + ((size_t)(bb*GS2+y0)*GS2+x1)*C2) + lane;
    const float4* D  = reinterpret_cast<const float4*>(xb2 + ((size_t)(bb*GS2+y1)*GS2+x1)*C2) + lane;
    float4 a = __ldg(A), b = __ldg(Bp), c = __ldg(Cp), d = __ldg(D);
    float4 r;
    r.x = a.x*wa + b.x*wb + c.x*wc + d.x*wd;
    r.y = a.y*wa + b.y*wb + c.y*wc + d.y*wd;
    r.z = a.z*wa + b.z*wb + c.z*wc + d.z*wd;
    r.w = a.w*wa + b.w*wb + c.w*wc + d.w*wd;
    reinterpret_cast<float4*>(out + (size_t)i * C2)[lane] = r;
}

// ---------------- launch ----------------
extern "C" void kernel_launch(void* const* d_in, const int* in_sizes, int n_in,
                              void* d_out, int out_size)
{
    const float* feat = (const float*)d_in[0];
    const int* unq = (const int*)d_in[1];
    const int* inv = (const int*)d_in[2];
    int wb = (in_sizes[3] == 1) ? 4 : 3;
    const float* W[24];
    for (int i = 0; i < 24; i++) W[i] = (const float*)d_in[wb + i];
    float* out = (float*)d_out;

    float *p_h0, *p_hmax, *p_fv, *p_x1, *p_x2, *p_xb2, *p_occ, *p_occ1, *p_occ2;
    __nv_bfloat16 *a0h, *a0l, *a1h, *a1l, *a2h, *a2l, *a3h, *a3l, *a4h, *a4l, *a5h, *a5l;
    uint2* p_wf;
    cudaGetSymbolAddress((void**)&p_h0, g_h0);
    cudaGetSymbolAddress((void**)&p_hmax, g_hmax);
    cudaGetSymbolAddress((void**)&p_fv, g_fv);
    cudaGetSymbolAddress((void**)&p_x1, g_x1);
    cudaGetSymbolAddress((void**)&p_x2, g_x2);
    cudaGetSymbolAddress((void**)&p_xb2, g_xb2);
    cudaGetSymbolAddress((void**)&p_occ, g_occ);
    cudaGetSymbolAddress((void**)&p_occ1, g_occ1);
    cudaGetSymbolAddress((void**)&p_occ2, g_occ2);
    cudaGetSymbolAddress((void**)&a0h, g_a0h); cudaGetSymbolAddress((void**)&a0l, g_a0l);
    cudaGetSymbolAddress((void**)&a1h, g_a1h); cudaGetSymbolAddress((void**)&a1l, g_a1l);
    cudaGetSymbolAddress((void**)&a2h, g_a2h); cudaGetSymbolAddress((void**)&a2l, g_a2l);
    cudaGetSymbolAddress((void**)&a3h, g_a3h); cudaGetSymbolAddress((void**)&a3l, g_a3l);
    cudaGetSymbolAddress((void**)&a4h, g_a4h); cudaGetSymbolAddress((void**)&a4l, g_a4l);
    cudaGetSymbolAddress((void**)&a5h, g_a5h); cudaGetSymbolAddress((void**)&a5l, g_a5l);
    cudaGetSymbolAddress((void**)&p_wf, g_wfrag);

    zero4_kernel<<<(BATCH*GS*GS*C1*2/16 + 255)/256, 256>>>((uint4*)a0h, BATCH*GS*GS*C1*2/16);
    zero4_kernel<<<(BATCH*GS*GS*C1*2/16 + 255)/256, 256>>>((uint4*)a0l, BATCH*GS*GS*C1*2/16);
    zero4_kernel<<<(MPIL*16*4/16 + 255)/256, 256>>>((uint4*)p_hmax, MPIL*16*4/16);
    zero4_kernel<<<(MPIL*64*4/16 + 255)/256, 256>>>((uint4*)p_fv, MPIL*64*4/16);
    zero4_kernel<<<(BATCH*GS*GS*4/16 + 255)/256, 256>>>((uint4*)p_occ, BATCH*GS*GS*4/16);

    wprep_kernel<64,64><<<(9*4*8*32 + 255)/256, 256>>>(W[6],  p_wf + FOFF1);
    wprep_kernel<64,64><<<(9*4*8*32 + 255)/256, 256>>>(W[9],  p_wf + FOFF2);
    wprep_kernel<64,64><<<(9*4*8*32 + 255)/256, 256>>>(W[12], p_wf + FOFF3);
    wprep_kernel<64,128><<<(9*4*16*32 + 255)/256, 256>>>(W[15], p_wf + FOFF4);
    wprep_kernel<128,128><<<(9*8*16*32 + 255)/256, 256>>>(W[18], p_wf + FOFF5);
    wprep_kernel<128,128><<<(9*8*16*32 + 255)/256, 256>>>(W[21], p_wf + FOFF6);

    pfn0_kernel<<<(NPTS + 255)/256, 256>>>(feat, inv, W[0], W[1], W[2], p_h0, p_hmax);
    pfn1_kernel<<<(NPTS + 127)/128, 128>>>(inv, W[3], W[4], W[5], p_h0, p_hmax, p_fv);
    scatter_kernel<<<(MPIL*8 + 255)/256, 256>>>(unq, p_fv, a0h, a0l, p_occ);
    occ1_kernel<<<(BATCH*GS*GS + 255)/256, 256>>>(p_occ, p_occ1);
    occ2_kernel<<<(BATCH*GS2*GS2 + 255)/256, 256>>>(p_occ1, p_occ2);

    // dynamic smem sizes: BUFS * 2 * R * PXW * 16 * 2B
    const int S13 = 3 * 2 * 6 * 66 * 16 * 2;   // 76032 (TM=4, s1, BUFS=3)
    const int S4  = 2 * 2 * 5 * 130 * 16 * 2;  // 83200 (TM=2, s2, BUFS=2)
    const int S56 = 3 * 2 * 4 * 66 * 16 * 2;   // 50688 (TM=2, s1, BUFS=3)
    cudaFuncSetAttribute(conv_mma<64,64,1,4,3,false,true,true>,   cudaFuncAttributeMaxDynamicSharedMemorySize, S13);
    cudaFuncSetAttribute(conv_mma<64,64,1,4,3,false,false,true>,  cudaFuncAttributeMaxDynamicSharedMemorySize, S13);
    cudaFuncSetAttribute(conv_mma<64,64,1,4,3,true,false,true>,   cudaFuncAttributeMaxDynamicSharedMemorySize, S13);
    cudaFuncSetAttribute(conv_mma<64,128,2,2,2,false,true,true>,  cudaFuncAttributeMaxDynamicSharedMemorySize, S4);
    cudaFuncSetAttribute(conv_mma<128,128,1,2,3,false,false,true>,cudaFuncAttributeMaxDynamicSharedMemorySize, S56);
    cudaFuncSetAttribute(conv_mma<128,128,1,2,3,true,true,false>, cudaFuncAttributeMaxDynamicSharedMemorySize, S56);

    dim3 blk(256);
    // L1-3: 64->64 s1, TM=4, BUFS=3 single-sync: grid (4, 64, 2)
    dim3 g1(GS/64, GS/4, BATCH);
    conv_mma<64,64,1,4,3,false,true,true><<<g1, blk, S13>>>(
        a0h, a0l, p_wf + FOFF1, W[7], W[8], p_occ1, nullptr, p_x1, a1h, a1l, GS, GS, GS, GS);
    conv_mma<64,64,1,4,3,false,false,true><<<g1, blk, S13>>>(
        a1h, a1l, p_wf + FOFF2, W[10], W[11], p_occ1, nullptr, nullptr, a2h, a2l, GS, GS, GS, GS);
    conv_mma<64,64,1,4,3,true,false,true><<<g1, blk, S13>>>(
        a2h, a2l, p_wf + FOFF3, W[13], W[14], p_occ1, p_x1, nullptr, a3h, a3l, GS, GS, GS, GS);

    // L4: 64->128 s2, TM=2, BUFS=2: grid (2, 64, 2)
    dim3 g2(GS2/64, GS2/2, BATCH);
    conv_mma<64,128,2,2,2,false,true,true><<<g2, blk, S4>>>(
        a3h, a3l, p_wf + FOFF4, W[16], W[17], p_occ2, nullptr, p_x2, a4h, a4l, GS, GS, GS2, GS2);
    // L5/6: 128->128 s1, TM=2, BUFS=3 single-sync: grid (2, 64, 2)
    conv_mma<128,128,1,2,3,false,false,true><<<g2, blk, S56>>>(
        a4h, a4l, p_wf + FOFF5, W[19], W[20], p_occ2, nullptr, nullptr, a5h, a5l, GS2, GS2, GS2, GS2);
    conv_mma<128,128,1,2,3,true,true,false><<<g2, blk, S56>>>(
        a5h, a5l, p_wf + FOFF6, W[22], W[23], p_occ2, p_x2, p_xb2, nullptr, nullptr, GS2, GS2, GS2, GS2);

    gather_kernel<<<(NPTS*32 + 255)/256, 256>>>(feat, unq, inv, p_xb2, out);
    (void)n_in; (void)out_size;
}

// round 9
// speedup vs baseline: 5.7500x; 1.8420x over previous
#include <cuda_runtime.h>
#include <cuda_fp16.h>
#include <cstdint>

#define NPTS 200000
#define MPIL 30000
#define BATCH 2
#define GS 256
#define GS2 128
#define C1 64
#define C2 128

// ---------------- scratch ----------------
__device__ __align__(16) __half g_a0[BATCH*GS*GS*C1];
__device__ __align__(16) __half g_a1[BATCH*GS*GS*C1];
__device__ __align__(16) __half g_a2[BATCH*GS*GS*C1];
__device__ __align__(16) __half g_a3[BATCH*GS*GS*C1];
__device__ __align__(16) __half g_a4[BATCH*GS2*GS2*C2];
__device__ __align__(16) __half g_a5[BATCH*GS2*GS2*C2];
__device__ __align__(16) float g_x1 [BATCH*GS*GS*C1];
__device__ __align__(16) float g_x2 [BATCH*GS2*GS2*C2];
__device__ __align__(16) float g_xb2[BATCH*GS2*GS2*C2];
__device__ __align__(16) float g_h0  [NPTS*16];
__device__ __align__(16) float g_hmax[MPIL*16];
__device__ __align__(16) float g_fv  [MPIL*64];
__device__ __align__(16) float g_occ [BATCH*GS*GS];
__device__ __align__(16) float g_occ1[BATCH*GS*GS];
__device__ __align__(16) float g_occ2[BATCH*GS2*GS2];

// B-fragment store: [tap][chunk][ntile] blocks of 32 uint2 (fp16 frags)
#define FOFF1 0
#define FOFF2 (FOFF1 + 9216)
#define FOFF3 (FOFF2 + 9216)
#define FOFF4 (FOFF3 + 9216)
#define FOFF5 (FOFF4 + 18432)
#define FOFF6 (FOFF5 + 36864)
#define FTOT  (FOFF6 + 36864)
__device__ __align__(16) uint2 g_wfrag[FTOT];

// ---------------- helpers ----------------
__device__ __forceinline__ uint32_t smem_u32(const void* p) {
    uint32_t a;
    asm("{ .reg .u64 t; cvta.to.shared.u64 t, %1; cvt.u32.u64 %0, t; }" : "=r"(a) : "l"(p));
    return a;
}
__device__ __forceinline__ uint32_t pack_h2(float f0, float f1) {
    uint32_t r;
    asm("cvt.rn.f16x2.f32 %0, %1, %2;" : "=r"(r) : "f"(f1), "f"(f0));
    return r;
}
__device__ __forceinline__ void mma16816(float* c, const uint32_t* a,
                                         uint32_t b0, uint32_t b1) {
    asm volatile("mma.sync.aligned.m16n8k16.row.col.f32.f16.f16.f32 "
        "{%0,%1,%2,%3}, {%4,%5,%6,%7}, {%8,%9}, {%0,%1,%2,%3};"
        : "+f"(c[0]), "+f"(c[1]), "+f"(c[2]), "+f"(c[3])
        : "r"(a[0]), "r"(a[1]), "r"(a[2]), "r"(a[3]), "r"(b0), "r"(b1));
}
__device__ __forceinline__ void cp16(uint32_t dst, const void* src, bool ok) {
    int sz = ok ? 16 : 0;
    asm volatile("cp.async.cg.shared.global [%0], [%1], 16, %2;"
        :: "r"(dst), "l"(src), "r"(sz) : "memory");
}
__device__ __forceinline__ void cp_commit() {
    asm volatile("cp.async.commit_group;" ::: "memory");
}
template <int N>
__device__ __forceinline__ void cp_wait() {
    asm volatile("cp.async.wait_group %0;" :: "n"(N) : "memory");
}

// ---------------- zero ----------------
__global__ void zero4_kernel(uint4* __restrict__ p, int n4) {
    int i = blockIdx.x * blockDim.x + threadIdx.x;
    if (i < n4) p[i] = make_uint4(0u, 0u, 0u, 0u);
}

// ---------------- weight prep -> fp16 mma B fragments ----------------
template <int CIN, int COUT>
__global__ void wprep_kernel(const float* __restrict__ w, uint2* __restrict__ dst) {
    constexpr int CHUNKS = CIN / 16;
    constexpr int NTTOT = COUT / 8;
    int idx = blockIdx.x * blockDim.x + threadIdx.x;
    if (idx >= 9 * CHUNKS * NTTOT * 32) return;
    int lane = idx & 31;
    int t = idx >> 5;
    int nt = t % NTTOT;
    int t2 = t / NTTOT;
    int ch = t2 % CHUNKS;
    int tap = t2 / CHUNKS;
    int n = nt * 8 + (lane >> 2);
    int k0 = (lane & 3) * 2;
    int cib = ch * 16;
    float w00 = w[((size_t)tap * CIN + cib + k0)     * COUT + n];
    float w01 = w[((size_t)tap * CIN + cib + k0 + 1) * COUT + n];
    float w10 = w[((size_t)tap * CIN + cib + k0 + 8) * COUT + n];
    float w11 = w[((size_t)tap * CIN + cib + k0 + 9) * COUT + n];
    uint2* blk = dst + (size_t)((tap * CHUNKS + ch) * NTTOT + nt) * 32;
    blk[lane] = make_uint2(pack_h2(w00, w01), pack_h2(w10, w11));
}

// ---------------- PFN layer 0 ----------------
__global__ __launch_bounds__(256) void pfn0_kernel(
    const float* __restrict__ feat, const int* __restrict__ inv,
    const float* __restrict__ w0, const float* __restrict__ g0, const float* __restrict__ b0,
    float* __restrict__ h0, float* __restrict__ hmax)
{
    __shared__ float sw[256];
    __shared__ float sg[16], sb[16];
    if (threadIdx.x < 256) sw[threadIdx.x] = w0[threadIdx.x];
    if (threadIdx.x < 16) { sg[threadIdx.x] = g0[threadIdx.x]; sb[threadIdx.x] = b0[threadIdx.x]; }
    __syncthreads();
    int i = blockIdx.x * 256 + threadIdx.x;
    if (i >= NPTS) return;
    float f[16];
    const float4* fp = reinterpret_cast<const float4*>(feat + (size_t)i * 16);
#pragma unroll
    for (int t = 0; t < 4; t++) {
        float4 v = fp[t];
        f[4*t]=v.x; f[4*t+1]=v.y; f[4*t+2]=v.z; f[4*t+3]=v.w;
    }
    float acc[16];
#pragma unroll
    for (int j = 0; j < 16; j++) acc[j] = 0.f;
#pragma unroll
    for (int c = 0; c < 16; c++) {
        float xv = f[c];
#pragma unroll
        for (int j = 0; j < 16; j++) acc[j] += xv * sw[c * 16 + j];
    }
    int seg = inv[i];
    float h[16];
#pragma unroll
    for (int j = 0; j < 16; j++) h[j] = fmaxf(acc[j] * sg[j] + sb[j], 0.f);
    float4* hp = reinterpret_cast<float4*>(h0 + (size_t)i * 16);
#pragma unroll
    for (int t = 0; t < 4; t++) hp[t] = make_float4(h[4*t], h[4*t+1], h[4*t+2], h[4*t+3]);
    int* hm = reinterpret_cast<int*>(hmax + (size_t)seg * 16);
#pragma unroll
    for (int j = 0; j < 16; j++) atomicMax(hm + j, __float_as_int(h[j]));
}

// ---------------- PFN layer 1 ----------------
__global__ __launch_bounds__(128) void pfn1_kernel(
    const int* __restrict__ inv,
    const float* __restrict__ w1, const float* __restrict__ g1, const float* __restrict__ b1,
    const float* __restrict__ h0, const float* __restrict__ hmax, float* __restrict__ fv)
{
    __shared__ float sw[32 * 64];
    __shared__ float sg[64], sb[64];
    for (int t = threadIdx.x; t < 2048; t += blockDim.x) sw[t] = w1[t];
    if (threadIdx.x < 64) { sg[threadIdx.x] = g1[threadIdx.x]; sb[threadIdx.x] = b1[threadIdx.x]; }
    __syncthreads();
    int i = blockIdx.x * blockDim.x + threadIdx.x;
    if (i >= NPTS) return;
    int seg = inv[i];
    float x[32];
    const float4* hp = reinterpret_cast<const float4*>(h0 + (size_t)i * 16);
    const float4* mp = reinterpret_cast<const float4*>(hmax + (size_t)seg * 16);
#pragma unroll
    for (int t = 0; t < 4; t++) {
        float4 v = hp[t];
        x[4*t]=v.x; x[4*t+1]=v.y; x[4*t+2]=v.z; x[4*t+3]=v.w;
        float4 u = mp[t];
        x[16+4*t]=u.x; x[16+4*t+1]=u.y; x[16+4*t+2]=u.z; x[16+4*t+3]=u.w;
    }
    float acc[64];
#pragma unroll
    for (int j = 0; j < 64; j++) acc[j] = 0.f;
#pragma unroll
    for (int c = 0; c < 32; c++) {
        float xv = x[c];
        const float4* wr = reinterpret_cast<const float4*>(&sw[c * 64]);
#pragma unroll
        for (int k = 0; k < 16; k++) {
            float4 w = wr[k];
            acc[4*k] += xv*w.x; acc[4*k+1] += xv*w.y;
            acc[4*k+2] += xv*w.z; acc[4*k+3] += xv*w.w;
        }
    }
    int* fp = reinterpret_cast<int*>(fv + (size_t)seg * 64);
#pragma unroll
    for (int j = 0; j < 64; j++) {
        float v = fmaxf(acc[j] * sg[j] + sb[j], 0.f);
        atomicMax(fp + j, __float_as_int(v));
    }
}

// ---------------- scatter pillars -> fp16 plane + occ ----------------
__global__ void scatter_kernel(const int* __restrict__ unq, const float* __restrict__ fv,
                               __half* __restrict__ ah, float* __restrict__ occ)
{
    int idx = blockIdx.x * blockDim.x + threadIdx.x;
    if (idx >= MPIL * 8) return;
    int m = idx >> 3, k = idx & 7;
    int bb = unq[m*3], yy = unq[m*3+1], xx = unq[m*3+2];
    const float4* fp = reinterpret_cast<const float4*>(fv) + m * 16 + 2 * k;
    float4 a = fp[0], b = fp[1];
    uint4 hw;
    hw.x = pack_h2(a.x, a.y);
    hw.y = pack_h2(a.z, a.w);
    hw.z = pack_h2(b.x, b.y);
    hw.w = pack_h2(b.z, b.w);
    size_t pix = ((size_t)(bb * GS + yy) * GS + xx) * 64;
    reinterpret_cast<uint4*>(ah + pix)[k] = hw;
    if (k == 0) occ[(bb * GS + yy) * GS + xx] = 1.0f;
}

// ---------------- occupancy dilations ----------------
__global__ void occ1_kernel(const float* __restrict__ occ, float* __restrict__ occ1) {
    int idx = blockIdx.x * blockDim.x + threadIdx.x;
    if (idx >= BATCH * GS * GS) return;
    int x = idx % GS, y = (idx / GS) % GS, b = idx / (GS * GS);
    float m = 0.f;
#pragma unroll
    for (int dy = -1; dy <= 1; dy++)
#pragma unroll
        for (int dx = -1; dx <= 1; dx++) {
            int yy = y + dy, xx = x + dx;
            if (yy >= 0 && yy < GS && xx >= 0 && xx < GS)
                m = fmaxf(m, occ[(b * GS + yy) * GS + xx]);
        }
    occ1[idx] = m;
}
__global__ void occ2_kernel(const float* __restrict__ occ1, float* __restrict__ occ2) {
    int idx = blockIdx.x * blockDim.x + threadIdx.x;
    if (idx >= BATCH * GS2 * GS2) return;
    int x = idx % GS2, y = (idx / GS2) % GS2, b = idx / (GS2 * GS2);
    float m = 0.f;
#pragma unroll
    for (int dy = -1; dy <= 1; dy++)
#pragma unroll
        for (int dx = -1; dx <= 1; dx++) {
            int yy = 2 * y + dy, xx = 2 * x + dx;
            if (yy >= 0 && yy < GS && xx >= 0 && xx < GS)
                m = fmaxf(m, occ1[(b * GS + yy) * GS + xx]);
        }
    occ2[idx] = m;
}

// ---------------- HMMA conv3x3 (fp16 single product), cp.async pipelined ----------------
template <int CIN, int COUT, int STRIDE, int TM, int BUFS, bool RESID, bool OUTF32, bool PLANES>
__global__ __launch_bounds__(256) void conv_mma(
    const __half* __restrict__ in,
    const uint2* __restrict__ wfrag,
    const float* __restrict__ gm, const float* __restrict__ bt,
    const float* __restrict__ mask, const float* __restrict__ resid,
    float* __restrict__ outf, __half* __restrict__ outh,
    int IH, int IW, int OH, int OW)
{
    constexpr int CHUNKS = CIN / 16;
    constexpr int NTTOT = COUT / 8;
    constexpr int NT = COUT / 16;
    constexpr int R = (TM - 1) * STRIDE + 3;
    constexpr int PXW = 64 * STRIDE + 2;
    constexpr int NV = R * PXW * 2;

    extern __shared__ __align__(16) char smem_raw[];
    __half* s_in = reinterpret_cast<__half*>(smem_raw);
    auto sidx = [&](int buf, int ry, int px) {
        return ((buf * R + ry) * PXW + px) * 16;
    };

    const int tid = threadIdx.x;
    const int wid = tid >> 5, lane = tid & 31;
    const int mwarp = wid >> 1, nwarp = wid & 1;
    const int g = lane >> 2, q = lane & 3;
    const int y0 = blockIdx.y * TM;
    const int xb = blockIdx.x * 64;
    const int bb = blockIdx.z;

    float acc[TM][NT][4];
#pragma unroll
    for (int r = 0; r < TM; r++)
#pragma unroll
        for (int nt = 0; nt < NT; nt++)
#pragma unroll
            for (int j = 0; j < 4; j++) acc[r][nt][j] = 0.f;

    auto stage = [&](int ch, int buf) {
#pragma unroll 1
        for (int i = tid; i < NV; i += 256) {
            int half = i & 1;
            int r2 = i >> 1;
            int px = r2 % PXW;
            int ry = r2 / PXW;
            int iy = y0 * STRIDE + ry - 1;
            int ix = xb * STRIDE + px - 1;
            bool ok = (iy >= 0) && (iy < IH) && (ix >= 0) && (ix < IW);
            const void* src = ok
                ? (const void*)(in + ((size_t)(bb * IH + iy) * IW + ix) * CIN + ch * 16 + half * 8)
                : (const void*)in;
            cp16(smem_u32(s_in + sidx(buf, ry, px) + half * 8), src, ok);
        }
        cp_commit();
    };

    stage(0, 0);

#pragma unroll 1
    for (int ch = 0; ch < CHUNKS; ch++) {
        const int buf = (BUFS == 3) ? (ch % 3) : (ch & 1);
        if (ch + 1 < CHUNKS) {
            stage(ch + 1, (BUFS == 3) ? ((ch + 1) % 3) : ((ch + 1) & 1));
            cp_wait<1>();
        } else {
            cp_wait<0>();
        }
        __syncthreads();
#pragma unroll
        for (int ky = 0; ky < 3; ky++) {
#pragma unroll
            for (int kx = 0; kx < 3; kx++) {
                const uint2* bbase = wfrag
                    + (size_t)(((ky * 3 + kx) * CHUNKS + ch) * NTTOT + nwarp * NT) * 32;
                uint2 bh[NT];
#pragma unroll
                for (int nt = 0; nt < NT; nt++) bh[nt] = __ldg(bbase + nt * 32 + lane);
                const int pxa = (mwarp * 16 + g) * STRIDE + kx;
                uint32_t A[TM][4];
#pragma unroll
                for (int r = 0; r < TM; r++) {
                    const int row = r * STRIDE + ky;
                    const __half* pA = s_in + sidx(buf, row, pxa) + q * 2;
                    A[r][0] = *reinterpret_cast<const uint32_t*>(pA);
                    A[r][2] = *reinterpret_cast<const uint32_t*>(pA + 8);
                    A[r][1] = *reinterpret_cast<const uint32_t*>(pA + 8 * STRIDE * 16);
                    A[r][3] = *reinterpret_cast<const uint32_t*>(pA + 8 * STRIDE * 16 + 8);
                }
#pragma unroll
                for (int r = 0; r < TM; r++)
#pragma unroll
                    for (int nt = 0; nt < NT; nt++)
                        mma16816(acc[r][nt], A[r], bh[nt].x, bh[nt].y);
            }
        }
        if (BUFS == 2) __syncthreads();
    }

    // epilogue
    const int xa = xb + mwarp * 16 + g;
#pragma unroll
    for (int r = 0; r < TM; r++) {
        const int y = y0 + r;
        const size_t pa = (size_t)(bb * OH + y) * OW + xa;
        const size_t pb = pa + 8;
        const float mva = mask[pa];
        const float mvb = mask[pb];
#pragma unroll
        for (int nt = 0; nt < NT; nt++) {
            const int co = nwarp * (COUT / 2) + nt * 8 + 2 * q;
            const float g0 = __ldg(gm + co), g1 = __ldg(gm + co + 1);
            const float b0 = __ldg(bt + co), b1 = __ldg(bt + co + 1);
            float v0 = acc[r][nt][0] * g0 + b0;
            float v1 = acc[r][nt][1] * g1 + b1;
            float v2 = acc[r][nt][2] * g0 + b0;
            float v3 = acc[r][nt][3] * g1 + b1;
            if (RESID) {
                float2 ra = *reinterpret_cast<const float2*>(resid + pa * COUT + co);
                float2 rb = *reinterpret_cast<const float2*>(resid + pb * COUT + co);
                v0 = fmaxf(ra.x + v0 * mva, 0.f);
                v1 = fmaxf(ra.y + v1 * mva, 0.f);
                v2 = fmaxf(rb.x + v2 * mvb, 0.f);
                v3 = fmaxf(rb.y + v3 * mvb, 0.f);
            } else {
                v0 = fmaxf(v0, 0.f) * mva;
                v1 = fmaxf(v1, 0.f) * mva;
                v2 = fmaxf(v2, 0.f) * mvb;
                v3 = fmaxf(v3, 0.f) * mvb;
            }
            if (OUTF32) {
                *reinterpret_cast<float2*>(outf + pa * COUT + co) = make_float2(v0, v1);
                *reinterpret_cast<float2*>(outf + pb * COUT + co) = make_float2(v2, v3);
            }
            if (PLANES) {
                *reinterpret_cast<uint32_t*>(outh + pa * COUT + co) = pack_h2(v0, v1);
                *reinterpret_cast<uint32_t*>(outh + pb * COUT + co) = pack_h2(v2, v3);
            }
        }
    }
}

// ---------------- bilinear gather ----------------
__global__ __launch_bounds__(256) void gather_kernel(
    const float* __restrict__ feat, const int* __restrict__ unq, const int* __restrict__ inv,
    const float* __restrict__ xb2, float* __restrict__ out)
{
    int gwarp = (blockIdx.x * blockDim.x + threadIdx.x) >> 5;
    int lane = threadIdx.x & 31;
    if (gwarp >= NPTS) return;
    int i = gwarp;
    float f0 = __ldg(feat + (size_t)i * 16);
    float f1 = __ldg(feat + (size_t)i * 16 + 1);
    float px = ((f0 + 51.2f) / 0.4f) * 0.5f;
    float py = ((f1 + 51.2f) / 0.4f) * 0.5f;
    int seg = __ldg(inv + i);
    int bb = __ldg(unq + seg * 3);
    int fx = (int)floorf(px), fy = (int)floorf(py);
    int x0 = min(max(fx, 0), GS2 - 1), x1 = min(max(fx + 1, 0), GS2 - 1);
    int y0 = min(max(fy, 0), GS2 - 1), y1 = min(max(fy + 1, 0), GS2 - 1);
    float x0f = (float)x0, x1f = (float)x1, y0f = (float)y0, y1f = (float)y1;
    float wa = (x1f - px) * (y1f - py);
    float wb = (x1f - px) * (py - y0f);
    float wc = (px - x0f) * (y1f - py);
    float wd = (px - x0f) * (py - y0f);
    const float4* A  = reinterpret_cast<const float4*>(xb2 + ((size_t)(bb*GS2+y0)*GS2+x0)*C2) + lane;
    const float4* Bp = reinterpret_cast<const float4*>(xb2 + ((size_t)(bb*GS2+y1)*GS2+x0)*C2) + lane;
    const float4* Cp = reinterpret_cast<const float4*>(xb2 + ((size_t)(bb*GS2+y0)*GS2+x1)*C2) + lane;
    const float4* D  = reinterpret_cast<const float4*>(xb2 + ((size_t)(bb*GS2+y1)*GS2+x1)*C2) + lane;
    float4 a = __ldg(A), b = __ldg(Bp), c = __ldg(Cp), d = __ldg(D);
    float4 r;
    r.x = a.x*wa + b.x*wb + c.x*wc + d.x*wd;
    r.y = a.y*wa + b.y*wb + c.y*wc + d.y*wd;
    r.z = a.z*wa + b.z*wb + c.z*wc + d.z*wd;
    r.w = a.w*wa + b.w*wb + c.w*wc + d.w*wd;
    reinterpret_cast<float4*>(out + (size_t)i * C2)[lane] = r;
}

// ---------------- launch ----------------
extern "C" void kernel_launch(void* const* d_in, const int* in_sizes, int n_in,
                              void* d_out, int out_size)
{
    const float* feat = (const float*)d_in[0];
    const int* unq = (const int*)d_in[1];
    const int* inv = (const int*)d_in[2];
    int wb = (in_sizes[3] == 1) ? 4 : 3;
    const float* W[24];
    for (int i = 0; i < 24; i++) W[i] = (const float*)d_in[wb + i];
    float* out = (float*)d_out;

    float *p_h0, *p_hmax, *p_fv, *p_x1, *p_x2, *p_xb2, *p_occ, *p_occ1, *p_occ2;
    __half *a0, *a1, *a2, *a3, *a4, *a5;
    uint2* p_wf;
    cudaGetSymbolAddress((void**)&p_h0, g_h0);
    cudaGetSymbolAddress((void**)&p_hmax, g_hmax);
    cudaGetSymbolAddress((void**)&p_fv, g_fv);
    cudaGetSymbolAddress((void**)&p_x1, g_x1);
    cudaGetSymbolAddress((void**)&p_x2, g_x2);
    cudaGetSymbolAddress((void**)&p_xb2, g_xb2);
    cudaGetSymbolAddress((void**)&p_occ, g_occ);
    cudaGetSymbolAddress((void**)&p_occ1, g_occ1);
    cudaGetSymbolAddress((void**)&p_occ2, g_occ2);
    cudaGetSymbolAddress((void**)&a0, g_a0);
    cudaGetSymbolAddress((void**)&a1, g_a1);
    cudaGetSymbolAddress((void**)&a2, g_a2);
    cudaGetSymbolAddress((void**)&a3, g_a3);
    cudaGetSymbolAddress((void**)&a4, g_a4);
    cudaGetSymbolAddress((void**)&a5, g_a5);
    cudaGetSymbolAddress((void**)&p_wf, g_wfrag);

    zero4_kernel<<<(BATCH*GS*GS*C1*2/16 + 255)/256, 256>>>((uint4*)a0, BATCH*GS*GS*C1*2/16);
    zero4_kernel<<<(MPIL*16*4/16 + 255)/256, 256>>>((uint4*)p_hmax, MPIL*16*4/16);
    zero4_kernel<<<(MPIL*64*4/16 + 255)/256, 256>>>((uint4*)p_fv, MPIL*64*4/16);
    zero4_kernel<<<(BATCH*GS*GS*4/16 + 255)/256, 256>>>((uint4*)p_occ, BATCH*GS*GS*4/16);

    wprep_kernel<64,64><<<(9*4*8*32 + 255)/256, 256>>>(W[6],  p_wf + FOFF1);
    wprep_kernel<64,64><<<(9*4*8*32 + 255)/256, 256>>>(W[9],  p_wf + FOFF2);
    wprep_kernel<64,64><<<(9*4*8*32 + 255)/256, 256>>>(W[12], p_wf + FOFF3);
    wprep_kernel<64,128><<<(9*4*16*32 + 255)/256, 256>>>(W[15], p_wf + FOFF4);
    wprep_kernel<128,128><<<(9*8*16*32 + 255)/256, 256>>>(W[18], p_wf + FOFF5);
    wprep_kernel<128,128><<<(9*8*16*32 + 255)/256, 256>>>(W[21], p_wf + FOFF6);

    pfn0_kernel<<<(NPTS + 255)/256, 256>>>(feat, inv, W[0], W[1], W[2], p_h0, p_hmax);
    pfn1_kernel<<<(NPTS + 127)/128, 128>>>(inv, W[3], W[4], W[5], p_h0, p_hmax, p_fv);
    scatter_kernel<<<(MPIL*8 + 255)/256, 256>>>(unq, p_fv, a0, p_occ);
    occ1_kernel<<<(BATCH*GS*GS + 255)/256, 256>>>(p_occ, p_occ1);
    occ2_kernel<<<(BATCH*GS2*GS2 + 255)/256, 256>>>(p_occ1, p_occ2);

    // dynamic smem: BUFS * R * PXW * 16 halves * 2B
    const int S13 = 3 * 6 * 66 * 16 * 2;   // 38016 (TM=4, s1, BUFS=3)
    const int S4  = 2 * 5 * 130 * 16 * 2;  // 41600 (TM=2, s2, BUFS=2)
    const int S56 = 3 * 4 * 66 * 16 * 2;   // 25344 (TM=2, s1, BUFS=3)
    cudaFuncSetAttribute(conv_mma<64,64,1,4,3,false,true,true>,   cudaFuncAttributeMaxDynamicSharedMemorySize, S13);
    cudaFuncSetAttribute(conv_mma<64,64,1,4,3,false,false,true>,  cudaFuncAttributeMaxDynamicSharedMemorySize, S13);
    cudaFuncSetAttribute(conv_mma<64,64,1,4,3,true,false,true>,   cudaFuncAttributeMaxDynamicSharedMemorySize, S13);
    cudaFuncSetAttribute(conv_mma<64,128,2,2,2,false,true,true>,  cudaFuncAttributeMaxDynamicSharedMemorySize, S4);
    cudaFuncSetAttribute(conv_mma<128,128,1,2,3,false,false,true>,cudaFuncAttributeMaxDynamicSharedMemorySize, S56);
    cudaFuncSetAttribute(conv_mma<128,128,1,2,3,true,true,false>, cudaFuncAttributeMaxDynamicSharedMemorySize, S56);

    dim3 blk(256);
    // L1-3: 64->64 s1, TM=4, BUFS=3: grid (4, 64, 2)
    dim3 g1(GS/64, GS/4, BATCH);
    conv_mma<64,64,1,4,3,false,true,true><<<g1, blk, S13>>>(
        a0, p_wf + FOFF1, W[7], W[8], p_occ1, nullptr, p_x1, a1, GS, GS, GS, GS);
    conv_mma<64,64,1,4,3,false,false,true><<<g1, blk, S13>>>(
        a1, p_wf + FOFF2, W[10], W[11], p_occ1, nullptr, nullptr, a2, GS, GS, GS, GS);
    conv_mma<64,64,1,4,3,true,false,true><<<g1, blk, S13>>>(
        a2, p_wf + FOFF3, W[13], W[14], p_occ1, p_x1, nullptr, a3, GS, GS, GS, GS);

    // L4: 64->128 s2, TM=2, BUFS=2: grid (2, 64, 2)
    dim3 g2(GS2/64, GS2/2, BATCH);
    conv_mma<64,128,2,2,2,false,true,true><<<g2, blk, S4>>>(
        a3, p_wf + FOFF4, W[16], W[17], p_occ2, nullptr, p_x2, a4, GS, GS, GS2, GS2);
    // L5/6: 128->128 s1, TM=2, BUFS=3: grid (2, 64, 2)
    conv_mma<128,128,1,2,3,false,false,true><<<g2, blk, S56>>>(
        a4, p_wf + FOFF5, W[19], W[20], p_occ2, nullptr, nullptr, a5, GS2, GS2, GS2, GS2);
    conv_mma<128,128,1,2,3,true,true,false><<<g2, blk, S56>>>(
        a5, p_wf + FOFF6, W[22], W[23], p_occ2, p_x2, p_xb2, nullptr, GS2, GS2, GS2, GS2);

    gather_kernel<<<(NPTS*32 + 255)/256, 256>>>(feat, unq, inv, p_xb2, out);
    (void)n_in; (void)out_size;
}

// round 10
// speedup vs baseline: 5.7882x; 1.0066x over previous
#include <cuda_runtime.h>
#include <cuda_fp16.h>
#include <cstdint>

#define NPTS 200000
#define MPIL 30000
#define BATCH 2
#define GS 256
#define GS2 128
#define C1 64
#define C2 128

// ---------------- scratch ----------------
__device__ __align__(16) __half g_a0[BATCH*GS*GS*C1];
__device__ __align__(16) __half g_a1[BATCH*GS*GS*C1];
__device__ __align__(16) __half g_a2[BATCH*GS*GS*C1];
__device__ __align__(16) __half g_a3[BATCH*GS*GS*C1];
__device__ __align__(16) __half g_a4[BATCH*GS2*GS2*C2];
__device__ __align__(16) __half g_a5[BATCH*GS2*GS2*C2];
__device__ __align__(16) float g_x1 [BATCH*GS*GS*C1];
__device__ __align__(16) float g_x2 [BATCH*GS2*GS2*C2];
__device__ __align__(16) float g_xb2[BATCH*GS2*GS2*C2];
__device__ __align__(16) float g_h0  [NPTS*16];
__device__ __align__(16) float g_hmax[MPIL*16];
__device__ __align__(16) float g_fv  [MPIL*64];
__device__ __align__(16) float g_occ [BATCH*GS*GS];
__device__ __align__(16) float g_occ1[BATCH*GS*GS];
__device__ __align__(16) float g_occ2[BATCH*GS2*GS2];

// B-fragment store: [tap][chunk][ntile] blocks of 32 uint2 (fp16 frags)
#define FOFF1 0
#define FOFF2 (FOFF1 + 9216)
#define FOFF3 (FOFF2 + 9216)
#define FOFF4 (FOFF3 + 9216)
#define FOFF5 (FOFF4 + 18432)
#define FOFF6 (FOFF5 + 36864)
#define FTOT  (FOFF6 + 36864)
__device__ __align__(16) uint2 g_wfrag[FTOT];

// ---------------- helpers ----------------
__device__ __forceinline__ uint32_t smem_u32(const void* p) {
    uint32_t a;
    asm("{ .reg .u64 t; cvta.to.shared.u64 t, %1; cvt.u32.u64 %0, t; }" : "=r"(a) : "l"(p));
    return a;
}
__device__ __forceinline__ uint32_t pack_h2(float f0, float f1) {
    uint32_t r;
    asm("cvt.rn.f16x2.f32 %0, %1, %2;" : "=r"(r) : "f"(f1), "f"(f0));
    return r;
}
__device__ __forceinline__ void mma16816(float* c, const uint32_t* a,
                                         uint32_t b0, uint32_t b1) {
    asm volatile("mma.sync.aligned.m16n8k16.row.col.f32.f16.f16.f32 "
        "{%0,%1,%2,%3}, {%4,%5,%6,%7}, {%8,%9}, {%0,%1,%2,%3};"
        : "+f"(c[0]), "+f"(c[1]), "+f"(c[2]), "+f"(c[3])
        : "r"(a[0]), "r"(a[1]), "r"(a[2]), "r"(a[3]), "r"(b0), "r"(b1));
}
__device__ __forceinline__ void ldsm_x4(uint32_t& r0, uint32_t& r1, uint32_t& r2, uint32_t& r3,
                                        uint32_t saddr) {
    asm volatile("ldmatrix.sync.aligned.m8n8.x4.shared.b16 {%0,%1,%2,%3}, [%4];"
        : "=r"(r0), "=r"(r1), "=r"(r2), "=r"(r3) : "r"(saddr));
}
__device__ __forceinline__ void cp16(uint32_t dst, const void* src, bool ok) {
    int sz = ok ? 16 : 0;
    asm volatile("cp.async.cg.shared.global [%0], [%1], 16, %2;"
        :: "r"(dst), "l"(src), "r"(sz) : "memory");
}
__device__ __forceinline__ void cp_commit() {
    asm volatile("cp.async.commit_group;" ::: "memory");
}
template <int N>
__device__ __forceinline__ void cp_wait() {
    asm volatile("cp.async.wait_group %0;" :: "n"(N) : "memory");
}

// ---------------- merged zero ----------------
__global__ void zero_all_kernel(uint4* p0, int n0, uint4* p1, int n1,
                                uint4* p2, int n2, uint4* p3, int n3) {
    int i = blockIdx.x * blockDim.x + threadIdx.x;
    uint4 z = make_uint4(0u, 0u, 0u, 0u);
    if (i < n0) p0[i] = z;
    i -= n0;
    if (i >= 0 && i < n1) p1[i] = z;
    i -= n1;
    if (i >= 0 && i < n2) p2[i] = z;
    i -= n2;
    if (i >= 0 && i < n3) p3[i] = z;
}

// ---------------- weight prep -> fp16 mma B fragments ----------------
template <int CIN, int COUT>
__global__ void wprep_kernel(const float* __restrict__ w, uint2* __restrict__ dst) {
    constexpr int CHUNKS = CIN / 16;
    constexpr int NTTOT = COUT / 8;
    int idx = blockIdx.x * blockDim.x + threadIdx.x;
    if (idx >= 9 * CHUNKS * NTTOT * 32) return;
    int lane = idx & 31;
    int t = idx >> 5;
    int nt = t % NTTOT;
    int t2 = t / NTTOT;
    int ch = t2 % CHUNKS;
    int tap = t2 / CHUNKS;
    int n = nt * 8 + (lane >> 2);
    int k0 = (lane & 3) * 2;
    int cib = ch * 16;
    float w00 = w[((size_t)tap * CIN + cib + k0)     * COUT + n];
    float w01 = w[((size_t)tap * CIN + cib + k0 + 1) * COUT + n];
    float w10 = w[((size_t)tap * CIN + cib + k0 + 8) * COUT + n];
    float w11 = w[((size_t)tap * CIN + cib + k0 + 9) * COUT + n];
    uint2* blk = dst + (size_t)((tap * CHUNKS + ch) * NTTOT + nt) * 32;
    blk[lane] = make_uint2(pack_h2(w00, w01), pack_h2(w10, w11));
}

// ---------------- PFN layer 0 ----------------
__global__ __launch_bounds__(256) void pfn0_kernel(
    const float* __restrict__ feat, const int* __restrict__ inv,
    const float* __restrict__ w0, const float* __restrict__ g0, const float* __restrict__ b0,
    float* __restrict__ h0, float* __restrict__ hmax)
{
    __shared__ float sw[256];
    __shared__ float sg[16], sb[16];
    if (threadIdx.x < 256) sw[threadIdx.x] = w0[threadIdx.x];
    if (threadIdx.x < 16) { sg[threadIdx.x] = g0[threadIdx.x]; sb[threadIdx.x] = b0[threadIdx.x]; }
    __syncthreads();
    int i = blockIdx.x * 256 + threadIdx.x;
    if (i >= NPTS) return;
    float f[16];
    const float4* fp = reinterpret_cast<const float4*>(feat + (size_t)i * 16);
#pragma unroll
    for (int t = 0; t < 4; t++) {
        float4 v = fp[t];
        f[4*t]=v.x; f[4*t+1]=v.y; f[4*t+2]=v.z; f[4*t+3]=v.w;
    }
    float acc[16];
#pragma unroll
    for (int j = 0; j < 16; j++) acc[j] = 0.f;
#pragma unroll
    for (int c = 0; c < 16; c++) {
        float xv = f[c];
#pragma unroll
        for (int j = 0; j < 16; j++) acc[j] += xv * sw[c * 16 + j];
    }
    int seg = inv[i];
    float h[16];
#pragma unroll
    for (int j = 0; j < 16; j++) h[j] = fmaxf(acc[j] * sg[j] + sb[j], 0.f);
    float4* hp = reinterpret_cast<float4*>(h0 + (size_t)i * 16);
#pragma unroll
    for (int t = 0; t < 4; t++) hp[t] = make_float4(h[4*t], h[4*t+1], h[4*t+2], h[4*t+3]);
    int* hm = reinterpret_cast<int*>(hmax + (size_t)seg * 16);
#pragma unroll
    for (int j = 0; j < 16; j++) atomicMax(hm + j, __float_as_int(h[j]));
}

// ---------------- PFN layer 1 ----------------
__global__ __launch_bounds__(128) void pfn1_kernel(
    const int* __restrict__ inv,
    const float* __restrict__ w1, const float* __restrict__ g1, const float* __restrict__ b1,
    const float* __restrict__ h0, const float* __restrict__ hmax, float* __restrict__ fv)
{
    __shared__ float sw[32 * 64];
    __shared__ float sg[64], sb[64];
    for (int t = threadIdx.x; t < 2048; t += blockDim.x) sw[t] = w1[t];
    if (threadIdx.x < 64) { sg[threadIdx.x] = g1[threadIdx.x]; sb[threadIdx.x] = b1[threadIdx.x]; }
    __syncthreads();
    int i = blockIdx.x * blockDim.x + threadIdx.x;
    if (i >= NPTS) return;
    int seg = inv[i];
    float x[32];
    const float4* hp = reinterpret_cast<const float4*>(h0 + (size_t)i * 16);
    const float4* mp = reinterpret_cast<const float4*>(hmax + (size_t)seg * 16);
#pragma unroll
    for (int t = 0; t < 4; t++) {
        float4 v = hp[t];
        x[4*t]=v.x; x[4*t+1]=v.y; x[4*t+2]=v.z; x[4*t+3]=v.w;
        float4 u = mp[t];
        x[16+4*t]=u.x; x[16+4*t+1]=u.y; x[16+4*t+2]=u.z; x[16+4*t+3]=u.w;
    }
    float acc[64];
#pragma unroll
    for (int j = 0; j < 64; j++) acc[j] = 0.f;
#pragma unroll
    for (int c = 0; c < 32; c++) {
        float xv = x[c];
        const float4* wr = reinterpret_cast<const float4*>(&sw[c * 64]);
#pragma unroll
        for (int k = 0; k < 16; k++) {
            float4 w = wr[k];
            acc[4*k] += xv*w.x; acc[4*k+1] += xv*w.y;
            acc[4*k+2] += xv*w.z; acc[4*k+3] += xv*w.w;
        }
    }
    int* fp = reinterpret_cast<int*>(fv + (size_t)seg * 64);
#pragma unroll
    for (int j = 0; j < 64; j++) {
        float v = fmaxf(acc[j] * sg[j] + sb[j], 0.f);
        atomicMax(fp + j, __float_as_int(v));
    }
}

// ---------------- scatter pillars -> fp16 plane + occ ----------------
__global__ void scatter_kernel(const int* __restrict__ unq, const float* __restrict__ fv,
                               __half* __restrict__ ah, float* __restrict__ occ)
{
    int idx = blockIdx.x * blockDim.x + threadIdx.x;
    if (idx >= MPIL * 8) return;
    int m = idx >> 3, k = idx & 7;
    int bb = unq[m*3], yy = unq[m*3+1], xx = unq[m*3+2];
    const float4* fp = reinterpret_cast<const float4*>(fv) + m * 16 + 2 * k;
    float4 a = fp[0], b = fp[1];
    uint4 hw;
    hw.x = pack_h2(a.x, a.y);
    hw.y = pack_h2(a.z, a.w);
    hw.z = pack_h2(b.x, b.y);
    hw.w = pack_h2(b.z, b.w);
    size_t pix = ((size_t)(bb * GS + yy) * GS + xx) * 64;
    reinterpret_cast<uint4*>(ah + pix)[k] = hw;
    if (k == 0) occ[(bb * GS + yy) * GS + xx] = 1.0f;
}

// ---------------- occupancy dilations ----------------
__global__ void occ1_kernel(const float* __restrict__ occ, float* __restrict__ occ1) {
    int idx = blockIdx.x * blockDim.x + threadIdx.x;
    if (idx >= BATCH * GS * GS) return;
    int x = idx % GS, y = (idx / GS) % GS, b = idx / (GS * GS);
    float m = 0.f;
#pragma unroll
    for (int dy = -1; dy <= 1; dy++)
#pragma unroll
        for (int dx = -1; dx <= 1; dx++) {
            int yy = y + dy, xx = x + dx;
            if (yy >= 0 && yy < GS && xx >= 0 && xx < GS)
                m = fmaxf(m, occ[(b * GS + yy) * GS + xx]);
        }
    occ1[idx] = m;
}
__global__ void occ2_kernel(const float* __restrict__ occ1, float* __restrict__ occ2) {
    int idx = blockIdx.x * blockDim.x + threadIdx.x;
    if (idx >= BATCH * GS2 * GS2) return;
    int x = idx % GS2, y = (idx / GS2) % GS2, b = idx / (GS2 * GS2);
    float m = 0.f;
#pragma unroll
    for (int dy = -1; dy <= 1; dy++)
#pragma unroll
        for (int dx = -1; dx <= 1; dx++) {
            int yy = 2 * y + dy, xx = 2 * x + dx;
            if (yy >= 0 && yy < GS && xx >= 0 && xx < GS)
                m = fmaxf(m, occ1[(b * GS + yy) * GS + xx]);
        }
    occ2[idx] = m;
}

// ---------------- HMMA conv3x3 (fp16), cp.async pipelined, ldmatrix A ----------------
template <int CIN, int COUT, int STRIDE, int TM, int BUFS, bool RESID, bool OUTF32, bool PLANES>
__global__ __launch_bounds__(256) void conv_mma(
    const __half* __restrict__ in,
    const uint2* __restrict__ wfrag,
    const float* __restrict__ gm, const float* __restrict__ bt,
    const float* __restrict__ mask, const float* __restrict__ resid,
    float* __restrict__ outf, __half* __restrict__ outh,
    int IH, int IW, int OH, int OW)
{
    constexpr int CHUNKS = CIN / 16;
    constexpr int NTTOT = COUT / 8;
    constexpr int NT = COUT / 16;
    constexpr int R = (TM - 1) * STRIDE + 3;
    constexpr int PXW = 64 * STRIDE + 2;
    constexpr int NV = R * PXW * 2;

    extern __shared__ __align__(16) char smem_raw[];
    __half* s_in = reinterpret_cast<__half*>(smem_raw);
    auto sidx = [&](int buf, int ry, int px) {
        return ((buf * R + ry) * PXW + px) * 16;
    };

    const int tid = threadIdx.x;
    const int wid = tid >> 5, lane = tid & 31;
    const int mwarp = wid >> 1, nwarp = wid & 1;
    const int g = lane >> 2, q = lane & 3;
    const int y0 = blockIdx.y * TM;
    const int xb = blockIdx.x * 64;
    const int bb = blockIdx.z;

    // ldmatrix lane constants: matrix = lane>>3; rows 0-7/8-15, k-half 0/1
    const int mat = lane >> 3;
    const int mrow = (mat & 1) * 8 + (lane & 7);
    const int koff = (mat >> 1) * 8;
    const int pxbase = (mwarp * 16 + mrow) * STRIDE;
    const uint32_t sb32 = smem_u32(s_in);

    float acc[TM][NT][4];
#pragma unroll
    for (int r = 0; r < TM; r++)
#pragma unroll
        for (int nt = 0; nt < NT; nt++)
#pragma unroll
            for (int j = 0; j < 4; j++) acc[r][nt][j] = 0.f;

    auto stage = [&](int ch, int buf) {
#pragma unroll 1
        for (int i = tid; i < NV; i += 256) {
            int half = i & 1;
            int r2 = i >> 1;
            int px = r2 % PXW;
            int ry = r2 / PXW;
            int iy = y0 * STRIDE + ry - 1;
            int ix = xb * STRIDE + px - 1;
            bool ok = (iy >= 0) && (iy < IH) && (ix >= 0) && (ix < IW);
            const void* src = ok
                ? (const void*)(in + ((size_t)(bb * IH + iy) * IW + ix) * CIN + ch * 16 + half * 8)
                : (const void*)in;
            cp16(smem_u32(s_in + sidx(buf, ry, px) + half * 8), src, ok);
        }
        cp_commit();
    };

    stage(0, 0);

#pragma unroll 1
    for (int ch = 0; ch < CHUNKS; ch++) {
        const int buf = (BUFS == 3) ? (ch % 3) : (ch & 1);
        if (ch + 1 < CHUNKS) {
            stage(ch + 1, (BUFS == 3) ? ((ch + 1) % 3) : ((ch + 1) & 1));
            cp_wait<1>();
        } else {
            cp_wait<0>();
        }
        __syncthreads();
#pragma unroll
        for (int ky = 0; ky < 3; ky++) {
#pragma unroll
            for (int kx = 0; kx < 3; kx++) {
                const uint2* bbase = wfrag
                    + (size_t)(((ky * 3 + kx) * CHUNKS + ch) * NTTOT + nwarp * NT) * 32;
                uint2 bh[NT];
#pragma unroll
                for (int nt = 0; nt < NT; nt++) bh[nt] = __ldg(bbase + nt * 32 + lane);
                uint32_t A[TM][4];
#pragma unroll
                for (int r = 0; r < TM; r++) {
                    const int row = r * STRIDE + ky;
                    uint32_t ad = sb32 + (uint32_t)((((buf * R + row) * PXW) + pxbase + kx) * 16 + koff) * 2;
                    ldsm_x4(A[r][0], A[r][1], A[r][2], A[r][3], ad);
                }
#pragma unroll
                for (int r = 0; r < TM; r++)
#pragma unroll
                    for (int nt = 0; nt < NT; nt++)
                        mma16816(acc[r][nt], A[r], bh[nt].x, bh[nt].y);
            }
        }
        if (BUFS == 2) __syncthreads();
    }

    // epilogue
    const int xa = xb + mwarp * 16 + g;
#pragma unroll
    for (int r = 0; r < TM; r++) {
        const int y = y0 + r;
        const size_t pa = (size_t)(bb * OH + y) * OW + xa;
        const size_t pb = pa + 8;
        const float mva = mask[pa];
        const float mvb = mask[pb];
#pragma unroll
        for (int nt = 0; nt < NT; nt++) {
            const int co = nwarp * (COUT / 2) + nt * 8 + 2 * q;
            const float g0 = __ldg(gm + co), g1 = __ldg(gm + co + 1);
            const float b0 = __ldg(bt + co), b1 = __ldg(bt + co + 1);
            float v0 = acc[r][nt][0] * g0 + b0;
            float v1 = acc[r][nt][1] * g1 + b1;
            float v2 = acc[r][nt][2] * g0 + b0;
            float v3 = acc[r][nt][3] * g1 + b1;
            if (RESID) {
                float2 ra = *reinterpret_cast<const float2*>(resid + pa * COUT + co);
                float2 rb = *reinterpret_cast<const float2*>(resid + pb * COUT + co);
                v0 = fmaxf(ra.x + v0 * mva, 0.f);
                v1 = fmaxf(ra.y + v1 * mva, 0.f);
                v2 = fmaxf(rb.x + v2 * mvb, 0.f);
                v3 = fmaxf(rb.y + v3 * mvb, 0.f);
            } else {
                v0 = fmaxf(v0, 0.f) * mva;
                v1 = fmaxf(v1, 0.f) * mva;
                v2 = fmaxf(v2, 0.f) * mvb;
                v3 = fmaxf(v3, 0.f) * mvb;
            }
            if (OUTF32) {
                *reinterpret_cast<float2*>(outf + pa * COUT + co) = make_float2(v0, v1);
                *reinterpret_cast<float2*>(outf + pb * COUT + co) = make_float2(v2, v3);
            }
            if (PLANES) {
                *reinterpret_cast<uint32_t*>(outh + pa * COUT + co) = pack_h2(v0, v1);
                *reinterpret_cast<uint32_t*>(outh + pb * COUT + co) = pack_h2(v2, v3);
            }
        }
    }
}

// ---------------- bilinear gather ----------------
__global__ __launch_bounds__(256) void gather_kernel(
    const float* __restrict__ feat, const int* __restrict__ unq, const int* __restrict__ inv,
    const float* __restrict__ xb2, float* __restrict__ out)
{
    int gwarp = (blockIdx.x * blockDim.x + threadIdx.x) >> 5;
    int lane = threadIdx.x & 31;
    if (gwarp >= NPTS) return;
    int i = gwarp;
    float f0 = __ldg(feat + (size_t)i * 16);
    float f1 = __ldg(feat + (size_t)i * 16 + 1);
    float px = ((f0 + 51.2f) / 0.4f) * 0.5f;
    float py = ((f1 + 51.2f) / 0.4f) * 0.5f;
    int seg = __ldg(inv + i);
    int bb = __ldg(unq + seg * 3);
    int fx = (int)floorf(px), fy = (int)floorf(py);
    int x0 = min(max(fx, 0), GS2 - 1), x1 = min(max(fx + 1, 0), GS2 - 1);
    int y0 = min(max(fy, 0), GS2 - 1), y1 = min(max(fy + 1, 0), GS2 - 1);
    float x0f = (float)x0, x1f = (float)x1, y0f = (float)y0, y1f = (float)y1;
    float wa = (x1f - px) * (y1f - py);
    float wb = (x1f - px) * (py - y0f);
    float wc = (px - x0f) * (y1f - py);
    float wd = (px - x0f) * (py - y0f);
    const float4* A  = reinterpret_cast<const float4*>(xb2 + ((size_t)(bb*GS2+y0)*GS2+x0)*C2) + lane;
    const float4* Bp = reinterpret_cast<const float4*>(xb2 + ((size_t)(bb*GS2+y1)*GS2+x0)*C2) + lane;
    const float4* Cp = reinterpret_cast<const float4*>(xb2 + ((size_t)(bb*GS2+y0)*GS2+x1)*C2) + lane;
    const float4* D  = reinterpret_cast<const float4*>(xb2 + ((size_t)(bb*GS2+y1)*GS2+x1)*C2) + lane;
    float4 a = __ldg(A), b = __ldg(Bp), c = __ldg(Cp), d = __ldg(D);
    float4 r;
    r.x = a.x*wa + b.x*wb + c.x*wc + d.x*wd;
    r.y = a.y*wa + b.y*wb + c.y*wc + d.y*wd;
    r.z = a.z*wa + b.z*wb + c.z*wc + d.z*wd;
    r.w = a.w*wa + b.w*wb + c.w*wc + d.w*wd;
    reinterpret_cast<float4*>(out + (size_t)i * C2)[lane] = r;
}

// ---------------- launch ----------------
extern "C" void kernel_launch(void* const* d_in, const int* in_sizes, int n_in,
                              void* d_out, int out_size)
{
    const float* feat = (const float*)d_in[0];
    const int* unq = (const int*)d_in[1];
    const int* inv = (const int*)d_in[2];
    int wb = (in_sizes[3] == 1) ? 4 : 3;
    const float* W[24];
    for (int i = 0; i < 24; i++) W[i] = (const float*)d_in[wb + i];
    float* out = (float*)d_out;

    float *p_h0, *p_hmax, *p_fv, *p_x1, *p_x2, *p_xb2, *p_occ, *p_occ1, *p_occ2;
    __half *a0, *a1, *a2, *a3, *a4, *a5;
    uint2* p_wf;
    cudaGetSymbolAddress((void**)&p_h0, g_h0);
    cudaGetSymbolAddress((void**)&p_hmax, g_hmax);
    cudaGetSymbolAddress((void**)&p_fv, g_fv);
    cudaGetSymbolAddress((void**)&p_x1, g_x1);
    cudaGetSymbolAddress((void**)&p_x2, g_x2);
    cudaGetSymbolAddress((void**)&p_xb2, g_xb2);
    cudaGetSymbolAddress((void**)&p_occ, g_occ);
    cudaGetSymbolAddress((void**)&p_occ1, g_occ1);
    cudaGetSymbolAddress((void**)&p_occ2, g_occ2);
    cudaGetSymbolAddress((void**)&a0, g_a0);
    cudaGetSymbolAddress((void**)&a1, g_a1);
    cudaGetSymbolAddress((void**)&a2, g_a2);
    cudaGetSymbolAddress((void**)&a3, g_a3);
    cudaGetSymbolAddress((void**)&a4, g_a4);
    cudaGetSymbolAddress((void**)&a5, g_a5);
    cudaGetSymbolAddress((void**)&p_wf, g_wfrag);

    // merged zero: a0 (fp16 plane), hmax, fv, occ
    const int N0 = BATCH*GS*GS*C1*2/16;
    const int N1 = MPIL*16*4/16;
    const int N2 = MPIL*64*4/16;
    const int N3 = BATCH*GS*GS*4/16;
    zero_all_kernel<<<(N0+N1+N2+N3 + 255)/256, 256>>>(
        (uint4*)a0, N0, (uint4*)p_hmax, N1, (uint4*)p_fv, N2, (uint4*)p_occ, N3);

    wprep_kernel<64,64><<<(9*4*8*32 + 255)/256, 256>>>(W[6],  p_wf + FOFF1);
    wprep_kernel<64,64><<<(9*4*8*32 + 255)/256, 256>>>(W[9],  p_wf + FOFF2);
    wprep_kernel<64,64><<<(9*4*8*32 + 255)/256, 256>>>(W[12], p_wf + FOFF3);
    wprep_kernel<64,128><<<(9*4*16*32 + 255)/256, 256>>>(W[15], p_wf + FOFF4);
    wprep_kernel<128,128><<<(9*8*16*32 + 255)/256, 256>>>(W[18], p_wf + FOFF5);
    wprep_kernel<128,128><<<(9*8*16*32 + 255)/256, 256>>>(W[21], p_wf + FOFF6);

    pfn0_kernel<<<(NPTS + 255)/256, 256>>>(feat, inv, W[0], W[1], W[2], p_h0, p_hmax);
    pfn1_kernel<<<(NPTS + 127)/128, 128>>>(inv, W[3], W[4], W[5], p_h0, p_hmax, p_fv);
    scatter_kernel<<<(MPIL*8 + 255)/256, 256>>>(unq, p_fv, a0, p_occ);
    occ1_kernel<<<(BATCH*GS*GS + 255)/256, 256>>>(p_occ, p_occ1);
    occ2_kernel<<<(BATCH*GS2*GS2 + 255)/256, 256>>>(p_occ1, p_occ2);

    // dynamic smem: BUFS * R * PXW * 16 halves * 2B
    const int S13 = 3 * 6 * 66 * 16 * 2;   // 38016 (TM=4, s1, BUFS=3)
    const int S4  = 2 * 5 * 130 * 16 * 2;  // 41600 (TM=2, s2, BUFS=2)
    const int S56 = 3 * 4 * 66 * 16 * 2;   // 25344 (TM=2, s1, BUFS=3)
    cudaFuncSetAttribute(conv_mma<64,64,1,4,3,false,true,true>,   cudaFuncAttributeMaxDynamicSharedMemorySize, S13);
    cudaFuncSetAttribute(conv_mma<64,64,1,4,3,false,false,true>,  cudaFuncAttributeMaxDynamicSharedMemorySize, S13);
    cudaFuncSetAttribute(conv_mma<64,64,1,4,3,true,false,true>,   cudaFuncAttributeMaxDynamicSharedMemorySize, S13);
    cudaFuncSetAttribute(conv_mma<64,128,2,2,2,false,true,true>,  cudaFuncAttributeMaxDynamicSharedMemorySize, S4);
    cudaFuncSetAttribute(conv_mma<128,128,1,2,3,false,false,true>,cudaFuncAttributeMaxDynamicSharedMemorySize, S56);
    cudaFuncSetAttribute(conv_mma<128,128,1,2,3,true,true,false>, cudaFuncAttributeMaxDynamicSharedMemorySize, S56);

    dim3 blk(256);
    // L1-3: 64->64 s1, TM=4, BUFS=3: grid (4, 64, 2)
    dim3 g1(GS/64, GS/4, BATCH);
    conv_mma<64,64,1,4,3,false,true,true><<<g1, blk, S13>>>(
        a0, p_wf + FOFF1, W[7], W[8], p_occ1, nullptr, p_x1, a1, GS, GS, GS, GS);
    conv_mma<64,64,1,4,3,false,false,true><<<g1, blk, S13>>>(
        a1, p_wf + FOFF2, W[10], W[11], p_occ1, nullptr, nullptr, a2, GS, GS, GS, GS);
    conv_mma<64,64,1,4,3,true,false,true><<<g1, blk, S13>>>(
        a2, p_wf + FOFF3, W[13], W[14], p_occ1, p_x1, nullptr, a3, GS, GS, GS, GS);

    // L4: 64->128 s2, TM=2, BUFS=2: grid (2, 64, 2)
    dim3 g2(GS2/64, GS2/2, BATCH);
    conv_mma<64,128,2,2,2,false,true,true><<<g2, blk, S4>>>(
        a3, p_wf + FOFF4, W[16], W[17], p_occ2, nullptr, p_x2, a4, GS, GS, GS2, GS2);
    // L5/6: 128->128 s1, TM=2, BUFS=3: grid (2, 64, 2)
    conv_mma<128,128,1,2,3,false,false,true><<<g2, blk, S56>>>(
        a4, p_wf + FOFF5, W[19], W[20], p_occ2, nullptr, nullptr, a5, GS2, GS2, GS2, GS2);
    conv_mma<128,128,1,2,3,true,true,false><<<g2, blk, S56>>>(
        a5, p_wf + FOFF6, W[22], W[23], p_occ2, p_x2, p_xb2, nullptr, GS2, GS2, GS2, GS2);

    gather_kernel<<<(NPTS*32 + 255)/256, 256>>>(feat, unq, inv, p_xb2, out);
    (void)n_in; (void)out_size;
}

// round 11
// speedup vs baseline: 6.5023x; 1.1234x over previous
#include <cuda_runtime.h>
#include <cuda_fp16.h>
#include <cstdint>

#define NPTS 200000
#define MPIL 30000
#define BATCH 2
#define GS 256
#define GS2 128
#define C1 64
#define C2 128

// ---------------- scratch ----------------
__device__ __align__(16) __half g_a0[BATCH*GS*GS*C1];
__device__ __align__(16) __half g_a1[BATCH*GS*GS*C1];
__device__ __align__(16) __half g_a2[BATCH*GS*GS*C1];
__device__ __align__(16) __half g_a3[BATCH*GS*GS*C1];
__device__ __align__(16) __half g_a4[BATCH*GS2*GS2*C2];
__device__ __align__(16) __half g_a5[BATCH*GS2*GS2*C2];
__device__ __align__(16) float g_x1 [BATCH*GS*GS*C1];
__device__ __align__(16) float g_x2 [BATCH*GS2*GS2*C2];
__device__ __align__(16) float g_xb2[BATCH*GS2*GS2*C2];
__device__ __align__(16) float g_h0  [NPTS*16];
__device__ __align__(16) float g_hmax[MPIL*16];
__device__ __align__(16) float g_fv  [MPIL*64];
__device__ __align__(16) float g_occ [BATCH*GS*GS];
__device__ __align__(16) float g_occ1[BATCH*GS*GS];
__device__ __align__(16) float g_occ2[BATCH*GS2*GS2];

// B-fragment store: [tap][chunk][ntile] blocks of 32 uint2 (fp16 frags)
#define FOFF1 0
#define FOFF2 (FOFF1 + 9216)
#define FOFF3 (FOFF2 + 9216)
#define FOFF4 (FOFF3 + 9216)
#define FOFF5 (FOFF4 + 18432)
#define FOFF6 (FOFF5 + 36864)
#define FTOT  (FOFF6 + 36864)
__device__ __align__(16) uint2 g_wfrag[FTOT];

// ---------------- helpers ----------------
__device__ __forceinline__ uint32_t smem_u32(const void* p) {
    uint32_t a;
    asm("{ .reg .u64 t; cvta.to.shared.u64 t, %1; cvt.u32.u64 %0, t; }" : "=r"(a) : "l"(p));
    return a;
}
__device__ __forceinline__ uint32_t pack_h2(float f0, float f1) {
    uint32_t r;
    asm("cvt.rn.f16x2.f32 %0, %1, %2;" : "=r"(r) : "f"(f1), "f"(f0));
    return r;
}
__device__ __forceinline__ void mma16816(float* c, const uint32_t* a,
                                         uint32_t b0, uint32_t b1) {
    asm volatile("mma.sync.aligned.m16n8k16.row.col.f32.f16.f16.f32 "
        "{%0,%1,%2,%3}, {%4,%5,%6,%7}, {%8,%9}, {%0,%1,%2,%3};"
        : "+f"(c[0]), "+f"(c[1]), "+f"(c[2]), "+f"(c[3])
        : "r"(a[0]), "r"(a[1]), "r"(a[2]), "r"(a[3]), "r"(b0), "r"(b1));
}
__device__ __forceinline__ void ldsm_x4(uint32_t& r0, uint32_t& r1, uint32_t& r2, uint32_t& r3,
                                        uint32_t saddr) {
    asm volatile("ldmatrix.sync.aligned.m8n8.x4.shared.b16 {%0,%1,%2,%3}, [%4];"
        : "=r"(r0), "=r"(r1), "=r"(r2), "=r"(r3) : "r"(saddr));
}
__device__ __forceinline__ void cp16(uint32_t dst, const void* src, bool ok) {
    int sz = ok ? 16 : 0;
    asm volatile("cp.async.cg.shared.global [%0], [%1], 16, %2;"
        :: "r"(dst), "l"(src), "r"(sz) : "memory");
}
__device__ __forceinline__ void cp_commit() {
    asm volatile("cp.async.commit_group;" ::: "memory");
}
template <int N>
__device__ __forceinline__ void cp_wait() {
    asm volatile("cp.async.wait_group %0;" :: "n"(N) : "memory");
}

// ---------------- merged zero ----------------
__global__ void zero_all_kernel(uint4* p0, int n0, uint4* p1, int n1,
                                uint4* p2, int n2, uint4* p3, int n3) {
    int i = blockIdx.x * blockDim.x + threadIdx.x;
    uint4 z = make_uint4(0u, 0u, 0u, 0u);
    if (i < n0) p0[i] = z;
    i -= n0;
    if (i >= 0 && i < n1) p1[i] = z;
    i -= n1;
    if (i >= 0 && i < n2) p2[i] = z;
    i -= n2;
    if (i >= 0 && i < n3) p3[i] = z;
}

// ---------------- merged weight prep (all 6 layers) ----------------
__global__ void wprep_all_kernel(
    const float* w1p, const float* w2p, const float* w3p,
    const float* w4p, const float* w5p, const float* w6p,
    uint2* __restrict__ dst)
{
    int idx = blockIdx.x * blockDim.x + threadIdx.x;
    // per-layer thread counts and params
    // counts: L1-3: 9216, L4: 18432, L5/6: 36864; total 119808
    int layer, base;
    const float* w;
    int cin, cout, foff;
    if (idx < 9216)            { layer = 0; base = 0; }
    else if (idx < 18432)      { layer = 1; base = 9216; }
    else if (idx < 27648)      { layer = 2; base = 18432; }
    else if (idx < 46080)      { layer = 3; base = 27648; }
    else if (idx < 82944)      { layer = 4; base = 46080; }
    else if (idx < 119808)     { layer = 5; base = 82944; }
    else return;
    switch (layer) {
        case 0: w = w1p; cin = 64;  cout = 64;  foff = FOFF1; break;
        case 1: w = w2p; cin = 64;  cout = 64;  foff = FOFF2; break;
        case 2: w = w3p; cin = 64;  cout = 64;  foff = FOFF3; break;
        case 3: w = w4p; cin = 64;  cout = 128; foff = FOFF4; break;
        case 4: w = w5p; cin = 128; cout = 128; foff = FOFF5; break;
        default:w = w6p; cin = 128; cout = 128; foff = FOFF6; break;
    }
    int li = idx - base;
    int chunks = cin / 16;
    int nttot = cout / 8;
    int lane = li & 31;
    int t = li >> 5;
    int nt = t % nttot;
    int t2 = t / nttot;
    int ch = t2 % chunks;
    int tap = t2 / chunks;
    int n = nt * 8 + (lane >> 2);
    int k0 = (lane & 3) * 2;
    int cib = ch * 16;
    float w00 = w[((size_t)tap * cin + cib + k0)     * cout + n];
    float w01 = w[((size_t)tap * cin + cib + k0 + 1) * cout + n];
    float w10 = w[((size_t)tap * cin + cib + k0 + 8) * cout + n];
    float w11 = w[((size_t)tap * cin + cib + k0 + 9) * cout + n];
    uint2* blk = dst + foff + (size_t)((tap * chunks + ch) * nttot + nt) * 32;
    blk[lane] = make_uint2(pack_h2(w00, w01), pack_h2(w10, w11));
}

// ---------------- PFN layer 0 ----------------
__global__ __launch_bounds__(256) void pfn0_kernel(
    const float* __restrict__ feat, const int* __restrict__ inv,
    const float* __restrict__ w0, const float* __restrict__ g0, const float* __restrict__ b0,
    float* __restrict__ h0, float* __restrict__ hmax)
{
    __shared__ float sw[256];
    __shared__ float sg[16], sb[16];
    if (threadIdx.x < 256) sw[threadIdx.x] = w0[threadIdx.x];
    if (threadIdx.x < 16) { sg[threadIdx.x] = g0[threadIdx.x]; sb[threadIdx.x] = b0[threadIdx.x]; }
    __syncthreads();
    int i = blockIdx.x * 256 + threadIdx.x;
    if (i >= NPTS) return;
    float f[16];
    const float4* fp = reinterpret_cast<const float4*>(feat + (size_t)i * 16);
#pragma unroll
    for (int t = 0; t < 4; t++) {
        float4 v = fp[t];
        f[4*t]=v.x; f[4*t+1]=v.y; f[4*t+2]=v.z; f[4*t+3]=v.w;
    }
    float acc[16];
#pragma unroll
    for (int j = 0; j < 16; j++) acc[j] = 0.f;
#pragma unroll
    for (int c = 0; c < 16; c++) {
        float xv = f[c];
#pragma unroll
        for (int j = 0; j < 16; j++) acc[j] += xv * sw[c * 16 + j];
    }
    int seg = inv[i];
    float h[16];
#pragma unroll
    for (int j = 0; j < 16; j++) h[j] = fmaxf(acc[j] * sg[j] + sb[j], 0.f);
    float4* hp = reinterpret_cast<float4*>(h0 + (size_t)i * 16);
#pragma unroll
    for (int t = 0; t < 4; t++) hp[t] = make_float4(h[4*t], h[4*t+1], h[4*t+2], h[4*t+3]);
    int* hm = reinterpret_cast<int*>(hmax + (size_t)seg * 16);
#pragma unroll
    for (int j = 0; j < 16; j++)
        if (h[j] > 0.f) atomicMax(hm + j, __float_as_int(h[j]));
}

// ---------------- PFN layer 1 ----------------
__global__ __launch_bounds__(128) void pfn1_kernel(
    const int* __restrict__ inv,
    const float* __restrict__ w1, const float* __restrict__ g1, const float* __restrict__ b1,
    const float* __restrict__ h0, const float* __restrict__ hmax, float* __restrict__ fv)
{
    __shared__ float sw[32 * 64];
    __shared__ float sg[64], sb[64];
    for (int t = threadIdx.x; t < 2048; t += blockDim.x) sw[t] = w1[t];
    if (threadIdx.x < 64) { sg[threadIdx.x] = g1[threadIdx.x]; sb[threadIdx.x] = b1[threadIdx.x]; }
    __syncthreads();
    int i = blockIdx.x * blockDim.x + threadIdx.x;
    if (i >= NPTS) return;
    int seg = inv[i];
    float x[32];
    const float4* hp = reinterpret_cast<const float4*>(h0 + (size_t)i * 16);
    const float4* mp = reinterpret_cast<const float4*>(hmax + (size_t)seg * 16);
#pragma unroll
    for (int t = 0; t < 4; t++) {
        float4 v = hp[t];
        x[4*t]=v.x; x[4*t+1]=v.y; x[4*t+2]=v.z; x[4*t+3]=v.w;
        float4 u = mp[t];
        x[16+4*t]=u.x; x[16+4*t+1]=u.y; x[16+4*t+2]=u.z; x[16+4*t+3]=u.w;
    }
    float acc[64];
#pragma unroll
    for (int j = 0; j < 64; j++) acc[j] = 0.f;
#pragma unroll
    for (int c = 0; c < 32; c++) {
        float xv = x[c];
        const float4* wr = reinterpret_cast<const float4*>(&sw[c * 64]);
#pragma unroll
        for (int k = 0; k < 16; k++) {
            float4 w = wr[k];
            acc[4*k] += xv*w.x; acc[4*k+1] += xv*w.y;
            acc[4*k+2] += xv*w.z; acc[4*k+3] += xv*w.w;
        }
    }
    int* fp = reinterpret_cast<int*>(fv + (size_t)seg * 64);
#pragma unroll
    for (int j = 0; j < 64; j++) {
        float v = fmaxf(acc[j] * sg[j] + sb[j], 0.f);
        if (v > 0.f) atomicMax(fp + j, __float_as_int(v));
    }
}

// ---------------- scatter pillars -> fp16 plane + occ ----------------
__global__ void scatter_kernel(const int* __restrict__ unq, const float* __restrict__ fv,
                               __half* __restrict__ ah, float* __restrict__ occ)
{
    int idx = blockIdx.x * blockDim.x + threadIdx.x;
    if (idx >= MPIL * 8) return;
    int m = idx >> 3, k = idx & 7;
    int bb = unq[m*3], yy = unq[m*3+1], xx = unq[m*3+2];
    const float4* fp = reinterpret_cast<const float4*>(fv) + m * 16 + 2 * k;
    float4 a = fp[0], b = fp[1];
    uint4 hw;
    hw.x = pack_h2(a.x, a.y);
    hw.y = pack_h2(a.z, a.w);
    hw.z = pack_h2(b.x, b.y);
    hw.w = pack_h2(b.z, b.w);
    size_t pix = ((size_t)(bb * GS + yy) * GS + xx) * 64;
    reinterpret_cast<uint4*>(ah + pix)[k] = hw;
    if (k == 0) occ[(bb * GS + yy) * GS + xx] = 1.0f;
}

// ---------------- occupancy dilations ----------------
__global__ void occ1_kernel(const float* __restrict__ occ, float* __restrict__ occ1) {
    int idx = blockIdx.x * blockDim.x + threadIdx.x;
    if (idx >= BATCH * GS * GS) return;
    int x = idx % GS, y = (idx / GS) % GS, b = idx / (GS * GS);
    float m = 0.f;
#pragma unroll
    for (int dy = -1; dy <= 1; dy++)
#pragma unroll
        for (int dx = -1; dx <= 1; dx++) {
            int yy = y + dy, xx = x + dx;
            if (yy >= 0 && yy < GS && xx >= 0 && xx < GS)
                m = fmaxf(m, occ[(b * GS + yy) * GS + xx]);
        }
    occ1[idx] = m;
}
__global__ void occ2_kernel(const float* __restrict__ occ1, float* __restrict__ occ2) {
    int idx = blockIdx.x * blockDim.x + threadIdx.x;
    if (idx >= BATCH * GS2 * GS2) return;
    int x = idx % GS2, y = (idx / GS2) % GS2, b = idx / (GS2 * GS2);
    float m = 0.f;
#pragma unroll
    for (int dy = -1; dy <= 1; dy++)
#pragma unroll
        for (int dx = -1; dx <= 1; dx++) {
            int yy = 2 * y + dy, xx = 2 * x + dx;
            if (yy >= 0 && yy < GS && xx >= 0 && xx < GS)
                m = fmaxf(m, occ1[(b * GS + yy) * GS + xx]);
        }
    occ2[idx] = m;
}

// ---------------- HMMA conv3x3 (fp16), cp.async pipelined, ldmatrix A ----------------
template <int CIN, int COUT, int STRIDE, int TM, int BUFS, bool RESID, bool OUTF32, bool PLANES>
__global__ __launch_bounds__(256) void conv_mma(
    const __half* __restrict__ in,
    const uint2* __restrict__ wfrag,
    const float* __restrict__ gm, const float* __restrict__ bt,
    const float* __restrict__ mask, const float* __restrict__ resid,
    float* __restrict__ outf, __half* __restrict__ outh,
    int IH, int IW, int OH, int OW)
{
    constexpr int CHUNKS = CIN / 16;
    constexpr int NTTOT = COUT / 8;
    constexpr int NT = COUT / 16;
    constexpr int R = (TM - 1) * STRIDE + 3;
    constexpr int PXW = 64 * STRIDE + 2;
    constexpr int NV = R * PXW * 2;

    extern __shared__ __align__(16) char smem_raw[];
    __half* s_in = reinterpret_cast<__half*>(smem_raw);
    auto sidx = [&](int buf, int ry, int px) {
        return ((buf * R + ry) * PXW + px) * 16;
    };

    const int tid = threadIdx.x;
    const int wid = tid >> 5, lane = tid & 31;
    const int mwarp = wid >> 1, nwarp = wid & 1;
    const int g = lane >> 2, q = lane & 3;
    const int y0 = blockIdx.y * TM;
    const int xb = blockIdx.x * 64;
    const int bb = blockIdx.z;

    const int mat = lane >> 3;
    const int mrow = (mat & 1) * 8 + (lane & 7);
    const int koff = (mat >> 1) * 8;
    const int pxbase = (mwarp * 16 + mrow) * STRIDE;
    const uint32_t sb32 = smem_u32(s_in);

    float acc[TM][NT][4];
#pragma unroll
    for (int r = 0; r < TM; r++)
#pragma unroll
        for (int nt = 0; nt < NT; nt++)
#pragma unroll
            for (int j = 0; j < 4; j++) acc[r][nt][j] = 0.f;

    auto stage = [&](int ch, int buf) {
#pragma unroll 1
        for (int i = tid; i < NV; i += 256) {
            int half = i & 1;
            int r2 = i >> 1;
            int px = r2 % PXW;
            int ry = r2 / PXW;
            int iy = y0 * STRIDE + ry - 1;
            int ix = xb * STRIDE + px - 1;
            bool ok = (iy >= 0) && (iy < IH) && (ix >= 0) && (ix < IW);
            const void* src = ok
                ? (const void*)(in + ((size_t)(bb * IH + iy) * IW + ix) * CIN + ch * 16 + half * 8)
                : (const void*)in;
            cp16(smem_u32(s_in + sidx(buf, ry, px) + half * 8), src, ok);
        }
        cp_commit();
    };

    stage(0, 0);

#pragma unroll 1
    for (int ch = 0; ch < CHUNKS; ch++) {
        const int buf = (BUFS == 3) ? (ch % 3) : (ch & 1);
        if (ch + 1 < CHUNKS) {
            stage(ch + 1, (BUFS == 3) ? ((ch + 1) % 3) : ((ch + 1) & 1));
            cp_wait<1>();
        } else {
            cp_wait<0>();
        }
        __syncthreads();
#pragma unroll
        for (int ky = 0; ky < 3; ky++) {
#pragma unroll
            for (int kx = 0; kx < 3; kx++) {
                const uint2* bbase = wfrag
                    + (size_t)(((ky * 3 + kx) * CHUNKS + ch) * NTTOT + nwarp * NT) * 32;
                uint2 bh[NT];
#pragma unroll
                for (int nt = 0; nt < NT; nt++) bh[nt] = __ldg(bbase + nt * 32 + lane);
                uint32_t A[TM][4];
#pragma unroll
                for (int r = 0; r < TM; r++) {
                    const int row = r * STRIDE + ky;
                    uint32_t ad = sb32 + (uint32_t)((((buf * R + row) * PXW) + pxbase + kx) * 16 + koff) * 2;
                    ldsm_x4(A[r][0], A[r][1], A[r][2], A[r][3], ad);
                }
#pragma unroll
                for (int r = 0; r < TM; r++)
#pragma unroll
                    for (int nt = 0; nt < NT; nt++)
                        mma16816(acc[r][nt], A[r], bh[nt].x, bh[nt].y);
            }
        }
        if (BUFS == 2) __syncthreads();
    }

    // epilogue
    const int xa = xb + mwarp * 16 + g;
#pragma unroll
    for (int r = 0; r < TM; r++) {
        const int y = y0 + r;
        const size_t pa = (size_t)(bb * OH + y) * OW + xa;
        const size_t pb = pa + 8;
        const float mva = mask[pa];
        const float mvb = mask[pb];
#pragma unroll
        for (int nt = 0; nt < NT; nt++) {
            const int co = nwarp * (COUT / 2) + nt * 8 + 2 * q;
            const float g0 = __ldg(gm + co), g1 = __ldg(gm + co + 1);
            const float b0 = __ldg(bt + co), b1 = __ldg(bt + co + 1);
            float v0 = acc[r][nt][0] * g0 + b0;
            float v1 = acc[r][nt][1] * g1 + b1;
            float v2 = acc[r][nt][2] * g0 + b0;
            float v3 = acc[r][nt][3] * g1 + b1;
            if (RESID) {
                float2 ra = *reinterpret_cast<const float2*>(resid + pa * COUT + co);
                float2 rb = *reinterpret_cast<const float2*>(resid + pb * COUT + co);
                v0 = fmaxf(ra.x + v0 * mva, 0.f);
                v1 = fmaxf(ra.y + v1 * mva, 0.f);
                v2 = fmaxf(rb.x + v2 * mvb, 0.f);
                v3 = fmaxf(rb.y + v3 * mvb, 0.f);
            } else {
                v0 = fmaxf(v0, 0.f) * mva;
                v1 = fmaxf(v1, 0.f) * mva;
                v2 = fmaxf(v2, 0.f) * mvb;
                v3 = fmaxf(v3, 0.f) * mvb;
            }
            if (OUTF32) {
                *reinterpret_cast<float2*>(outf + pa * COUT + co) = make_float2(v0, v1);
                *reinterpret_cast<float2*>(outf + pb * COUT + co) = make_float2(v2, v3);
            }
            if (PLANES) {
                *reinterpret_cast<uint32_t*>(outh + pa * COUT + co) = pack_h2(v0, v1);
                *reinterpret_cast<uint32_t*>(outh + pb * COUT + co) = pack_h2(v2, v3);
            }
        }
    }
}

// ---------------- bilinear gather ----------------
__global__ __launch_bounds__(256) void gather_kernel(
    const float* __restrict__ feat, const int* __restrict__ unq, const int* __restrict__ inv,
    const float* __restrict__ xb2, float* __restrict__ out)
{
    int gwarp = (blockIdx.x * blockDim.x + threadIdx.x) >> 5;
    int lane = threadIdx.x & 31;
    if (gwarp >= NPTS) return;
    int i = gwarp;
    float f0 = __ldg(feat + (size_t)i * 16);
    float f1 = __ldg(feat + (size_t)i * 16 + 1);
    float px = ((f0 + 51.2f) / 0.4f) * 0.5f;
    float py = ((f1 + 51.2f) / 0.4f) * 0.5f;
    int seg = __ldg(inv + i);
    int bb = __ldg(unq + seg * 3);
    int fx = (int)floorf(px), fy = (int)floorf(py);
    int x0 = min(max(fx, 0), GS2 - 1), x1 = min(max(fx + 1, 0), GS2 - 1);
    int y0 = min(max(fy, 0), GS2 - 1), y1 = min(max(fy + 1, 0), GS2 - 1);
    float x0f = (float)x0, x1f = (float)x1, y0f = (float)y0, y1f = (float)y1;
    float wa = (x1f - px) * (y1f - py);
    float wb = (x1f - px) * (py - y0f);
    float wc = (px - x0f) * (y1f - py);
    float wd = (px - x0f) * (py - y0f);
    const float4* A  = reinterpret_cast<const float4*>(xb2 + ((size_t)(bb*GS2+y0)*GS2+x0)*C2) + lane;
    const float4* Bp = reinterpret_cast<const float4*>(xb2 + ((size_t)(bb*GS2+y1)*GS2+x0)*C2) + lane;
    const float4* Cp = reinterpret_cast<const float4*>(xb2 + ((size_t)(bb*GS2+y0)*GS2+x1)*C2) + lane;
    const float4* D  = reinterpret_cast<const float4*>(xb2 + ((size_t)(bb*GS2+y1)*GS2+x1)*C2) + lane;
    float4 a = __ldg(A), b = __ldg(Bp), c = __ldg(Cp), d = __ldg(D);
    float4 r;
    r.x = a.x*wa + b.x*wb + c.x*wc + d.x*wd;
    r.y = a.y*wa + b.y*wb + c.y*wc + d.y*wd;
    r.z = a.z*wa + b.z*wb + c.z*wc + d.z*wd;
    r.w = a.w*wa + b.w*wb + c.w*wc + d.w*wd;
    reinterpret_cast<float4*>(out + (size_t)i * C2)[lane] = r;
}

// ---------------- launch ----------------
extern "C" void kernel_launch(void* const* d_in, const int* in_sizes, int n_in,
                              void* d_out, int out_size)
{
    const float* feat = (const float*)d_in[0];
    const int* unq = (const int*)d_in[1];
    const int* inv = (const int*)d_in[2];
    int wb = (in_sizes[3] == 1) ? 4 : 3;
    const float* W[24];
    for (int i = 0; i < 24; i++) W[i] = (const float*)d_in[wb + i];
    float* out = (float*)d_out;

    float *p_h0, *p_hmax, *p_fv, *p_x1, *p_x2, *p_xb2, *p_occ, *p_occ1, *p_occ2;
    __half *a0, *a1, *a2, *a3, *a4, *a5;
    uint2* p_wf;
    cudaGetSymbolAddress((void**)&p_h0, g_h0);
    cudaGetSymbolAddress((void**)&p_hmax, g_hmax);
    cudaGetSymbolAddress((void**)&p_fv, g_fv);
    cudaGetSymbolAddress((void**)&p_x1, g_x1);
    cudaGetSymbolAddress((void**)&p_x2, g_x2);
    cudaGetSymbolAddress((void**)&p_xb2, g_xb2);
    cudaGetSymbolAddress((void**)&p_occ, g_occ);
    cudaGetSymbolAddress((void**)&p_occ1, g_occ1);
    cudaGetSymbolAddress((void**)&p_occ2, g_occ2);
    cudaGetSymbolAddress((void**)&a0, g_a0);
    cudaGetSymbolAddress((void**)&a1, g_a1);
    cudaGetSymbolAddress((void**)&a2, g_a2);
    cudaGetSymbolAddress((void**)&a3, g_a3);
    cudaGetSymbolAddress((void**)&a4, g_a4);
    cudaGetSymbolAddress((void**)&a5, g_a5);
    cudaGetSymbolAddress((void**)&p_wf, g_wfrag);

    // merged zero: a0 (fp16 plane), hmax, fv, occ
    const int N0 = BATCH*GS*GS*C1*2/16;
    const int N1 = MPIL*16*4/16;
    const int N2 = MPIL*64*4/16;
    const int N3 = BATCH*GS*GS*4/16;
    zero_all_kernel<<<(N0+N1+N2+N3 + 255)/256, 256>>>(
        (uint4*)a0, N0, (uint4*)p_hmax, N1, (uint4*)p_fv, N2, (uint4*)p_occ, N3);

    // merged weight prep (all 6 layers, 119808 threads)
    wprep_all_kernel<<<(119808 + 255)/256, 256>>>(
        W[6], W[9], W[12], W[15], W[18], W[21], p_wf);

    pfn0_kernel<<<(NPTS + 255)/256, 256>>>(feat, inv, W[0], W[1], W[2], p_h0, p_hmax);
    pfn1_kernel<<<(NPTS + 127)/128, 128>>>(inv, W[3], W[4], W[5], p_h0, p_hmax, p_fv);
    scatter_kernel<<<(MPIL*8 + 255)/256, 256>>>(unq, p_fv, a0, p_occ);
    occ1_kernel<<<(BATCH*GS*GS + 255)/256, 256>>>(p_occ, p_occ1);
    occ2_kernel<<<(BATCH*GS2*GS2 + 255)/256, 256>>>(p_occ1, p_occ2);

    // dynamic smem: BUFS * R * PXW * 16 halves * 2B
    const int S13 = 3 * 6 * 66 * 16 * 2;   // 38016 (TM=4, s1, BUFS=3)
    const int S4  = 2 * 5 * 130 * 16 * 2;  // 41600 (TM=2, s2, BUFS=2)
    const int S56 = 3 * 4 * 66 * 16 * 2;   // 25344 (TM=2, s1, BUFS=3)
    cudaFuncSetAttribute(conv_mma<64,64,1,4,3,false,true,true>,   cudaFuncAttributeMaxDynamicSharedMemorySize, S13);
    cudaFuncSetAttribute(conv_mma<64,64,1,4,3,false,false,true>,  cudaFuncAttributeMaxDynamicSharedMemorySize, S13);
    cudaFuncSetAttribute(conv_mma<64,64,1,4,3,true,false,true>,   cudaFuncAttributeMaxDynamicSharedMemorySize, S13);
    cudaFuncSetAttribute(conv_mma<64,128,2,2,2,false,true,true>,  cudaFuncAttributeMaxDynamicSharedMemorySize, S4);
    cudaFuncSetAttribute(conv_mma<128,128,1,2,3,false,false,true>,cudaFuncAttributeMaxDynamicSharedMemorySize, S56);
    cudaFuncSetAttribute(conv_mma<128,128,1,2,3,true,true,false>, cudaFuncAttributeMaxDynamicSharedMemorySize, S56);

    dim3 blk(256);
    // L1-3: 64->64 s1, TM=4, BUFS=3: grid (4, 64, 2)
    dim3 g1(GS/64, GS/4, BATCH);
    conv_mma<64,64,1,4,3,false,true,true><<<g1, blk, S13>>>(
        a0, p_wf + FOFF1, W[7], W[8], p_occ1, nullptr, p_x1, a1, GS, GS, GS, GS);
    conv_mma<64,64,1,4,3,false,false,true><<<g1, blk, S13>>>(
        a1, p_wf + FOFF2, W[10], W[11], p_occ1, nullptr, nullptr, a2, GS, GS, GS, GS);
    conv_mma<64,64,1,4,3,true,false,true><<<g1, blk, S13>>>(
        a2, p_wf + FOFF3, W[13], W[14], p_occ1, p_x1, nullptr, a3, GS, GS, GS, GS);

    // L4: 64->128 s2, TM=2, BUFS=2: grid (2, 64, 2)
    dim3 g2(GS2/64, GS2/2, BATCH);
    conv_mma<64,128,2,2,2,false,true,true><<<g2, blk, S4>>>(
        a3, p_wf + FOFF4, W[16], W[17], p_occ2, nullptr, p_x2, a4, GS, GS, GS2, GS2);
    // L5/6: 128->128 s1, TM=2, BUFS=3: grid (2, 64, 2)
    conv_mma<128,128,1,2,3,false,false,true><<<g2, blk, S56>>>(
        a4, p_wf + FOFF5, W[19], W[20], p_occ2, nullptr, nullptr, a5, GS2, GS2, GS2, GS2);
    conv_mma<128,128,1,2,3,true,true,false><<<g2, blk, S56>>>(
        a5, p_wf + FOFF6, W[22], W[23], p_occ2, p_x2, p_xb2, nullptr, GS2, GS2, GS2, GS2);

    gather_kernel<<<(NPTS*32 + 255)/256, 256>>>(feat, unq, inv, p_xb2, out);
    (void)n_in; (void)out_size;
}